// round 1
// baseline (speedup 1.0000x reference)
#include <cuda_runtime.h>

#define BB 2
#define NN 512
#define HH 64
#define NODES (BB*NN)

// ---------------- scratch (device globals; no allocation allowed) -------------
__device__ float g_h[NODES*HH];      // node features
__device__ float g_a[NODES*HH];      // a_i = h_i @ W_i + b1   (per layer)
__device__ float g_ct[BB*HH*NN];     // c_j = h_j @ W_j, stored n-major: [b][n][j]
__device__ float g_magg[NODES*HH];   // sum_j m_ij
__device__ float g_fsum[NODES*2];    // accumulated pair forces across layers

// ---------------- helpers -----------------------------------------------------
__device__ __forceinline__ float silu_f(float x){
    float e = __expf(-x);
    return x * __fdividef(1.0f, 1.0f + e);
}

__device__ __forceinline__ unsigned long long splat2(float x){
    unsigned long long r; asm("mov.b64 %0, {%1, %1};" : "=l"(r) : "f"(x)); return r;
}
__device__ __forceinline__ unsigned long long ffma2(unsigned long long a,
                                                    unsigned long long b,
                                                    unsigned long long c){
    unsigned long long d;
    asm("fma.rn.f32x2 %0, %1, %2, %3;" : "=l"(d) : "l"(a), "l"(b), "l"(c));
    return d;
}
__device__ __forceinline__ float2 unpack2(unsigned long long v){
    float lo, hi; asm("mov.b64 {%0, %1}, %2;" : "=f"(lo), "=f"(hi) : "l"(v));
    return make_float2(lo, hi);
}

// ---------------- h init -------------------------------------------------------
__global__ void k_init(const float* __restrict__ state,
                       const float* __restrict__ hw,
                       const float* __restrict__ hb){
    int idx  = blockIdx.x * 256 + threadIdx.x;   // NODES*HH threads
    int node = idx >> 6;
    int ch   = idx & 63;
    float4 st = ((const float4*)state)[node];
    float spd = sqrtf(st.z*st.z + st.w*st.w);
    g_h[idx] = silu_f(spd * hw[ch] + hb[ch]);
}

// ---------------- per-layer prep: a_i, c_j (transposed) ------------------------
__global__ void k_prep(const float* __restrict__ ew1l,
                       const float* __restrict__ eb1l){
    __shared__ float hs[HH];
    int node = blockIdx.x;
    int t = threadIdx.x;
    hs[t] = g_h[node*HH + t];
    __syncthreads();
    float a = eb1l[t], c = 0.f;
    #pragma unroll 8
    for (int k = 0; k < HH; ++k){
        float hv = hs[k];
        a = fmaf(hv, ew1l[k*HH + t],        a);   // rows 0..63   : W_i
        c = fmaf(hv, ew1l[(HH + k)*HH + t], c);   // rows 64..127 : W_j
    }
    g_a[node*HH + t] = a;
    int b = node >> 9, j = node & (NN - 1);
    g_ct[(b*HH + t)*NN + j] = c;                  // n-major for coalesced edge reads
}

// ---------------- edge kernel: one CTA per (b,i), thread = pair ----------------
__global__ void __launch_bounds__(256, 1) k_edge(
    const float* __restrict__ state,
    const float* __restrict__ ew1l,   // for scalar-feature rows 128..131
    const float* __restrict__ ew2l,
    const float* __restrict__ eb2l,
    const float* __restrict__ fw1l,
    const float* __restrict__ fb1l,
    const float* __restrict__ fw2l,
    const float* __restrict__ fb2l,
    int accumulate)
{
    __shared__ __align__(16) float sW2[HH*HH];
    __shared__ __align__(16) float sF1[HH*HH];
    __shared__ float  sA[HH];
    __shared__ float4 sWS[HH];
    __shared__ __align__(8) float sB2[HH];
    __shared__ __align__(8) float sFB1[HH];
    __shared__ float sFW2[HH];
    __shared__ float sMagg[HH];
    __shared__ float sFxy[2];

    int tid = threadIdx.x;
    int bi  = blockIdx.x;
    int b   = bi >> 9;
    int i   = bi & (NN - 1);

    {   // cooperative weight staging (coalesced float4)
        const float4* g2 = (const float4*)ew2l;
        const float4* g1 = (const float4*)fw1l;
        float4* s2 = (float4*)sW2;
        float4* s1 = (float4*)sF1;
        #pragma unroll
        for (int q = 0; q < 4; q++){
            s2[tid + 256*q] = g2[tid + 256*q];
            s1[tid + 256*q] = g1[tid + 256*q];
        }
    }
    if (tid < HH){
        sA[tid]   = g_a[bi*HH + tid];
        sB2[tid]  = eb2l[tid];
        sFB1[tid] = fb1l[tid];
        sFW2[tid] = fw2l[tid];
        sWS[tid]  = make_float4(ew1l[128*HH + tid], ew1l[129*HH + tid],
                                ew1l[130*HH + tid], ew1l[131*HH + tid]);
        sMagg[tid] = 0.0f;
    }
    if (tid < 2) sFxy[tid] = 0.0f;

    float4 sti = ((const float4*)state)[b*NN + i];
    float spi  = sti.z*sti.z + sti.w*sti.w;
    float fb2v = fb2l[0];
    __syncthreads();

    float fx = 0.f, fy = 0.f;

    for (int it = 0; it < 2; ++it){
        int j = (it << 8) + tid;
        float4 stj = ((const float4*)state)[b*NN + j];
        float dxp = stj.x - sti.x;
        float dyp = stj.y - sti.y;
        float dsq = dxp*dxp + dyp*dyp;
        float invd = rsqrtf(dsq + 1e-8f);
        float nx2 = dxp * invd;
        float ny2 = dyp * invd;
        float dvx = stj.z - sti.z;
        float dvy = stj.w - sti.w;
        float spj = stj.z*stj.z + stj.w*stj.w;
        float appr = dvx*nx2 + dvy*ny2;

        // ---- stage 0: t1 = silu(a_i + c_j + scalars @ W_s) -----------------
        float buf[HH];
        const float* ct = &g_ct[b*HH*NN + j];
        #pragma unroll
        for (int n = 0; n < HH; ++n){
            float c = ct[n*NN];
            float4 w = sWS[n];
            float p = sA[n] + c;
            p = fmaf(dsq,  w.x, p);
            p = fmaf(spi,  w.y, p);
            p = fmaf(spj,  w.z, p);
            p = fmaf(appr, w.w, p);
            buf[n] = silu_f(p);
        }

        // ---- stage 1: t2 = silu(t1 @ W2 + b2), packed f32x2 ----------------
        unsigned long long acc[32];
        {
            const unsigned long long* bp = (const unsigned long long*)sB2;
            #pragma unroll
            for (int m = 0; m < 32; ++m) acc[m] = bp[m];
        }
        {
            const ulonglong2* W = (const ulonglong2*)sW2;
            #pragma unroll
            for (int k = 0; k < HH; ++k){
                unsigned long long tk = splat2(buf[k]);
                #pragma unroll
                for (int m = 0; m < 16; ++m){
                    ulonglong2 w = W[k*16 + m];
                    acc[2*m]   = ffma2(tk, w.x, acc[2*m]);
                    acc[2*m+1] = ffma2(tk, w.y, acc[2*m+1]);
                }
            }
        }
        #pragma unroll
        for (int m = 0; m < 32; ++m){
            float2 v = unpack2(acc[m]);
            buf[2*m]   = silu_f(v.x);
            buf[2*m+1] = silu_f(v.y);
        }

        // ---- stage 2: t3 = silu(t2 @ F1 + fb1); fw = t3 . fw2 + fb2 --------
        {
            const unsigned long long* bp = (const unsigned long long*)sFB1;
            #pragma unroll
            for (int m = 0; m < 32; ++m) acc[m] = bp[m];
        }
        {
            const ulonglong2* W = (const ulonglong2*)sF1;
            #pragma unroll
            for (int k = 0; k < HH; ++k){
                unsigned long long tk = splat2(buf[k]);
                #pragma unroll
                for (int m = 0; m < 16; ++m){
                    ulonglong2 w = W[k*16 + m];
                    acc[2*m]   = ffma2(tk, w.x, acc[2*m]);
                    acc[2*m+1] = ffma2(tk, w.y, acc[2*m+1]);
                }
            }
        }
        float fw = fb2v;
        #pragma unroll
        for (int m = 0; m < 32; ++m){
            float2 v = unpack2(acc[m]);
            fw = fmaf(silu_f(v.x), sFW2[2*m],   fw);
            fw = fmaf(silu_f(v.y), sFW2[2*m+1], fw);
        }

        float msk = (j == i) ? 0.0f : 1.0f;
        fw *= msk;
        fx = fmaf(fw, nx2, fx);
        fy = fmaf(fw, ny2, fy);

        // ---- m_agg: warp butterfly reduce over 32 pairs, lane0 -> smem -----
        #pragma unroll
        for (int n = 0; n < HH; ++n){
            float v = msk * buf[n];
            v += __shfl_xor_sync(0xffffffffu, v, 16);
            v += __shfl_xor_sync(0xffffffffu, v, 8);
            v += __shfl_xor_sync(0xffffffffu, v, 4);
            v += __shfl_xor_sync(0xffffffffu, v, 2);
            v += __shfl_xor_sync(0xffffffffu, v, 1);
            if ((tid & 31) == 0) atomicAdd(&sMagg[n], v);
        }
    }

    atomicAdd(&sFxy[0], fx);
    atomicAdd(&sFxy[1], fy);
    __syncthreads();

    if (tid < HH) g_magg[bi*HH + tid] = sMagg[tid];
    if (tid < 2){
        float v = sFxy[tid];
        if (accumulate) g_fsum[bi*2 + tid] += v;
        else            g_fsum[bi*2 + tid] = v;
    }
}

// ---------------- node update MLP ----------------------------------------------
__global__ void k_node(const float* __restrict__ nw1l, const float* __restrict__ nb1l,
                       const float* __restrict__ nw2l, const float* __restrict__ nb2l){
    __shared__ float sIn[2*HH];
    __shared__ float sY[HH];
    int node = blockIdx.x; int t = threadIdx.x;
    sIn[t]      = g_h[node*HH + t];
    sIn[HH + t] = g_magg[node*HH + t];
    __syncthreads();
    float a = nb1l[t];
    #pragma unroll 8
    for (int k = 0; k < 2*HH; ++k) a = fmaf(sIn[k], nw1l[k*HH + t], a);
    sY[t] = silu_f(a);
    __syncthreads();
    float o = nb2l[t];
    #pragma unroll 8
    for (int k = 0; k < HH; ++k) o = fmaf(sY[k], nw2l[k*HH + t], o);
    g_h[node*HH + t] = o;
}

// ---------------- wall MLP + final output --------------------------------------
__global__ void k_wall(const float* __restrict__ state,
                       const float* __restrict__ w1, const float* __restrict__ b1,
                       const float* __restrict__ w2, const float* __restrict__ b2,
                       const float* __restrict__ w3, const float* __restrict__ b3,
                       float* __restrict__ out){
    __shared__ float sIn[HH + 4];
    __shared__ float sY[HH];
    __shared__ float sM[4];
    int node = blockIdx.x; int t = threadIdx.x;
    sIn[t] = g_h[node*HH + t];
    if (t < 4){
        float4 st = ((const float4*)state)[node];
        float d = (t == 0) ? st.x : (t == 1) ? 1.0f - st.x
                : (t == 2) ? st.y : 1.0f - st.y;
        sIn[HH + t] = d;
    }
    __syncthreads();
    float a = b1[t];
    #pragma unroll 4
    for (int k = 0; k < HH + 4; ++k) a = fmaf(sIn[k], w1[k*HH + t], a);
    sY[t] = silu_f(a);
    __syncthreads();
    float a2 = b2[t];
    #pragma unroll 8
    for (int k = 0; k < HH; ++k) a2 = fmaf(sY[k], w2[k*HH + t], a2);
    __syncthreads();
    sY[t] = silu_f(a2);
    __syncthreads();
    if (t < 4){
        float m = b3[t];
        #pragma unroll 8
        for (int k = 0; k < HH; ++k) m = fmaf(sY[k], w3[k*4 + t], m);
        sM[t] = m;
    }
    __syncthreads();
    if (t < 2){
        float wf = (t == 0) ? (sM[0] - sM[1]) : (sM[2] - sM[3]);
        out[node*2 + t] = g_fsum[node*2 + t] + wf;
    }
}

// ---------------- launch --------------------------------------------------------
extern "C" void kernel_launch(void* const* d_in, const int* in_sizes, int n_in,
                              void* d_out, int out_size){
    const float* state = (const float*)d_in[0];
    const float* hiw  = (const float*)d_in[1];
    const float* hib  = (const float*)d_in[2];
    const float* ew1  = (const float*)d_in[3];
    const float* eb1  = (const float*)d_in[4];
    const float* ew2  = (const float*)d_in[5];
    const float* eb2  = (const float*)d_in[6];
    const float* fw1  = (const float*)d_in[7];
    const float* fb1  = (const float*)d_in[8];
    const float* fw2  = (const float*)d_in[9];
    const float* fb2  = (const float*)d_in[10];
    const float* nw1  = (const float*)d_in[11];
    const float* nb1  = (const float*)d_in[12];
    const float* nw2  = (const float*)d_in[13];
    const float* nb2  = (const float*)d_in[14];
    const float* ww1  = (const float*)d_in[15];
    const float* wb1  = (const float*)d_in[16];
    const float* ww2  = (const float*)d_in[17];
    const float* wb2  = (const float*)d_in[18];
    const float* ww3  = (const float*)d_in[19];
    const float* wb3  = (const float*)d_in[20];
    float* out = (float*)d_out;

    k_init<<<(NODES*HH)/256, 256>>>(state, hiw, hib);
    for (int l = 0; l < 3; ++l){
        k_prep<<<NODES, HH>>>(ew1 + l*132*HH, eb1 + l*HH);
        k_edge<<<NODES, 256>>>(state,
                               ew1 + l*132*HH,
                               ew2 + l*HH*HH, eb2 + l*HH,
                               fw1 + l*HH*HH, fb1 + l*HH,
                               fw2 + l*HH,    fb2 + l,
                               l);
        k_node<<<NODES, HH>>>(nw1 + l*2*HH*HH, nb1 + l*HH,
                              nw2 + l*HH*HH,   nb2 + l*HH);
    }
    k_wall<<<NODES, HH>>>(state, ww1, wb1, ww2, wb2, ww3, wb3, out);
}

// round 2
// speedup vs baseline: 1.2350x; 1.2350x over previous
#include <cuda_runtime.h>

#define BB 2
#define NN 512
#define HH 64
#define NODES (BB*NN)

// ---------------- scratch (device globals; no allocation allowed) -------------
__device__ float g_h[NODES*HH];      // node features
__device__ float g_a[NODES*HH];      // a_i = h_i @ W_i + b1   (per layer)
__device__ float g_ct[BB*HH*NN];     // c_j = h_j @ W_j, n-major: [b][n][j]
__device__ float g_magg[NODES*HH];   // sum_j m_ij
__device__ float g_fsum[NODES*2];    // accumulated pair forces across layers

// ---------------- helpers -----------------------------------------------------
__device__ __forceinline__ float silu_f(float x){
    float e = __expf(-x);
    return x * __fdividef(1.0f, 1.0f + e);
}
__device__ __forceinline__ unsigned long long splat2(float x){
    unsigned long long r; asm("mov.b64 %0, {%1, %1};" : "=l"(r) : "f"(x)); return r;
}
__device__ __forceinline__ unsigned long long ffma2(unsigned long long a,
                                                    unsigned long long b,
                                                    unsigned long long c){
    unsigned long long d;
    asm("fma.rn.f32x2 %0, %1, %2, %3;" : "=l"(d) : "l"(a), "l"(b), "l"(c));
    return d;
}
__device__ __forceinline__ float2 unpack2(unsigned long long v){
    float lo, hi; asm("mov.b64 {%0, %1}, %2;" : "=f"(lo), "=f"(hi) : "l"(v));
    return make_float2(lo, hi);
}

// 32-output half-GEMV: acc[16] u64 covers outputs [BASE, BASE+32)
template<int BASE>
__device__ __forceinline__ void gemv32(const float* __restrict__ sW,
                                       const float (&buf)[HH],
                                       unsigned long long (&acc)[16]){
    const ulonglong2* W = (const ulonglong2*)sW;
    constexpr int OFF = BASE / 4;   // ulonglong2 offset within a 64-float row
    #pragma unroll
    for (int k = 0; k < HH; ++k){
        unsigned long long tk = splat2(buf[k]);
        #pragma unroll
        for (int m = 0; m < 8; ++m){
            ulonglong2 w = W[k*16 + OFF + m];
            acc[2*m]   = ffma2(tk, w.x, acc[2*m]);
            acc[2*m+1] = ffma2(tk, w.y, acc[2*m+1]);
        }
    }
}

// ---------------- fused: h init + layer-0 prep ---------------------------------
__global__ void k_pre(const float* __restrict__ state,
                      const float* __restrict__ hw, const float* __restrict__ hb,
                      const float* __restrict__ ew1l, const float* __restrict__ eb1l){
    __shared__ float hs[HH];
    int node = blockIdx.x; int t = threadIdx.x;
    float4 st = ((const float4*)state)[node];
    float spd = sqrtf(st.z*st.z + st.w*st.w);
    float h = silu_f(spd * hw[t] + hb[t]);
    g_h[node*HH + t] = h;
    hs[t] = h;
    __syncthreads();
    float a = eb1l[t], c = 0.f;
    #pragma unroll 8
    for (int k = 0; k < HH; ++k){
        float hv = hs[k];
        a = fmaf(hv, ew1l[k*HH + t],        a);
        c = fmaf(hv, ew1l[(HH + k)*HH + t], c);
    }
    g_a[node*HH + t] = a;
    int b = node >> 9, j = node & (NN - 1);
    g_ct[(b*HH + t)*NN + j] = c;
}

// ---------------- edge kernel: CTA = (b,i), 128 thr, 4 j each ------------------
__global__ void __launch_bounds__(128, 3) k_edge(
    const float* __restrict__ state,
    const float* __restrict__ ew1l,
    const float* __restrict__ ew2l,
    const float* __restrict__ eb2l,
    const float* __restrict__ fw1l,
    const float* __restrict__ fb1l,
    const float* __restrict__ fw2l,
    const float* __restrict__ fb2l,
    int accumulate)
{
    __shared__ __align__(16) float sW2[HH*HH];
    __shared__ __align__(16) float sF1[HH*HH];
    __shared__ float  sA[HH];
    __shared__ float4 sWS[HH];
    __shared__ __align__(8) float sB2[HH];
    __shared__ __align__(8) float sFB1[HH];
    __shared__ float sFW2[HH];
    __shared__ float sMagg[HH];
    __shared__ float sFxy[2];

    int tid = threadIdx.x;
    int bi  = blockIdx.x;
    int b   = bi >> 9;
    int i   = bi & (NN - 1);

    {   // weight staging (coalesced float4)
        const float4* g2 = (const float4*)ew2l;
        const float4* g1 = (const float4*)fw1l;
        float4* s2 = (float4*)sW2;
        float4* s1 = (float4*)sF1;
        #pragma unroll
        for (int q = 0; q < 8; q++){
            s2[tid + 128*q] = g2[tid + 128*q];
            s1[tid + 128*q] = g1[tid + 128*q];
        }
    }
    if (tid < HH){
        sA[tid]   = g_a[bi*HH + tid];
        sB2[tid]  = eb2l[tid];
        sFB1[tid] = fb1l[tid];
        sFW2[tid] = fw2l[tid];
        sWS[tid]  = make_float4(ew1l[128*HH + tid], ew1l[129*HH + tid],
                                ew1l[130*HH + tid], ew1l[131*HH + tid]);
        sMagg[tid] = 0.0f;
    }
    if (tid < 2) sFxy[tid] = 0.0f;

    float4 sti = ((const float4*)state)[b*NN + i];
    float spi  = sti.z*sti.z + sti.w*sti.w;
    float fb2v = fb2l[0];
    __syncthreads();

    float fx = 0.f, fy = 0.f;

    #pragma unroll 1
    for (int it = 0; it < 4; ++it){
        int j = (it << 7) + tid;
        float4 stj = ((const float4*)state)[b*NN + j];
        float dxp = stj.x - sti.x;
        float dyp = stj.y - sti.y;
        float dsq = dxp*dxp + dyp*dyp;
        float invd = rsqrtf(dsq + 1e-8f);
        float nx2 = dxp * invd;
        float ny2 = dyp * invd;
        float dvx = stj.z - sti.z;
        float dvy = stj.w - sti.w;
        float spj = stj.z*stj.z + stj.w*stj.w;
        float appr = dvx*nx2 + dvy*ny2;

        // ---- stage 0: t1 = silu(a_i + c_j + scalars @ W_s) -----------------
        float buf[HH];
        const float* ct = &g_ct[b*HH*NN + j];
        #pragma unroll
        for (int n = 0; n < HH; ++n){
            float c = ct[n*NN];
            float4 w = sWS[n];
            float p = sA[n] + c;
            p = fmaf(dsq,  w.x, p);
            p = fmaf(spi,  w.y, p);
            p = fmaf(spj,  w.z, p);
            p = fmaf(appr, w.w, p);
            buf[n] = silu_f(p);
        }

        // ---- stage 1: t2 = silu(t1 @ W2 + b2), two 32-output passes --------
        float tmp[32];
        {
            unsigned long long acc[16];
            const unsigned long long* bp = (const unsigned long long*)sB2;
            #pragma unroll
            for (int m = 0; m < 16; ++m) acc[m] = bp[m];
            gemv32<0>(sW2, buf, acc);
            #pragma unroll
            for (int m = 0; m < 16; ++m){
                float2 v = unpack2(acc[m]);
                tmp[2*m]   = silu_f(v.x);
                tmp[2*m+1] = silu_f(v.y);
            }
        }
        {
            unsigned long long acc[16];
            const unsigned long long* bp = (const unsigned long long*)sB2;
            #pragma unroll
            for (int m = 0; m < 16; ++m) acc[m] = bp[16 + m];
            gemv32<32>(sW2, buf, acc);
            #pragma unroll
            for (int m = 0; m < 16; ++m){
                float2 v = unpack2(acc[m]);
                buf[32 + 2*m]   = silu_f(v.x);
                buf[32 + 2*m+1] = silu_f(v.y);
            }
        }
        #pragma unroll
        for (int m = 0; m < 32; ++m) buf[m] = tmp[m];

        float msk = (j == i) ? 0.0f : 1.0f;

        // ---- m_agg: warp butterfly over 32 pairs -> smem -------------------
        #pragma unroll
        for (int n = 0; n < HH; ++n){
            float v = msk * buf[n];
            v += __shfl_xor_sync(0xffffffffu, v, 16);
            v += __shfl_xor_sync(0xffffffffu, v, 8);
            v += __shfl_xor_sync(0xffffffffu, v, 4);
            v += __shfl_xor_sync(0xffffffffu, v, 2);
            v += __shfl_xor_sync(0xffffffffu, v, 1);
            if ((tid & 31) == 0) atomicAdd(&sMagg[n], v);
        }

        // ---- stage 2: fw = silu(t2 @ F1 + fb1) . fw2 + fb2 ------------------
        float fw = fb2v;
        {
            unsigned long long acc[16];
            const unsigned long long* bp = (const unsigned long long*)sFB1;
            #pragma unroll
            for (int m = 0; m < 16; ++m) acc[m] = bp[m];
            gemv32<0>(sF1, buf, acc);
            #pragma unroll
            for (int m = 0; m < 16; ++m){
                float2 v = unpack2(acc[m]);
                fw = fmaf(silu_f(v.x), sFW2[2*m],   fw);
                fw = fmaf(silu_f(v.y), sFW2[2*m+1], fw);
            }
        }
        {
            unsigned long long acc[16];
            const unsigned long long* bp = (const unsigned long long*)sFB1;
            #pragma unroll
            for (int m = 0; m < 16; ++m) acc[m] = bp[16 + m];
            gemv32<32>(sF1, buf, acc);
            #pragma unroll
            for (int m = 0; m < 16; ++m){
                float2 v = unpack2(acc[m]);
                fw = fmaf(silu_f(v.x), sFW2[32 + 2*m],   fw);
                fw = fmaf(silu_f(v.y), sFW2[32 + 2*m+1], fw);
            }
        }

        fw *= msk;
        fx = fmaf(fw, nx2, fx);
        fy = fmaf(fw, ny2, fy);
    }

    atomicAdd(&sFxy[0], fx);
    atomicAdd(&sFxy[1], fy);
    __syncthreads();

    if (tid < HH) g_magg[bi*HH + tid] = sMagg[tid];
    if (tid < 2){
        float v = sFxy[tid];
        if (accumulate) g_fsum[bi*2 + tid] += v;
        else            g_fsum[bi*2 + tid] = v;
    }
}

// ---------------- fused: node update + next-layer prep -------------------------
__global__ void k_nodeprep(const float* __restrict__ nw1l, const float* __restrict__ nb1l,
                           const float* __restrict__ nw2l, const float* __restrict__ nb2l,
                           const float* __restrict__ ew1n, const float* __restrict__ eb1n){
    __shared__ float sIn[2*HH];
    __shared__ float sY[HH];
    __shared__ float hs[HH];
    int node = blockIdx.x; int t = threadIdx.x;
    sIn[t]      = g_h[node*HH + t];
    sIn[HH + t] = g_magg[node*HH + t];
    __syncthreads();
    float a = nb1l[t];
    #pragma unroll 8
    for (int k = 0; k < 2*HH; ++k) a = fmaf(sIn[k], nw1l[k*HH + t], a);
    sY[t] = silu_f(a);
    __syncthreads();
    float o = nb2l[t];
    #pragma unroll 8
    for (int k = 0; k < HH; ++k) o = fmaf(sY[k], nw2l[k*HH + t], o);
    g_h[node*HH + t] = o;
    hs[t] = o;
    __syncthreads();
    float av = eb1n[t], c = 0.f;
    #pragma unroll 8
    for (int k = 0; k < HH; ++k){
        float hv = hs[k];
        av = fmaf(hv, ew1n[k*HH + t],        av);
        c  = fmaf(hv, ew1n[(HH + k)*HH + t], c);
    }
    g_a[node*HH + t] = av;
    int b = node >> 9, j = node & (NN - 1);
    g_ct[(b*HH + t)*NN + j] = c;
}

// ---------------- fused: last node update + wall MLP + output -------------------
__global__ void k_final(const float* __restrict__ state,
                        const float* __restrict__ nw1l, const float* __restrict__ nb1l,
                        const float* __restrict__ nw2l, const float* __restrict__ nb2l,
                        const float* __restrict__ w1, const float* __restrict__ b1,
                        const float* __restrict__ w2, const float* __restrict__ b2,
                        const float* __restrict__ w3, const float* __restrict__ b3,
                        float* __restrict__ out){
    __shared__ float sIn[2*HH];
    __shared__ float sY[HH];
    __shared__ float sH[HH + 4];
    __shared__ float sM[4];
    int node = blockIdx.x; int t = threadIdx.x;
    sIn[t]      = g_h[node*HH + t];
    sIn[HH + t] = g_magg[node*HH + t];
    __syncthreads();
    float a = nb1l[t];
    #pragma unroll 8
    for (int k = 0; k < 2*HH; ++k) a = fmaf(sIn[k], nw1l[k*HH + t], a);
    sY[t] = silu_f(a);
    __syncthreads();
    float o = nb2l[t];
    #pragma unroll 8
    for (int k = 0; k < HH; ++k) o = fmaf(sY[k], nw2l[k*HH + t], o);
    sH[t] = o;
    if (t < 4){
        float4 st = ((const float4*)state)[node];
        float d = (t == 0) ? st.x : (t == 1) ? 1.0f - st.x
                : (t == 2) ? st.y : 1.0f - st.y;
        sH[HH + t] = d;
    }
    __syncthreads();
    float a1 = b1[t];
    #pragma unroll 4
    for (int k = 0; k < HH + 4; ++k) a1 = fmaf(sH[k], w1[k*HH + t], a1);
    sY[t] = silu_f(a1);
    __syncthreads();
    float a2 = b2[t];
    #pragma unroll 8
    for (int k = 0; k < HH; ++k) a2 = fmaf(sY[k], w2[k*HH + t], a2);
    __syncthreads();
    sY[t] = silu_f(a2);
    __syncthreads();
    if (t < 4){
        float m = b3[t];
        #pragma unroll 8
        for (int k = 0; k < HH; ++k) m = fmaf(sY[k], w3[k*4 + t], m);
        sM[t] = m;
    }
    __syncthreads();
    if (t < 2){
        float wf = (t == 0) ? (sM[0] - sM[1]) : (sM[2] - sM[3]);
        out[node*2 + t] = g_fsum[node*2 + t] + wf;
    }
}

// ---------------- launch --------------------------------------------------------
extern "C" void kernel_launch(void* const* d_in, const int* in_sizes, int n_in,
                              void* d_out, int out_size){
    const float* state = (const float*)d_in[0];
    const float* hiw  = (const float*)d_in[1];
    const float* hib  = (const float*)d_in[2];
    const float* ew1  = (const float*)d_in[3];
    const float* eb1  = (const float*)d_in[4];
    const float* ew2  = (const float*)d_in[5];
    const float* eb2  = (const float*)d_in[6];
    const float* fw1  = (const float*)d_in[7];
    const float* fb1  = (const float*)d_in[8];
    const float* fw2  = (const float*)d_in[9];
    const float* fb2  = (const float*)d_in[10];
    const float* nw1  = (const float*)d_in[11];
    const float* nb1  = (const float*)d_in[12];
    const float* nw2  = (const float*)d_in[13];
    const float* nb2  = (const float*)d_in[14];
    const float* ww1  = (const float*)d_in[15];
    const float* wb1  = (const float*)d_in[16];
    const float* ww2  = (const float*)d_in[17];
    const float* wb2  = (const float*)d_in[18];
    const float* ww3  = (const float*)d_in[19];
    const float* wb3  = (const float*)d_in[20];
    float* out = (float*)d_out;

    k_pre<<<NODES, HH>>>(state, hiw, hib, ew1, eb1);
    for (int l = 0; l < 3; ++l){
        k_edge<<<NODES, 128>>>(state,
                               ew1 + l*132*HH,
                               ew2 + l*HH*HH, eb2 + l*HH,
                               fw1 + l*HH*HH, fb1 + l*HH,
                               fw2 + l*HH,    fb2 + l,
                               l);
        if (l < 2)
            k_nodeprep<<<NODES, HH>>>(nw1 + l*2*HH*HH, nb1 + l*HH,
                                      nw2 + l*HH*HH,   nb2 + l*HH,
                                      ew1 + (l+1)*132*HH, eb1 + (l+1)*HH);
    }
    k_final<<<NODES, HH>>>(state,
                           nw1 + 2*2*HH*HH, nb1 + 2*HH,
                           nw2 + 2*HH*HH,   nb2 + 2*HH,
                           ww1, wb1, ww2, wb2, ww3, wb3, out);
}

// round 3
// speedup vs baseline: 1.6377x; 1.3261x over previous
#include <cuda_runtime.h>

#define BB 2
#define NN 512
#define HH 64
#define NODES (BB*NN)
#define JT 128          // j-tile per iteration
#define NTILES (NN/JT)  // 4

// ---------------- scratch (device globals) -------------------------------------
__device__ float g_h[NODES*HH];
__device__ float g_a[NODES*HH];
__device__ float g_ct[BB*HH*NN];     // c_j, n-major: [b][n][j]
__device__ float g_magg[NODES*HH];
__device__ float g_fsum[NODES*2];

// ---------------- helpers -------------------------------------------------------
__device__ __forceinline__ float silu_f(float x){
    float e = __expf(-x);
    return x * __fdividef(1.0f, 1.0f + e);
}
__device__ __forceinline__ unsigned long long splat2(float x){
    unsigned long long r; asm("mov.b64 %0, {%1, %1};" : "=l"(r) : "f"(x)); return r;
}
__device__ __forceinline__ unsigned long long ffma2(unsigned long long a,
                                                    unsigned long long b,
                                                    unsigned long long c){
    unsigned long long d;
    asm("fma.rn.f32x2 %0, %1, %2, %3;" : "=l"(d) : "l"(a), "l"(b), "l"(c));
    return d;
}
__device__ __forceinline__ float2 unpack2(unsigned long long v){
    float lo, hi; asm("mov.b64 {%0, %1}, %2;" : "=f"(lo), "=f"(hi) : "l"(v));
    return make_float2(lo, hi);
}

// ---------------- edge smem layout ----------------------------------------------
struct EdgeSmem {
    float  T[HH*JT];        // T1 / T2 (aliased) 32KB
    float  W2[HH*HH];       // 16KB
    float  F1[HH*HH];       // 16KB
    float  A[HH];
    float4 WS[HH];
    float  B2[HH];          // u64-read: 8B aligned by construction
    float  FB1[HH];
    float  FW2[HH];
    float  Msk[JT], Nx[JT], Ny[JT];
    float  Magg[HH];
    float  Fxy[2];
};

// register-tiled 64-k GEMM accumulate: 4 rows x 8 cols per thread.
// SW: T is stored with the rg^ (k>>3) float4 swizzle (T2); else plain (T1).
template<bool SW>
__device__ __forceinline__ void gemm_acc(const float* __restrict__ sT,
                                         const float* __restrict__ sW,
                                         int rg, int cg,
                                         unsigned long long (&acc)[16]){
    #pragma unroll 16
    for (int k = 0; k < HH; ++k){
        int f4 = SW ? (rg ^ ((k >> 3) & 7)) : rg;
        float4 t = *(const float4*)&sT[k*JT + f4*4];
        ulonglong2 wa = *(const ulonglong2*)&sW[k*HH + cg*8];
        ulonglong2 wb = *(const ulonglong2*)&sW[k*HH + cg*8 + 4];
        unsigned long long tx = splat2(t.x), ty = splat2(t.y),
                           tz = splat2(t.z), tw = splat2(t.w);
        acc[0]  = ffma2(tx, wa.x, acc[0]);  acc[1]  = ffma2(tx, wa.y, acc[1]);
        acc[2]  = ffma2(tx, wb.x, acc[2]);  acc[3]  = ffma2(tx, wb.y, acc[3]);
        acc[4]  = ffma2(ty, wa.x, acc[4]);  acc[5]  = ffma2(ty, wa.y, acc[5]);
        acc[6]  = ffma2(ty, wb.x, acc[6]);  acc[7]  = ffma2(ty, wb.y, acc[7]);
        acc[8]  = ffma2(tz, wa.x, acc[8]);  acc[9]  = ffma2(tz, wa.y, acc[9]);
        acc[10] = ffma2(tz, wb.x, acc[10]); acc[11] = ffma2(tz, wb.y, acc[11]);
        acc[12] = ffma2(tw, wa.x, acc[12]); acc[13] = ffma2(tw, wa.y, acc[13]);
        acc[14] = ffma2(tw, wb.x, acc[14]); acc[15] = ffma2(tw, wb.y, acc[15]);
    }
}

// ---------------- fused: h init + layer-0 prep -----------------------------------
__global__ void k_pre(const float* __restrict__ state,
                      const float* __restrict__ hw, const float* __restrict__ hb,
                      const float* __restrict__ ew1l, const float* __restrict__ eb1l){
    __shared__ float hs[HH];
    int node = blockIdx.x; int t = threadIdx.x;
    float4 st = ((const float4*)state)[node];
    float spd = sqrtf(st.z*st.z + st.w*st.w);
    float h = silu_f(spd * hw[t] + hb[t]);
    g_h[node*HH + t] = h;
    hs[t] = h;
    __syncthreads();
    float a = eb1l[t], c = 0.f;
    #pragma unroll 8
    for (int k = 0; k < HH; ++k){
        float hv = hs[k];
        a = fmaf(hv, ew1l[k*HH + t],        a);
        c = fmaf(hv, ew1l[(HH + k)*HH + t], c);
    }
    g_a[node*HH + t] = a;
    int b = node >> 9, j = node & (NN - 1);
    g_ct[(b*HH + t)*NN + j] = c;
}

// ---------------- edge kernel: CTA = (b,i), tiled GEMM over j --------------------
__global__ void __launch_bounds__(256, 2) k_edge(
    const float* __restrict__ state,
    const float* __restrict__ ew1l,
    const float* __restrict__ ew2l,
    const float* __restrict__ eb2l,
    const float* __restrict__ fw1l,
    const float* __restrict__ fb1l,
    const float* __restrict__ fw2l,
    const float* __restrict__ fb2l,
    int accumulate)
{
    extern __shared__ __align__(16) char smem_raw[];
    EdgeSmem& s = *reinterpret_cast<EdgeSmem*>(smem_raw);

    int tid  = threadIdx.x;
    int lane = tid & 31;
    int cg   = tid & 7;          // col group: cols cg*8 .. cg*8+7
    int rg   = tid >> 3;         // row group: rows rg*4 .. rg*4+3
    int bi   = blockIdx.x;
    int b    = bi >> 9;
    int i    = bi & (NN - 1);

    {   // weight staging (coalesced float4)
        const float4* g2 = (const float4*)ew2l;
        const float4* g1 = (const float4*)fw1l;
        float4* s2 = (float4*)s.W2;
        float4* s1 = (float4*)s.F1;
        #pragma unroll
        for (int q = 0; q < 4; q++){
            s2[tid + 256*q] = g2[tid + 256*q];
            s1[tid + 256*q] = g1[tid + 256*q];
        }
    }
    if (tid < HH){
        s.A[tid]   = g_a[bi*HH + tid];
        s.B2[tid]  = eb2l[tid];
        s.FB1[tid] = fb1l[tid];
        s.FW2[tid] = fw2l[tid];
        s.WS[tid]  = make_float4(ew1l[128*HH + tid], ew1l[129*HH + tid],
                                 ew1l[130*HH + tid], ew1l[131*HH + tid]);
        s.Magg[tid] = 0.0f;
    }
    if (tid < 2) s.Fxy[tid] = 0.0f;

    float4 sti = ((const float4*)state)[b*NN + i];
    float spi  = sti.z*sti.z + sti.w*sti.w;
    float fb2v = fb2l[0];

    float fx = 0.f, fy = 0.f;
    __syncthreads();

    #pragma unroll 1
    for (int jt = 0; jt < NTILES; ++jt){
        // ================= stage 0: build T1 tile [n][jr] =======================
        {
            int jr = tid & (JT - 1);
            int half = tid >> 7;          // 0 or 1: which 32 n's
            int j = jt*JT + jr;
            float4 stj = ((const float4*)state)[b*NN + j];
            float dxp = stj.x - sti.x;
            float dyp = stj.y - sti.y;
            float dsq = dxp*dxp + dyp*dyp;
            float invd = rsqrtf(dsq + 1e-8f);
            float nx = dxp * invd;
            float ny = dyp * invd;
            float dvx = stj.z - sti.z;
            float dvy = stj.w - sti.w;
            float spj = stj.z*stj.z + stj.w*stj.w;
            float appr = dvx*nx + dvy*ny;
            if (half == 0){
                s.Msk[jr] = (j == i) ? 0.0f : 1.0f;
                s.Nx[jr]  = nx;
                s.Ny[jr]  = ny;
            }
            const float* ct = &g_ct[(b*HH + half*32)*NN + j];
            #pragma unroll 8
            for (int n = 0; n < 32; ++n){
                int nn = half*32 + n;
                float c = ct[n*NN];
                float4 w = s.WS[nn];
                float p = s.A[nn] + c;
                p = fmaf(dsq,  w.x, p);
                p = fmaf(spi,  w.y, p);
                p = fmaf(spj,  w.z, p);
                p = fmaf(appr, w.w, p);
                s.T[nn*JT + jr] = silu_f(p);
            }
        }
        __syncthreads();

        // ================= GEMM1: T2 = silu(T1^T @ W2 + b2) =====================
        unsigned long long acc[16];
        {
            const unsigned long long* bp = (const unsigned long long*)s.B2;
            #pragma unroll
            for (int cp = 0; cp < 4; ++cp){
                unsigned long long bv = bp[cg*4 + cp];
                acc[cp] = bv; acc[4+cp] = bv; acc[8+cp] = bv; acc[12+cp] = bv;
            }
        }
        gemm_acc<false>(s.T, s.W2, rg, cg, acc);

        float t2v[4][8];
        #pragma unroll
        for (int ri = 0; ri < 4; ++ri)
            #pragma unroll
            for (int cp = 0; cp < 4; ++cp){
                float2 v = unpack2(acc[ri*4 + cp]);
                t2v[ri][2*cp]   = silu_f(v.x);
                t2v[ri][2*cp+1] = silu_f(v.y);
            }

        // m_agg partials from accumulators (masked)
        {
            float mk[4];
            #pragma unroll
            for (int ri = 0; ri < 4; ++ri) mk[ri] = s.Msk[rg*4 + ri];
            #pragma unroll
            for (int c = 0; c < 8; ++c){
                float pm = t2v[0][c]*mk[0] + t2v[1][c]*mk[1]
                         + t2v[2][c]*mk[2] + t2v[3][c]*mk[3];
                pm += __shfl_xor_sync(0xffffffffu, pm, 8);
                pm += __shfl_xor_sync(0xffffffffu, pm, 16);
                if (lane < 8) atomicAdd(&s.Magg[lane*8 + c], pm);
            }
        }
        __syncthreads();   // all T1 reads done before overwrite

        // store T2 (transposed, float4-swizzled): T2[k2=c][j=r]
        #pragma unroll
        for (int ci = 0; ci < 8; ++ci){
            int k2 = cg*8 + ci;
            float4 v = make_float4(t2v[0][ci], t2v[1][ci], t2v[2][ci], t2v[3][ci]);
            *(float4*)&s.T[k2*JT + (rg ^ cg)*4] = v;
        }
        __syncthreads();

        // ================= GEMM2 + force epilogue ================================
        {
            const unsigned long long* bp = (const unsigned long long*)s.FB1;
            #pragma unroll
            for (int cp = 0; cp < 4; ++cp){
                unsigned long long bv = bp[cg*4 + cp];
                acc[cp] = bv; acc[4+cp] = bv; acc[8+cp] = bv; acc[12+cp] = bv;
            }
        }
        gemm_acc<true>(s.T, s.F1, rg, cg, acc);

        #pragma unroll
        for (int ri = 0; ri < 4; ++ri){
            float fwp = 0.f;
            #pragma unroll
            for (int cp = 0; cp < 4; ++cp){
                float2 v = unpack2(acc[ri*4 + cp]);
                fwp = fmaf(silu_f(v.x), s.FW2[cg*8 + 2*cp],     fwp);
                fwp = fmaf(silu_f(v.y), s.FW2[cg*8 + 2*cp + 1], fwp);
            }
            fwp += __shfl_xor_sync(0xffffffffu, fwp, 1);
            fwp += __shfl_xor_sync(0xffffffffu, fwp, 2);
            fwp += __shfl_xor_sync(0xffffffffu, fwp, 4);
            if ((lane & 7) == 0){
                int r = rg*4 + ri;
                float fw = (fwp + fb2v) * s.Msk[r];
                fx = fmaf(fw, s.Nx[r], fx);
                fy = fmaf(fw, s.Ny[r], fy);
            }
        }
        __syncthreads();   // before next tile's stage0 overwrites T
    }

    if ((lane & 7) == 0){
        atomicAdd(&s.Fxy[0], fx);
        atomicAdd(&s.Fxy[1], fy);
    }
    __syncthreads();

    if (tid < HH) g_magg[bi*HH + tid] = s.Magg[tid];
    if (tid < 2){
        float v = s.Fxy[tid];
        if (accumulate) g_fsum[bi*2 + tid] += v;
        else            g_fsum[bi*2 + tid] = v;
    }
}

// ---------------- fused: node update + next-layer prep ---------------------------
__global__ void k_nodeprep(const float* __restrict__ nw1l, const float* __restrict__ nb1l,
                           const float* __restrict__ nw2l, const float* __restrict__ nb2l,
                           const float* __restrict__ ew1n, const float* __restrict__ eb1n){
    __shared__ float sIn[2*HH];
    __shared__ float sY[HH];
    __shared__ float hs[HH];
    int node = blockIdx.x; int t = threadIdx.x;
    sIn[t]      = g_h[node*HH + t];
    sIn[HH + t] = g_magg[node*HH + t];
    __syncthreads();
    float a = nb1l[t];
    #pragma unroll 8
    for (int k = 0; k < 2*HH; ++k) a = fmaf(sIn[k], nw1l[k*HH + t], a);
    sY[t] = silu_f(a);
    __syncthreads();
    float o = nb2l[t];
    #pragma unroll 8
    for (int k = 0; k < HH; ++k) o = fmaf(sY[k], nw2l[k*HH + t], o);
    g_h[node*HH + t] = o;
    hs[t] = o;
    __syncthreads();
    float av = eb1n[t], c = 0.f;
    #pragma unroll 8
    for (int k = 0; k < HH; ++k){
        float hv = hs[k];
        av = fmaf(hv, ew1n[k*HH + t],        av);
        c  = fmaf(hv, ew1n[(HH + k)*HH + t], c);
    }
    g_a[node*HH + t] = av;
    int b = node >> 9, j = node & (NN - 1);
    g_ct[(b*HH + t)*NN + j] = c;
}

// ---------------- fused: last node update + wall MLP + output --------------------
__global__ void k_final(const float* __restrict__ state,
                        const float* __restrict__ nw1l, const float* __restrict__ nb1l,
                        const float* __restrict__ nw2l, const float* __restrict__ nb2l,
                        const float* __restrict__ w1, const float* __restrict__ b1,
                        const float* __restrict__ w2, const float* __restrict__ b2,
                        const float* __restrict__ w3, const float* __restrict__ b3,
                        float* __restrict__ out){
    __shared__ float sIn[2*HH];
    __shared__ float sY[HH];
    __shared__ float sH[HH + 4];
    __shared__ float sM[4];
    int node = blockIdx.x; int t = threadIdx.x;
    sIn[t]      = g_h[node*HH + t];
    sIn[HH + t] = g_magg[node*HH + t];
    __syncthreads();
    float a = nb1l[t];
    #pragma unroll 8
    for (int k = 0; k < 2*HH; ++k) a = fmaf(sIn[k], nw1l[k*HH + t], a);
    sY[t] = silu_f(a);
    __syncthreads();
    float o = nb2l[t];
    #pragma unroll 8
    for (int k = 0; k < HH; ++k) o = fmaf(sY[k], nw2l[k*HH + t], o);
    sH[t] = o;
    if (t < 4){
        float4 st = ((const float4*)state)[node];
        float d = (t == 0) ? st.x : (t == 1) ? 1.0f - st.x
                : (t == 2) ? st.y : 1.0f - st.y;
        sH[HH + t] = d;
    }
    __syncthreads();
    float a1 = b1[t];
    #pragma unroll 4
    for (int k = 0; k < HH + 4; ++k) a1 = fmaf(sH[k], w1[k*HH + t], a1);
    sY[t] = silu_f(a1);
    __syncthreads();
    float a2 = b2[t];
    #pragma unroll 8
    for (int k = 0; k < HH; ++k) a2 = fmaf(sY[k], w2[k*HH + t], a2);
    __syncthreads();
    sY[t] = silu_f(a2);
    __syncthreads();
    if (t < 4){
        float m = b3[t];
        #pragma unroll 8
        for (int k = 0; k < HH; ++k) m = fmaf(sY[k], w3[k*4 + t], m);
        sM[t] = m;
    }
    __syncthreads();
    if (t < 2){
        float wf = (t == 0) ? (sM[0] - sM[1]) : (sM[2] - sM[3]);
        out[node*2 + t] = g_fsum[node*2 + t] + wf;
    }
}

// ---------------- launch ----------------------------------------------------------
extern "C" void kernel_launch(void* const* d_in, const int* in_sizes, int n_in,
                              void* d_out, int out_size){
    const float* state = (const float*)d_in[0];
    const float* hiw  = (const float*)d_in[1];
    const float* hib  = (const float*)d_in[2];
    const float* ew1  = (const float*)d_in[3];
    const float* eb1  = (const float*)d_in[4];
    const float* ew2  = (const float*)d_in[5];
    const float* eb2  = (const float*)d_in[6];
    const float* fw1  = (const float*)d_in[7];
    const float* fb1  = (const float*)d_in[8];
    const float* fw2  = (const float*)d_in[9];
    const float* fb2  = (const float*)d_in[10];
    const float* nw1  = (const float*)d_in[11];
    const float* nb1  = (const float*)d_in[12];
    const float* nw2  = (const float*)d_in[13];
    const float* nb2  = (const float*)d_in[14];
    const float* ww1  = (const float*)d_in[15];
    const float* wb1  = (const float*)d_in[16];
    const float* ww2  = (const float*)d_in[17];
    const float* wb2  = (const float*)d_in[18];
    const float* ww3  = (const float*)d_in[19];
    const float* wb3  = (const float*)d_in[20];
    float* out = (float*)d_out;

    int smem = (int)sizeof(EdgeSmem);
    cudaFuncSetAttribute(k_edge, cudaFuncAttributeMaxDynamicSharedMemorySize, smem);

    k_pre<<<NODES, HH>>>(state, hiw, hib, ew1, eb1);
    for (int l = 0; l < 3; ++l){
        k_edge<<<NODES, 256, smem>>>(state,
                               ew1 + l*132*HH,
                               ew2 + l*HH*HH, eb2 + l*HH,
                               fw1 + l*HH*HH, fb1 + l*HH,
                               fw2 + l*HH,    fb2 + l,
                               l);
        if (l < 2)
            k_nodeprep<<<NODES, HH>>>(nw1 + l*2*HH*HH, nb1 + l*HH,
                                      nw2 + l*HH*HH,   nb2 + l*HH,
                                      ew1 + (l+1)*132*HH, eb1 + (l+1)*HH);
    }
    k_final<<<NODES, HH>>>(state,
                           nw1 + 2*2*HH*HH, nb1 + 2*HH,
                           nw2 + 2*HH*HH,   nb2 + 2*HH,
                           ww1, wb1, ww2, wb2, ww3, wb3, out);
}

// round 4
// speedup vs baseline: 2.2504x; 1.3741x over previous
#include <cuda_runtime.h>

#define BB 2
#define NN 512
#define HH 64
#define NODES (BB*NN)
#define JT 128
#define NTILES (NN/JT)

// ---------------- scratch (device globals) -------------------------------------
__device__ float g_h[NODES*HH];
__device__ float g_a[NODES*HH];
__device__ float g_ct[BB*HH*NN];     // c_j, n-major: [b][n][j]
__device__ float g_magg[NODES*HH];
__device__ float g_fsum[NODES*2];

// ---------------- helpers -------------------------------------------------------
__device__ __forceinline__ float silu_f(float x){
    float e = __expf(-x);
    return x * __fdividef(1.0f, 1.0f + e);
}
__device__ __forceinline__ unsigned long long splat2(float x){
    unsigned long long r; asm("mov.b64 %0, {%1, %1};" : "=l"(r) : "f"(x)); return r;
}
__device__ __forceinline__ unsigned long long ffma2(unsigned long long a,
                                                    unsigned long long b,
                                                    unsigned long long c){
    unsigned long long d;
    asm("fma.rn.f32x2 %0, %1, %2, %3;" : "=l"(d) : "l"(a), "l"(b), "l"(c));
    return d;
}
__device__ __forceinline__ float2 unpack2(unsigned long long v){
    float lo, hi; asm("mov.b64 {%0, %1}, %2;" : "=f"(lo), "=f"(hi) : "l"(v));
    return make_float2(lo, hi);
}

// ---------------- edge smem layout ----------------------------------------------
struct EdgeSmem {
    float  T[HH*JT];        // T1 / T2 (aliased) 32KB
    float  W2[HH*HH];       // 16KB
    float  F1[HH*HH];       // 16KB
    float  A[HH];
    float4 WS[HH];
    float  Msk[JT], Nx[JT], Ny[JT];
    float  Magg[HH];
    float  Fxy[2];
};

// 8x8 register-tiled GEMM accumulate over k=64.
// Thread covers rows rg*8..+7 (j) and cols {cg*4..+3} U {32+cg*4..+3}.
// acc[ri*4+p]: p=0,1 -> col pair (cg*4+2p, +1); p=2,3 -> (32+cg*4+2(p-2), +1).
// SW: T rows are stored with float4-chunk swizzle j4 ^ (k&7).
template<bool SW>
__device__ __forceinline__ void gemm_acc(const float* __restrict__ sT,
                                         const float* __restrict__ sW,
                                         int rg, int cg,
                                         unsigned long long (&acc)[32]){
    #pragma unroll 8
    for (int k = 0; k < HH; ++k){
        int c0 = SW ? ((rg*2)     ^ (k & 7)) : (rg*2);
        int c1 = SW ? ((rg*2 + 1) ^ (k & 7)) : (rg*2 + 1);
        float4 ta = *(const float4*)&sT[k*JT + c0*4];
        float4 tb = *(const float4*)&sT[k*JT + c1*4];
        ulonglong2 wa = *(const ulonglong2*)&sW[k*HH + cg*4];
        ulonglong2 wb = *(const ulonglong2*)&sW[k*HH + 32 + cg*4];
        float tv[8] = {ta.x, ta.y, ta.z, ta.w, tb.x, tb.y, tb.z, tb.w};
        #pragma unroll
        for (int ri = 0; ri < 8; ++ri){
            unsigned long long t2 = splat2(tv[ri]);
            acc[ri*4+0] = ffma2(t2, wa.x, acc[ri*4+0]);
            acc[ri*4+1] = ffma2(t2, wa.y, acc[ri*4+1]);
            acc[ri*4+2] = ffma2(t2, wb.x, acc[ri*4+2]);
            acc[ri*4+3] = ffma2(t2, wb.y, acc[ri*4+3]);
        }
    }
}

// ---------------- fused: h init + layer-0 prep -----------------------------------
__global__ void k_pre(const float* __restrict__ state,
                      const float* __restrict__ hw, const float* __restrict__ hb,
                      const float* __restrict__ ew1l, const float* __restrict__ eb1l){
    __shared__ float hs[HH];
    int node = blockIdx.x; int t = threadIdx.x;
    float4 st = ((const float4*)state)[node];
    float spd = sqrtf(st.z*st.z + st.w*st.w);
    float h = silu_f(spd * hw[t] + hb[t]);
    g_h[node*HH + t] = h;
    hs[t] = h;
    __syncthreads();
    float a = eb1l[t], c = 0.f;
    #pragma unroll 8
    for (int k = 0; k < HH; ++k){
        float hv = hs[k];
        a = fmaf(hv, ew1l[k*HH + t],        a);
        c = fmaf(hv, ew1l[(HH + k)*HH + t], c);
    }
    g_a[node*HH + t] = a;
    int b = node >> 9, j = node & (NN - 1);
    g_ct[(b*HH + t)*NN + j] = c;
}

// ---------------- edge kernel: CTA = (b,i), 128 thr, 8x8 tiles --------------------
__global__ void __launch_bounds__(128, 3) k_edge(
    const float* __restrict__ state,
    const float* __restrict__ ew1l,
    const float* __restrict__ ew2l,
    const float* __restrict__ eb2l,
    const float* __restrict__ fw1l,
    const float* __restrict__ fb1l,
    const float* __restrict__ fw2l,
    const float* __restrict__ fb2l,
    int accumulate)
{
    extern __shared__ __align__(16) char smem_raw[];
    EdgeSmem& s = *reinterpret_cast<EdgeSmem*>(smem_raw);

    int tid  = threadIdx.x;
    int lane = tid & 31;
    int cg   = tid & 7;
    int rg   = tid >> 3;          // 0..15
    int bi   = blockIdx.x;
    int b    = bi >> 9;
    int i    = bi & (NN - 1);

    {   // weight staging (coalesced float4)
        const float4* g2 = (const float4*)ew2l;
        const float4* g1 = (const float4*)fw1l;
        float4* s2 = (float4*)s.W2;
        float4* s1 = (float4*)s.F1;
        #pragma unroll
        for (int q = 0; q < 8; q++){
            s2[tid + 128*q] = g2[tid + 128*q];
            s1[tid + 128*q] = g1[tid + 128*q];
        }
    }
    if (tid < HH){
        s.A[tid]   = g_a[bi*HH + tid];
        s.WS[tid]  = make_float4(ew1l[128*HH + tid], ew1l[129*HH + tid],
                                 ew1l[130*HH + tid], ew1l[131*HH + tid]);
        s.Magg[tid] = 0.0f;
    }
    if (tid < 2) s.Fxy[tid] = 0.0f;

    // per-thread column constants in registers
    int cb[4];
    cb[0] = cg*4;      cb[1] = cg*4 + 2;
    cb[2] = 32 + cg*4; cb[3] = 32 + cg*4 + 2;
    unsigned long long b2p[4], fb1p[4];
    float w2c[8];
    #pragma unroll
    for (int p = 0; p < 4; ++p){
        b2p[p]  = *(const unsigned long long*)&eb2l[cb[p]];
        fb1p[p] = *(const unsigned long long*)&fb1l[cb[p]];
        w2c[2*p]   = fw2l[cb[p]];
        w2c[2*p+1] = fw2l[cb[p]+1];
    }

    float4 sti = ((const float4*)state)[b*NN + i];
    float spi  = sti.z*sti.z + sti.w*sti.w;
    float fb2v = fb2l[0];

    float fx = 0.f, fy = 0.f;

    #pragma unroll 1
    for (int jt = 0; jt < NTILES; ++jt){
        __syncthreads();   // previous tile's T reads complete
        // ================= stage 0: build T1 tile [n][j] ========================
        {
            int j = jt*JT + tid;
            float4 stj = ((const float4*)state)[b*NN + j];
            float dxp = stj.x - sti.x;
            float dyp = stj.y - sti.y;
            float dsq = dxp*dxp + dyp*dyp;
            float invd = rsqrtf(dsq + 1e-8f);
            float nx = dxp * invd;
            float ny = dyp * invd;
            float dvx = stj.z - sti.z;
            float dvy = stj.w - sti.w;
            float spj = stj.z*stj.z + stj.w*stj.w;
            float appr = dvx*nx + dvy*ny;
            s.Msk[tid] = (j == i) ? 0.0f : 1.0f;
            s.Nx[tid]  = nx;
            s.Ny[tid]  = ny;
            const float* ct = &g_ct[b*HH*NN + j];
            #pragma unroll 8
            for (int n = 0; n < HH; ++n){
                float c = ct[n*NN];
                float4 w = s.WS[n];
                float p = s.A[n] + c;
                p = fmaf(dsq,  w.x, p);
                p = fmaf(spi,  w.y, p);
                p = fmaf(spj,  w.z, p);
                p = fmaf(appr, w.w, p);
                s.T[n*JT + tid] = silu_f(p);
            }
        }
        __syncthreads();

        // ================= GEMM1: T2 = silu(T1^T @ W2 + b2) =====================
        unsigned long long acc[32];
        #pragma unroll
        for (int ri = 0; ri < 8; ++ri)
            #pragma unroll
            for (int p = 0; p < 4; ++p) acc[ri*4+p] = b2p[p];
        gemm_acc<false>(s.T, s.W2, rg, cg, acc);

        float mk[8];
        #pragma unroll
        for (int ri = 0; ri < 8; ++ri) mk[ri] = s.Msk[rg*8 + ri];

        __syncthreads();   // all T1 reads done before T2 overwrite

        #pragma unroll
        for (int p = 0; p < 4; ++p){
            float va[8], vb[8];
            #pragma unroll
            for (int ri = 0; ri < 8; ++ri){
                float2 v = unpack2(acc[ri*4+p]);
                va[ri] = silu_f(v.x);
                vb[ri] = silu_f(v.y);
            }
            #pragma unroll
            for (int h = 0; h < 2; ++h){
                const float* sv = h ? vb : va;
                int c = cb[p] + h;
                float pm = sv[0]*mk[0];
                #pragma unroll
                for (int ri = 1; ri < 8; ++ri) pm = fmaf(sv[ri], mk[ri], pm);
                pm += __shfl_xor_sync(0xffffffffu, pm, 8);
                pm += __shfl_xor_sync(0xffffffffu, pm, 16);
                if (lane < 8) atomicAdd(&s.Magg[c], pm);
                // store T2 row c, swizzled
                int sw = c & 7;
                *(float4*)&s.T[c*JT + (((rg*2)   ^ sw)*4)] =
                    make_float4(sv[0], sv[1], sv[2], sv[3]);
                *(float4*)&s.T[c*JT + (((rg*2+1) ^ sw)*4)] =
                    make_float4(sv[4], sv[5], sv[6], sv[7]);
            }
        }
        __syncthreads();

        // ================= GEMM2 + force epilogue ================================
        #pragma unroll
        for (int ri = 0; ri < 8; ++ri)
            #pragma unroll
            for (int p = 0; p < 4; ++p) acc[ri*4+p] = fb1p[p];
        gemm_acc<true>(s.T, s.F1, rg, cg, acc);

        #pragma unroll
        for (int ri = 0; ri < 8; ++ri){
            float fr = 0.f;
            #pragma unroll
            for (int p = 0; p < 4; ++p){
                float2 v = unpack2(acc[ri*4+p]);
                fr = fmaf(silu_f(v.x), w2c[2*p],   fr);
                fr = fmaf(silu_f(v.y), w2c[2*p+1], fr);
            }
            fr += __shfl_xor_sync(0xffffffffu, fr, 1);
            fr += __shfl_xor_sync(0xffffffffu, fr, 2);
            fr += __shfl_xor_sync(0xffffffffu, fr, 4);
            if (cg == 0){
                int r = rg*8 + ri;
                float fw = (fr + fb2v) * s.Msk[r];
                fx = fmaf(fw, s.Nx[r], fx);
                fy = fmaf(fw, s.Ny[r], fy);
            }
        }
    }

    if (cg == 0){
        atomicAdd(&s.Fxy[0], fx);
        atomicAdd(&s.Fxy[1], fy);
    }
    __syncthreads();

    if (tid < HH) g_magg[bi*HH + tid] = s.Magg[tid];
    if (tid < 2){
        float v = s.Fxy[tid];
        if (accumulate) g_fsum[bi*2 + tid] += v;
        else            g_fsum[bi*2 + tid] = v;
    }
}

// ---------------- fused: node update + next-layer prep ---------------------------
__global__ void k_nodeprep(const float* __restrict__ nw1l, const float* __restrict__ nb1l,
                           const float* __restrict__ nw2l, const float* __restrict__ nb2l,
                           const float* __restrict__ ew1n, const float* __restrict__ eb1n){
    __shared__ float sIn[2*HH];
    __shared__ float sY[HH];
    __shared__ float hs[HH];
    int node = blockIdx.x; int t = threadIdx.x;
    sIn[t]      = g_h[node*HH + t];
    sIn[HH + t] = g_magg[node*HH + t];
    __syncthreads();
    float a = nb1l[t];
    #pragma unroll 8
    for (int k = 0; k < 2*HH; ++k) a = fmaf(sIn[k], nw1l[k*HH + t], a);
    sY[t] = silu_f(a);
    __syncthreads();
    float o = nb2l[t];
    #pragma unroll 8
    for (int k = 0; k < HH; ++k) o = fmaf(sY[k], nw2l[k*HH + t], o);
    g_h[node*HH + t] = o;
    hs[t] = o;
    __syncthreads();
    float av = eb1n[t], c = 0.f;
    #pragma unroll 8
    for (int k = 0; k < HH; ++k){
        float hv = hs[k];
        av = fmaf(hv, ew1n[k*HH + t],        av);
        c  = fmaf(hv, ew1n[(HH + k)*HH + t], c);
    }
    g_a[node*HH + t] = av;
    int b = node >> 9, j = node & (NN - 1);
    g_ct[(b*HH + t)*NN + j] = c;
}

// ---------------- fused: last node update + wall MLP + output --------------------
__global__ void k_final(const float* __restrict__ state,
                        const float* __restrict__ nw1l, const float* __restrict__ nb1l,
                        const float* __restrict__ nw2l, const float* __restrict__ nb2l,
                        const float* __restrict__ w1, const float* __restrict__ b1,
                        const float* __restrict__ w2, const float* __restrict__ b2,
                        const float* __restrict__ w3, const float* __restrict__ b3,
                        float* __restrict__ out){
    __shared__ float sIn[2*HH];
    __shared__ float sY[HH];
    __shared__ float sH[HH + 4];
    __shared__ float sM[4];
    int node = blockIdx.x; int t = threadIdx.x;
    sIn[t]      = g_h[node*HH + t];
    sIn[HH + t] = g_magg[node*HH + t];
    __syncthreads();
    float a = nb1l[t];
    #pragma unroll 8
    for (int k = 0; k < 2*HH; ++k) a = fmaf(sIn[k], nw1l[k*HH + t], a);
    sY[t] = silu_f(a);
    __syncthreads();
    float o = nb2l[t];
    #pragma unroll 8
    for (int k = 0; k < HH; ++k) o = fmaf(sY[k], nw2l[k*HH + t], o);
    sH[t] = o;
    if (t < 4){
        float4 st = ((const float4*)state)[node];
        float d = (t == 0) ? st.x : (t == 1) ? 1.0f - st.x
                : (t == 2) ? st.y : 1.0f - st.y;
        sH[HH + t] = d;
    }
    __syncthreads();
    float a1 = b1[t];
    #pragma unroll 4
    for (int k = 0; k < HH + 4; ++k) a1 = fmaf(sH[k], w1[k*HH + t], a1);
    sY[t] = silu_f(a1);
    __syncthreads();
    float a2 = b2[t];
    #pragma unroll 8
    for (int k = 0; k < HH; ++k) a2 = fmaf(sY[k], w2[k*HH + t], a2);
    __syncthreads();
    sY[t] = silu_f(a2);
    __syncthreads();
    if (t < 4){
        float m = b3[t];
        #pragma unroll 8
        for (int k = 0; k < HH; ++k) m = fmaf(sY[k], w3[k*4 + t], m);
        sM[t] = m;
    }
    __syncthreads();
    if (t < 2){
        float wf = (t == 0) ? (sM[0] - sM[1]) : (sM[2] - sM[3]);
        out[node*2 + t] = g_fsum[node*2 + t] + wf;
    }
}

// ---------------- launch ----------------------------------------------------------
extern "C" void kernel_launch(void* const* d_in, const int* in_sizes, int n_in,
                              void* d_out, int out_size){
    const float* state = (const float*)d_in[0];
    const float* hiw  = (const float*)d_in[1];
    const float* hib  = (const float*)d_in[2];
    const float* ew1  = (const float*)d_in[3];
    const float* eb1  = (const float*)d_in[4];
    const float* ew2  = (const float*)d_in[5];
    const float* eb2  = (const float*)d_in[6];
    const float* fw1  = (const float*)d_in[7];
    const float* fb1  = (const float*)d_in[8];
    const float* fw2  = (const float*)d_in[9];
    const float* fb2  = (const float*)d_in[10];
    const float* nw1  = (const float*)d_in[11];
    const float* nb1  = (const float*)d_in[12];
    const float* nw2  = (const float*)d_in[13];
    const float* nb2  = (const float*)d_in[14];
    const float* ww1  = (const float*)d_in[15];
    const float* wb1  = (const float*)d_in[16];
    const float* ww2  = (const float*)d_in[17];
    const float* wb2  = (const float*)d_in[18];
    const float* ww3  = (const float*)d_in[19];
    const float* wb3  = (const float*)d_in[20];
    float* out = (float*)d_out;

    int smem = (int)sizeof(EdgeSmem);
    cudaFuncSetAttribute(k_edge, cudaFuncAttributeMaxDynamicSharedMemorySize, smem);

    k_pre<<<NODES, HH>>>(state, hiw, hib, ew1, eb1);
    for (int l = 0; l < 3; ++l){
        k_edge<<<NODES, 128, smem>>>(state,
                               ew1 + l*132*HH,
                               ew2 + l*HH*HH, eb2 + l*HH,
                               fw1 + l*HH*HH, fb1 + l*HH,
                               fw2 + l*HH,    fb2 + l,
                               l);
        if (l < 2)
            k_nodeprep<<<NODES, HH>>>(nw1 + l*2*HH*HH, nb1 + l*HH,
                                      nw2 + l*HH*HH,   nb2 + l*HH,
                                      ew1 + (l+1)*132*HH, eb1 + (l+1)*HH);
    }
    k_final<<<NODES, HH>>>(state,
                           nw1 + 2*2*HH*HH, nb1 + 2*HH,
                           nw2 + 2*HH*HH,   nb2 + 2*HH,
                           ww1, wb1, ww2, wb2, ww3, wb3, out);
}

// round 5
// speedup vs baseline: 2.3182x; 1.0301x over previous
#include <cuda_runtime.h>

#define BB 2
#define NN 512
#define HH 64
#define NODES (BB*NN)
#define JT 128
#define NTILES (NN/JT)

// ---------------- scratch (device globals) -------------------------------------
__device__ float g_h[NODES*HH];
__device__ float g_a[NODES*HH];
__device__ float g_ct[BB*HH*NN];     // c_j, n-major: [b][n][j]
__device__ float g_magg[NODES*HH];
__device__ float g_fsum[NODES*2];

// ---------------- helpers -------------------------------------------------------
__device__ __forceinline__ float silu_f(float x){
    float e = __expf(-x);
    return x * __fdividef(1.0f, 1.0f + e);
}
__device__ __forceinline__ unsigned long long splat2(float x){
    unsigned long long r; asm("mov.b64 %0, {%1, %1};" : "=l"(r) : "f"(x)); return r;
}
__device__ __forceinline__ unsigned long long ffma2(unsigned long long a,
                                                    unsigned long long b,
                                                    unsigned long long c){
    unsigned long long d;
    asm("fma.rn.f32x2 %0, %1, %2, %3;" : "=l"(d) : "l"(a), "l"(b), "l"(c));
    return d;
}
__device__ __forceinline__ float2 unpack2(unsigned long long v){
    float lo, hi; asm("mov.b64 {%0, %1}, %2;" : "=f"(lo), "=f"(hi) : "l"(v));
    return make_float2(lo, hi);
}

// ---------------- edge smem layout ----------------------------------------------
struct EdgeSmem {
    float  T1[HH*JT];       // 32KB
    float  T2[HH*JT];       // 32KB
    float  W2[HH*HH];       // 16KB
    float  F1[HH*HH];       // 16KB
    float  A[HH];
    float4 WS[HH];
    float  Msk[JT], Nx[JT], Ny[JT];
    float  Magg[HH];
    float  Fxy[2];
};

// 4x8 register-tiled GEMM over k=64.
// Thread: rows rg*4..+3 (j), cols {cg*4..+3} U {32+cg*4..+3}.
// acc[ri*4+p]: p=0,1 -> (cg*4+2p, +1); p=2,3 -> (32+cg*4+2(p-2), +1).
// SW=false: T chunks plain (chunk=rg). SW=true: chunk = rg ^ (((k>>2)&7)<<2).
template<bool SW>
__device__ __forceinline__ void gemm_acc(const float* __restrict__ sT,
                                         const float* __restrict__ sW,
                                         int rg, int cg,
                                         unsigned long long (&acc)[16]){
    #pragma unroll 8
    for (int k = 0; k < HH; ++k){
        int ch = SW ? (rg ^ (((k >> 2) & 7) << 2)) : rg;
        float4 t = *(const float4*)&sT[k*JT + ch*4];
        ulonglong2 wa = *(const ulonglong2*)&sW[k*HH + cg*4];
        ulonglong2 wb = *(const ulonglong2*)&sW[k*HH + 32 + cg*4];
        float tv[4] = {t.x, t.y, t.z, t.w};
        #pragma unroll
        for (int ri = 0; ri < 4; ++ri){
            unsigned long long t2 = splat2(tv[ri]);
            acc[ri*4+0] = ffma2(t2, wa.x, acc[ri*4+0]);
            acc[ri*4+1] = ffma2(t2, wa.y, acc[ri*4+1]);
            acc[ri*4+2] = ffma2(t2, wb.x, acc[ri*4+2]);
            acc[ri*4+3] = ffma2(t2, wb.y, acc[ri*4+3]);
        }
    }
}

// ---------------- fused: h init + layer-0 prep -----------------------------------
__global__ void k_pre(const float* __restrict__ state,
                      const float* __restrict__ hw, const float* __restrict__ hb,
                      const float* __restrict__ ew1l, const float* __restrict__ eb1l){
    __shared__ float hs[HH];
    int node = blockIdx.x; int t = threadIdx.x;
    float4 st = ((const float4*)state)[node];
    float spd = sqrtf(st.z*st.z + st.w*st.w);
    float h = silu_f(spd * hw[t] + hb[t]);
    g_h[node*HH + t] = h;
    hs[t] = h;
    __syncthreads();
    float a = eb1l[t], c = 0.f;
    #pragma unroll 8
    for (int k = 0; k < HH; ++k){
        float hv = hs[k];
        a = fmaf(hv, ew1l[k*HH + t],        a);
        c = fmaf(hv, ew1l[(HH + k)*HH + t], c);
    }
    g_a[node*HH + t] = a;
    int b = node >> 9, j = node & (NN - 1);
    g_ct[(b*HH + t)*NN + j] = c;
}

// ---------------- edge kernel: CTA = (b,i), 256 thr, 4x8 tiles --------------------
__global__ void __launch_bounds__(256, 2) k_edge(
    const float* __restrict__ state,
    const float* __restrict__ ew1l,
    const float* __restrict__ ew2l,
    const float* __restrict__ eb2l,
    const float* __restrict__ fw1l,
    const float* __restrict__ fb1l,
    const float* __restrict__ fw2l,
    const float* __restrict__ fb2l,
    int accumulate)
{
    extern __shared__ __align__(16) char smem_raw[];
    EdgeSmem& s = *reinterpret_cast<EdgeSmem*>(smem_raw);

    int tid  = threadIdx.x;
    int lane = tid & 31;
    int cg   = tid & 7;
    int rg   = tid >> 3;          // 0..31 -> j rows rg*4..+3
    int bi   = blockIdx.x;
    int b    = bi >> 9;
    int i    = bi & (NN - 1);

    {   // weight staging (coalesced float4)
        const float4* g2 = (const float4*)ew2l;
        const float4* g1 = (const float4*)fw1l;
        float4* s2 = (float4*)s.W2;
        float4* s1 = (float4*)s.F1;
        #pragma unroll
        for (int q = 0; q < 4; q++){
            s2[tid + 256*q] = g2[tid + 256*q];
            s1[tid + 256*q] = g1[tid + 256*q];
        }
    }
    if (tid < HH){
        s.A[tid]   = g_a[bi*HH + tid];
        s.WS[tid]  = make_float4(ew1l[128*HH + tid], ew1l[129*HH + tid],
                                 ew1l[130*HH + tid], ew1l[131*HH + tid]);
        s.Magg[tid] = 0.0f;
    }
    if (tid < 2) s.Fxy[tid] = 0.0f;

    // per-thread column constants in registers
    int cb[4];
    cb[0] = cg*4;      cb[1] = cg*4 + 2;
    cb[2] = 32 + cg*4; cb[3] = 32 + cg*4 + 2;
    unsigned long long b2p[4], fb1p[4];
    float w2c[8];
    #pragma unroll
    for (int p = 0; p < 4; ++p){
        b2p[p]  = *(const unsigned long long*)&eb2l[cb[p]];
        fb1p[p] = *(const unsigned long long*)&fb1l[cb[p]];
        w2c[2*p]   = fw2l[cb[p]];
        w2c[2*p+1] = fw2l[cb[p]+1];
    }
    int chT2 = rg ^ (cg << 2);    // conflict-free T2 store chunk (const per thread)

    float4 sti = ((const float4*)state)[b*NN + i];
    float spi  = sti.z*sti.z + sti.w*sti.w;
    float fb2v = fb2l[0];

    float fx = 0.f, fy = 0.f;
    __syncthreads();

    #pragma unroll 1
    for (int jt = 0; jt < NTILES; ++jt){
        // ================= stage 0: build T1 tile [n][j] ========================
        {
            int jr   = tid & (JT - 1);
            int half = tid >> 7;          // 0/1 -> which 32 n's
            int j = jt*JT + jr;
            float4 stj = ((const float4*)state)[b*NN + j];
            float dxp = stj.x - sti.x;
            float dyp = stj.y - sti.y;
            float dsq = dxp*dxp + dyp*dyp;
            float invd = rsqrtf(dsq + 1e-8f);
            float nx = dxp * invd;
            float ny = dyp * invd;
            float dvx = stj.z - sti.z;
            float dvy = stj.w - sti.w;
            float spj = stj.z*stj.z + stj.w*stj.w;
            float appr = dvx*nx + dvy*ny;
            if (half == 0){
                s.Msk[jr] = (j == i) ? 0.0f : 1.0f;
                s.Nx[jr]  = nx;
                s.Ny[jr]  = ny;
            }
            const float* ct = &g_ct[(b*HH + half*32)*NN + j];
            #pragma unroll 8
            for (int n = 0; n < 32; ++n){
                int nn = half*32 + n;
                float c = ct[n*NN];
                float4 w = s.WS[nn];
                float p = s.A[nn] + c;
                p = fmaf(dsq,  w.x, p);
                p = fmaf(spi,  w.y, p);
                p = fmaf(spj,  w.z, p);
                p = fmaf(appr, w.w, p);
                s.T1[nn*JT + jr] = silu_f(p);
            }
        }
        __syncthreads();    // (A) T1/Msk ready; also fences prev-tile GEMM2

        // snapshot this thread's row geometry into registers
        float mk[4], nxr[4], nyr[4];
        #pragma unroll
        for (int q = 0; q < 4; ++q){
            mk[q]  = s.Msk[rg*4 + q];
            nxr[q] = s.Nx[rg*4 + q];
            nyr[q] = s.Ny[rg*4 + q];
        }

        // ================= GEMM1: T2 = silu(T1^T @ W2 + b2) =====================
        unsigned long long acc[16];
        #pragma unroll
        for (int ri = 0; ri < 4; ++ri)
            #pragma unroll
            for (int p = 0; p < 4; ++p) acc[ri*4+p] = b2p[p];
        gemm_acc<false>(s.T1, s.W2, rg, cg, acc);

        #pragma unroll
        for (int p = 0; p < 4; ++p){
            float va[4], vb[4];
            #pragma unroll
            for (int ri = 0; ri < 4; ++ri){
                float2 v = unpack2(acc[ri*4+p]);
                va[ri] = silu_f(v.x);
                vb[ri] = silu_f(v.y);
            }
            #pragma unroll
            for (int h = 0; h < 2; ++h){
                const float* sv = h ? vb : va;
                int c = cb[p] + h;
                float pm = sv[0]*mk[0];
                #pragma unroll
                for (int ri = 1; ri < 4; ++ri) pm = fmaf(sv[ri], mk[ri], pm);
                pm += __shfl_xor_sync(0xffffffffu, pm, 8);
                pm += __shfl_xor_sync(0xffffffffu, pm, 16);
                if (lane < 8) atomicAdd(&s.Magg[c], pm);
                *(float4*)&s.T2[c*JT + chT2*4] =
                    make_float4(sv[0], sv[1], sv[2], sv[3]);
            }
        }
        __syncthreads();    // (B) T2 ready

        // ================= GEMM2 + force epilogue ================================
        #pragma unroll
        for (int ri = 0; ri < 4; ++ri)
            #pragma unroll
            for (int p = 0; p < 4; ++p) acc[ri*4+p] = fb1p[p];
        gemm_acc<true>(s.T2, s.F1, rg, cg, acc);

        #pragma unroll
        for (int ri = 0; ri < 4; ++ri){
            float fr = 0.f;
            #pragma unroll
            for (int p = 0; p < 4; ++p){
                float2 v = unpack2(acc[ri*4+p]);
                fr = fmaf(silu_f(v.x), w2c[2*p],   fr);
                fr = fmaf(silu_f(v.y), w2c[2*p+1], fr);
            }
            fr += __shfl_xor_sync(0xffffffffu, fr, 1);
            fr += __shfl_xor_sync(0xffffffffu, fr, 2);
            fr += __shfl_xor_sync(0xffffffffu, fr, 4);
            if (cg == 0){
                float fw = (fr + fb2v) * mk[ri];
                fx = fmaf(fw, nxr[ri], fx);
                fy = fmaf(fw, nyr[ri], fy);
            }
        }
        // no barrier: next stage0 writes T1 only (GEMM1 reads fenced by sync B)
    }

    if (cg == 0){
        atomicAdd(&s.Fxy[0], fx);
        atomicAdd(&s.Fxy[1], fy);
    }
    __syncthreads();

    if (tid < HH) g_magg[bi*HH + tid] = s.Magg[tid];
    if (tid < 2){
        float v = s.Fxy[tid];
        if (accumulate) g_fsum[bi*2 + tid] += v;
        else            g_fsum[bi*2 + tid] = v;
    }
}

// ---------------- fused: node update + next-layer prep ---------------------------
__global__ void k_nodeprep(const float* __restrict__ nw1l, const float* __restrict__ nb1l,
                           const float* __restrict__ nw2l, const float* __restrict__ nb2l,
                           const float* __restrict__ ew1n, const float* __restrict__ eb1n){
    __shared__ float sIn[2*HH];
    __shared__ float sY[HH];
    __shared__ float hs[HH];
    int node = blockIdx.x; int t = threadIdx.x;
    sIn[t]      = g_h[node*HH + t];
    sIn[HH + t] = g_magg[node*HH + t];
    __syncthreads();
    float a = nb1l[t];
    #pragma unroll 8
    for (int k = 0; k < 2*HH; ++k) a = fmaf(sIn[k], nw1l[k*HH + t], a);
    sY[t] = silu_f(a);
    __syncthreads();
    float o = nb2l[t];
    #pragma unroll 8
    for (int k = 0; k < HH; ++k) o = fmaf(sY[k], nw2l[k*HH + t], o);
    g_h[node*HH + t] = o;
    hs[t] = o;
    __syncthreads();
    float av = eb1n[t], c = 0.f;
    #pragma unroll 8
    for (int k = 0; k < HH; ++k){
        float hv = hs[k];
        av = fmaf(hv, ew1n[k*HH + t],        av);
        c  = fmaf(hv, ew1n[(HH + k)*HH + t], c);
    }
    g_a[node*HH + t] = av;
    int b = node >> 9, j = node & (NN - 1);
    g_ct[(b*HH + t)*NN + j] = c;
}

// ---------------- fused: last node update + wall MLP + output --------------------
__global__ void k_final(const float* __restrict__ state,
                        const float* __restrict__ nw1l, const float* __restrict__ nb1l,
                        const float* __restrict__ nw2l, const float* __restrict__ nb2l,
                        const float* __restrict__ w1, const float* __restrict__ b1,
                        const float* __restrict__ w2, const float* __restrict__ b2,
                        const float* __restrict__ w3, const float* __restrict__ b3,
                        float* __restrict__ out){
    __shared__ float sIn[2*HH];
    __shared__ float sY[HH];
    __shared__ float sH[HH + 4];
    __shared__ float sM[4];
    int node = blockIdx.x; int t = threadIdx.x;
    sIn[t]      = g_h[node*HH + t];
    sIn[HH + t] = g_magg[node*HH + t];
    __syncthreads();
    float a = nb1l[t];
    #pragma unroll 8
    for (int k = 0; k < 2*HH; ++k) a = fmaf(sIn[k], nw1l[k*HH + t], a);
    sY[t] = silu_f(a);
    __syncthreads();
    float o = nb2l[t];
    #pragma unroll 8
    for (int k = 0; k < HH; ++k) o = fmaf(sY[k], nw2l[k*HH + t], o);
    sH[t] = o;
    if (t < 4){
        float4 st = ((const float4*)state)[node];
        float d = (t == 0) ? st.x : (t == 1) ? 1.0f - st.x
                : (t == 2) ? st.y : 1.0f - st.y;
        sH[HH + t] = d;
    }
    __syncthreads();
    float a1 = b1[t];
    #pragma unroll 4
    for (int k = 0; k < HH + 4; ++k) a1 = fmaf(sH[k], w1[k*HH + t], a1);
    sY[t] = silu_f(a1);
    __syncthreads();
    float a2 = b2[t];
    #pragma unroll 8
    for (int k = 0; k < HH; ++k) a2 = fmaf(sY[k], w2[k*HH + t], a2);
    __syncthreads();
    sY[t] = silu_f(a2);
    __syncthreads();
    if (t < 4){
        float m = b3[t];
        #pragma unroll 8
        for (int k = 0; k < HH; ++k) m = fmaf(sY[k], w3[k*4 + t], m);
        sM[t] = m;
    }
    __syncthreads();
    if (t < 2){
        float wf = (t == 0) ? (sM[0] - sM[1]) : (sM[2] - sM[3]);
        out[node*2 + t] = g_fsum[node*2 + t] + wf;
    }
}

// ---------------- launch ----------------------------------------------------------
extern "C" void kernel_launch(void* const* d_in, const int* in_sizes, int n_in,
                              void* d_out, int out_size){
    const float* state = (const float*)d_in[0];
    const float* hiw  = (const float*)d_in[1];
    const float* hib  = (const float*)d_in[2];
    const float* ew1  = (const float*)d_in[3];
    const float* eb1  = (const float*)d_in[4];
    const float* ew2  = (const float*)d_in[5];
    const float* eb2  = (const float*)d_in[6];
    const float* fw1  = (const float*)d_in[7];
    const float* fb1  = (const float*)d_in[8];
    const float* fw2  = (const float*)d_in[9];
    const float* fb2  = (const float*)d_in[10];
    const float* nw1  = (const float*)d_in[11];
    const float* nb1  = (const float*)d_in[12];
    const float* nw2  = (const float*)d_in[13];
    const float* nb2  = (const float*)d_in[14];
    const float* ww1  = (const float*)d_in[15];
    const float* wb1  = (const float*)d_in[16];
    const float* ww2  = (const float*)d_in[17];
    const float* wb2  = (const float*)d_in[18];
    const float* ww3  = (const float*)d_in[19];
    const float* wb3  = (const float*)d_in[20];
    float* out = (float*)d_out;

    int smem = (int)sizeof(EdgeSmem);
    cudaFuncSetAttribute(k_edge, cudaFuncAttributeMaxDynamicSharedMemorySize, smem);

    k_pre<<<NODES, HH>>>(state, hiw, hib, ew1, eb1);
    for (int l = 0; l < 3; ++l){
        k_edge<<<NODES, 256, smem>>>(state,
                               ew1 + l*132*HH,
                               ew2 + l*HH*HH, eb2 + l*HH,
                               fw1 + l*HH*HH, fb1 + l*HH,
                               fw2 + l*HH,    fb2 + l,
                               l);
        if (l < 2)
            k_nodeprep<<<NODES, HH>>>(nw1 + l*2*HH*HH, nb1 + l*HH,
                                      nw2 + l*HH*HH,   nb2 + l*HH,
                                      ew1 + (l+1)*132*HH, eb1 + (l+1)*HH);
    }
    k_final<<<NODES, HH>>>(state,
                           nw1 + 2*2*HH*HH, nb1 + 2*HH,
                           nw2 + 2*HH*HH,   nb2 + 2*HH,
                           ww1, wb1, ww2, wb2, ww3, wb3, out);
}

// round 8
// speedup vs baseline: 3.6024x; 1.5540x over previous
#include <cuda_runtime.h>
#include <cuda_fp16.h>
#include <cstdint>

#define BB 2
#define NN 512
#define HH 64
#define NODES (BB*NN)
#define JT 128
#define NTILES (NN/JT)

// ---------------- scratch (device globals) -------------------------------------
__device__ float g_h[NODES*HH];
__device__ float g_a[NODES*HH];
__device__ float g_ct[BB*HH*NN];          // c_j, n-major: [b][n][j]
__device__ float g_magg[NODES*HH];
__device__ float g_fsum[NODES*2];
__device__ __half g_wh[3][4][HH*HH];      // per layer: W2hi,W2lo,F1hi,F1lo (swizzled [k][n] fp16)

// ---------------- helpers -------------------------------------------------------
__device__ __forceinline__ float silu_f(float x){
    float e = __expf(-x);
    return x * __fdividef(1.0f, 1.0f + e);
}
__device__ __forceinline__ uint32_t smem_u32(const void* p){
    uint32_t a;
    asm("{ .reg .u64 t; cvta.to.shared.u64 t, %1; cvt.u32.u64 %0, t; }" : "=r"(a) : "l"(p));
    return a;
}
__device__ __forceinline__ uint32_t sw128(uint32_t b){ return b ^ ((b >> 3) & 0x70); }

__device__ __forceinline__ void ldsm4(uint32_t& r0, uint32_t& r1, uint32_t& r2, uint32_t& r3, uint32_t a){
    asm volatile("ldmatrix.sync.aligned.m8n8.x4.shared.b16 {%0,%1,%2,%3}, [%4];"
                 : "=r"(r0), "=r"(r1), "=r"(r2), "=r"(r3) : "r"(a));
}
__device__ __forceinline__ void ldsm4t(uint32_t& r0, uint32_t& r1, uint32_t& r2, uint32_t& r3, uint32_t a){
    asm volatile("ldmatrix.sync.aligned.m8n8.x4.trans.shared.b16 {%0,%1,%2,%3}, [%4];"
                 : "=r"(r0), "=r"(r1), "=r"(r2), "=r"(r3) : "r"(a));
}
__device__ __forceinline__ void mma16816(float* d, uint32_t a0, uint32_t a1, uint32_t a2, uint32_t a3,
                                         uint32_t b0, uint32_t b1){
    asm volatile("mma.sync.aligned.m16n8k16.row.col.f32.f16.f16.f32 "
                 "{%0,%1,%2,%3},{%4,%5,%6,%7},{%8,%9},{%0,%1,%2,%3};"
                 : "+f"(d[0]), "+f"(d[1]), "+f"(d[2]), "+f"(d[3])
                 : "r"(a0), "r"(a1), "r"(a2), "r"(a3), "r"(b0), "r"(b1));
}
__device__ __forceinline__ uint32_t pack_h2(__half lo, __half hi){
    return (uint32_t)__half_as_ushort(lo) | ((uint32_t)__half_as_ushort(hi) << 16);
}

// fp16 split-GEMM: D[128x64] += T[128x64] @ W[64x64] with 3-product compensation.
// T stored [m][k] fp16 SW128; W stored [k][n] fp16 SW128. Warp owns m-tile m0.
__device__ __forceinline__ void gemm_mma(uint32_t Th, uint32_t Tl, uint32_t Wh, uint32_t Wl,
                                         int m0, int lane, float acc[8][4]){
    int rA    = m0 + (lane & 7) + ((lane >> 3) & 1) * 8;
    int colA8 = ((lane >> 4) & 1) * 8;
    int krB   = (lane & 7) + ((lane >> 3) & 1) * 8;
    int ncB8  = ((lane >> 4) & 1) * 8;
    #pragma unroll
    for (int kk = 0; kk < 4; ++kk){
        uint32_t aoff = sw128((uint32_t)(rA*128 + (kk*16 + colA8)*2));
        uint32_t ah0, ah1, ah2, ah3, al0, al1, al2, al3;
        ldsm4(ah0, ah1, ah2, ah3, Th + aoff);
        ldsm4(al0, al1, al2, al3, Tl + aoff);
        #pragma unroll
        for (int np = 0; np < 4; ++np){
            uint32_t boff = sw128((uint32_t)((kk*16 + krB)*128 + (np*16 + ncB8)*2));
            uint32_t bh0, bh1, bh2, bh3, bl0, bl1, bl2, bl3;
            ldsm4t(bh0, bh1, bh2, bh3, Wh + boff);
            ldsm4t(bl0, bl1, bl2, bl3, Wl + boff);
            mma16816(acc[np*2],   ah0, ah1, ah2, ah3, bh0, bh1);
            mma16816(acc[np*2+1], ah0, ah1, ah2, ah3, bh2, bh3);
            mma16816(acc[np*2],   ah0, ah1, ah2, ah3, bl0, bl1);
            mma16816(acc[np*2+1], ah0, ah1, ah2, ah3, bl2, bl3);
            mma16816(acc[np*2],   al0, al1, al2, al3, bh0, bh1);
            mma16816(acc[np*2+1], al0, al1, al2, al3, bh2, bh3);
        }
    }
}

// ---------------- weight prep: fp16 hi/lo split + SW128 swizzle -------------------
__global__ void k_wprep(const float* __restrict__ ew2, const float* __restrict__ fw1){
    int l = blockIdx.x >> 1, mat = blockIdx.x & 1;
    const float* src = (mat == 0) ? (ew2 + l*HH*HH) : (fw1 + l*HH*HH);
    __half* dh = g_wh[l][mat*2];
    __half* dl = g_wh[l][mat*2 + 1];
    for (int e = threadIdx.x; e < HH*HH; e += blockDim.x){
        float v = src[e];                      // [k][n], n fast
        __half hh = __float2half_rn(v);
        __half hl = __float2half_rn(v - __half2float(hh));
        uint32_t byte = (uint32_t)((e >> 6)*128 + (e & 63)*2);
        uint32_t sw = sw128(byte);
        dh[sw >> 1] = hh;
        dl[sw >> 1] = hl;
    }
}

// ---------------- fused: h init + layer-0 prep -----------------------------------
__global__ void k_pre(const float* __restrict__ state,
                      const float* __restrict__ hw, const float* __restrict__ hb,
                      const float* __restrict__ ew1l, const float* __restrict__ eb1l){
    __shared__ float hs[HH];
    int node = blockIdx.x; int t = threadIdx.x;
    float4 st = ((const float4*)state)[node];
    float spd = sqrtf(st.z*st.z + st.w*st.w);
    float h = silu_f(spd * hw[t] + hb[t]);
    g_h[node*HH + t] = h;
    hs[t] = h;
    __syncthreads();
    float a = eb1l[t], c = 0.f;
    #pragma unroll 8
    for (int k = 0; k < HH; ++k){
        float hv = hs[k];
        a = fmaf(hv, ew1l[k*HH + t],        a);
        c = fmaf(hv, ew1l[(HH + k)*HH + t], c);
    }
    g_a[node*HH + t] = a;
    int b = node >> 9, j = node & (NN - 1);
    g_ct[(b*HH + t)*NN + j] = c;
}

// ---------------- edge smem -------------------------------------------------------
struct EdgeSmem {
    __half T1h[JT*HH], T1l[JT*HH];   // 16KB each
    __half T2h[JT*HH], T2l[JT*HH];
    __half WB[4][HH*HH];             // W2h, W2l, F1h, F1l : 8KB each
    float  A[HH];
    float4 WS[HH];
    float  B2[HH], FB1[HH], FW2[HH];
    float  Nx[JT], Ny[JT];
    float  Magg[HH], T2i[HH], Fxy[2];
};

// ---------------- edge kernel: CTA=(b,i), 256 thr, mma.sync fp16 ------------------
__global__ void __launch_bounds__(256, 2) k_edge(
    const float* __restrict__ state,
    const float* __restrict__ ew1l,
    const float* __restrict__ eb2l,
    const float* __restrict__ fb1l,
    const float* __restrict__ fw2l,
    const float* __restrict__ fb2l,
    int layer, int accumulate)
{
    extern __shared__ __align__(16) char smem_raw[];
    EdgeSmem& s = *reinterpret_cast<EdgeSmem*>(smem_raw);

    int tid  = threadIdx.x;
    int wid  = tid >> 5;
    int lane = tid & 31;
    int bi   = blockIdx.x;
    int b    = bi >> 9;
    int i    = bi & (NN - 1);
    int m0   = wid * 16;             // warp's m-tile (j rows)

    {   // stage weights (32KB flat, coalesced)
        const float4* src = (const float4*)g_wh[layer][0];
        float4* dst = (float4*)s.WB[0];
        #pragma unroll
        for (int q = 0; q < 8; ++q) dst[tid + 256*q] = src[tid + 256*q];
    }
    if (tid < HH){
        s.A[tid]   = g_a[bi*HH + tid];
        s.WS[tid]  = make_float4(ew1l[128*HH + tid], ew1l[129*HH + tid],
                                 ew1l[130*HH + tid], ew1l[131*HH + tid]);
        s.B2[tid]  = eb2l[tid];
        s.FB1[tid] = fb1l[tid];
        s.FW2[tid] = fw2l[tid];
        s.Magg[tid] = 0.0f;
        s.T2i[tid]  = 0.0f;
    }
    if (tid < 2) s.Fxy[tid] = 0.0f;

    uint32_t aT1h = smem_u32(s.T1h), aT1l = smem_u32(s.T1l);
    uint32_t aT2h = smem_u32(s.T2h), aT2l = smem_u32(s.T2l);
    uint32_t aW2h = smem_u32(s.WB[0]), aW2l = smem_u32(s.WB[1]);
    uint32_t aF1h = smem_u32(s.WB[2]), aF1l = smem_u32(s.WB[3]);

    float4 sti = ((const float4*)state)[b*NN + i];
    float spi  = sti.z*sti.z + sti.w*sti.w;
    float fb2v = fb2l[0];
    int jt_i = i >> 7, r_i = i & (JT - 1);

    float fx = 0.f, fy = 0.f;

    __syncthreads();   // (INIT) s.A / s.WS / biases / Magg visible to all warps

    #pragma unroll 1
    for (int jt = 0; jt < NTILES; ++jt){
        // ================= stage 0: T1 row j -> fp16 hi/lo smem ==================
        {
            int jr = tid & (JT - 1);
            int half = tid >> 7;     // which 32 k's of the row
            int j = jt*JT + jr;
            float4 stj = ((const float4*)state)[b*NN + j];
            float dxp = stj.x - sti.x;
            float dyp = stj.y - sti.y;
            float dsq = dxp*dxp + dyp*dyp;
            float invd = rsqrtf(dsq + 1e-8f);
            float nx = dxp * invd;
            float ny = dyp * invd;
            float dvx = stj.z - sti.z;
            float dvy = stj.w - sti.w;
            float spj = stj.z*stj.z + stj.w*stj.w;
            float appr = dvx*nx + dvy*ny;
            if (half == 0){ s.Nx[jr] = nx; s.Ny[jr] = ny; }

            uint32_t hibuf[16], lobuf[16];
            #pragma unroll
            for (int q = 0; q < 16; ++q){
                float tv[2];
                #pragma unroll
                for (int e = 0; e < 2; ++e){
                    int n = half*32 + q*2 + e;
                    float c = g_ct[(b*HH + n)*NN + j];
                    float4 w = s.WS[n];
                    float p = s.A[n] + c;
                    p = fmaf(dsq,  w.x, p);
                    p = fmaf(spi,  w.y, p);
                    p = fmaf(spj,  w.z, p);
                    p = fmaf(appr, w.w, p);
                    tv[e] = silu_f(p);
                }
                __half h0 = __float2half_rn(tv[0]);
                __half h1 = __float2half_rn(tv[1]);
                hibuf[q] = pack_h2(h0, h1);
                lobuf[q] = pack_h2(__float2half_rn(tv[0] - __half2float(h0)),
                                   __float2half_rn(tv[1] - __half2float(h1)));
            }
            #pragma unroll
            for (int c = 0; c < 4; ++c){
                uint32_t cc = (uint32_t)(half*4 + c);
                uint32_t off = (uint32_t)(jr*128) + ((cc ^ (uint32_t)(jr & 7)) << 4);
                *(uint4*)((char*)s.T1h + off) =
                    make_uint4(hibuf[c*4], hibuf[c*4+1], hibuf[c*4+2], hibuf[c*4+3]);
                *(uint4*)((char*)s.T1l + off) =
                    make_uint4(lobuf[c*4], lobuf[c*4+1], lobuf[c*4+2], lobuf[c*4+3]);
            }
        }
        __syncthreads();   // (A) T1 / Nx / Ny ready

        // ================= GEMM1: D1 = T1 @ W2 (3-product fp16) ==================
        float acc[8][4];
        #pragma unroll
        for (int nt = 0; nt < 8; ++nt)
            #pragma unroll
            for (int p = 0; p < 4; ++p) acc[nt][p] = 0.f;
        gemm_mma(aT1h, aT1l, aW2h, aW2l, m0, lane, acc);

        // ---- epilogue1: silu(+b2), magg colsums, split->T2 smem ----
        #pragma unroll
        for (int nt = 0; nt < 8; ++nt){
            int c0 = nt*8 + (lane & 3)*2;
            float b2a = s.B2[c0], b2b = s.B2[c0+1];
            float v00 = silu_f(acc[nt][0] + b2a);
            float v01 = silu_f(acc[nt][1] + b2b);
            float v10 = silu_f(acc[nt][2] + b2a);
            float v11 = silu_f(acc[nt][3] + b2b);

            float s0 = v00 + v10, s1 = v01 + v11;
            s0 += __shfl_xor_sync(0xffffffffu, s0, 4);
            s0 += __shfl_xor_sync(0xffffffffu, s0, 8);
            s0 += __shfl_xor_sync(0xffffffffu, s0, 16);
            s1 += __shfl_xor_sync(0xffffffffu, s1, 4);
            s1 += __shfl_xor_sync(0xffffffffu, s1, 8);
            s1 += __shfl_xor_sync(0xffffffffu, s1, 16);
            if (lane < 4){
                atomicAdd(&s.Magg[c0],     s0);
                atomicAdd(&s.Magg[c0 + 1], s1);
            }

            int mg0 = m0 + (lane >> 2);
            int mg1 = mg0 + 8;
            uint32_t o0 = sw128((uint32_t)(mg0*128 + c0*2));
            uint32_t o1 = sw128((uint32_t)(mg1*128 + c0*2));
            __half h00 = __float2half_rn(v00), h01 = __float2half_rn(v01);
            __half h10 = __float2half_rn(v10), h11 = __float2half_rn(v11);
            *(uint32_t*)((char*)s.T2h + o0) = pack_h2(h00, h01);
            *(uint32_t*)((char*)s.T2h + o1) = pack_h2(h10, h11);
            *(uint32_t*)((char*)s.T2l + o0) =
                pack_h2(__float2half_rn(v00 - __half2float(h00)),
                        __float2half_rn(v01 - __half2float(h01)));
            *(uint32_t*)((char*)s.T2l + o1) =
                pack_h2(__float2half_rn(v10 - __half2float(h10)),
                        __float2half_rn(v11 - __half2float(h11)));
        }
        __syncthreads();   // (B) T2 ready

        // ---- capture T2 row i (for magg self-term subtraction) ----
        if (jt == jt_i && tid < 32){
            uint32_t o = sw128((uint32_t)(r_i*128 + tid*4));
            uint32_t hv = *(const uint32_t*)((const char*)s.T2h + o);
            uint32_t lv = *(const uint32_t*)((const char*)s.T2l + o);
            float v0 = __half2float(__ushort_as_half((unsigned short)(hv & 0xffff)))
                     + __half2float(__ushort_as_half((unsigned short)(lv & 0xffff)));
            float v1 = __half2float(__ushort_as_half((unsigned short)(hv >> 16)))
                     + __half2float(__ushort_as_half((unsigned short)(lv >> 16)));
            s.T2i[tid*2]     = v0;
            s.T2i[tid*2 + 1] = v1;
        }

        // ================= GEMM2: D2 = T2 @ F1 (3-product fp16) ==================
        #pragma unroll
        for (int nt = 0; nt < 8; ++nt)
            #pragma unroll
            for (int p = 0; p < 4; ++p) acc[nt][p] = 0.f;
        gemm_mma(aT2h, aT2l, aF1h, aF1l, m0, lane, acc);

        // ---- epilogue2: fw = silu(D2 + fb1) . fw2 + fb2; force ----
        float pm = 0.f, pm8 = 0.f;
        #pragma unroll
        for (int nt = 0; nt < 8; ++nt){
            int c0 = nt*8 + (lane & 3)*2;
            float fa = s.FB1[c0], fb = s.FB1[c0+1];
            float wa = s.FW2[c0], wb = s.FW2[c0+1];
            pm  = fmaf(silu_f(acc[nt][0] + fa), wa, pm);
            pm  = fmaf(silu_f(acc[nt][1] + fb), wb, pm);
            pm8 = fmaf(silu_f(acc[nt][2] + fa), wa, pm8);
            pm8 = fmaf(silu_f(acc[nt][3] + fb), wb, pm8);
        }
        pm  += __shfl_xor_sync(0xffffffffu, pm, 1);
        pm  += __shfl_xor_sync(0xffffffffu, pm, 2);
        pm8 += __shfl_xor_sync(0xffffffffu, pm8, 1);
        pm8 += __shfl_xor_sync(0xffffffffu, pm8, 2);
        if ((lane & 3) == 0){
            int r0_ = m0 + (lane >> 2);
            int r1_ = r0_ + 8;
            float f0 = pm + fb2v, f1 = pm8 + fb2v;
            // normal is exactly 0 at j==i -> self-term auto-masked
            fx = fmaf(f0, s.Nx[r0_], fx); fx = fmaf(f1, s.Nx[r1_], fx);
            fy = fmaf(f0, s.Ny[r0_], fy); fy = fmaf(f1, s.Ny[r1_], fy);
        }
        __syncthreads();   // (C) epilogue2's Nx/Ny reads done before next stage0
    }

    // ---- reduce forces ----
    fx += __shfl_xor_sync(0xffffffffu, fx, 16);
    fx += __shfl_xor_sync(0xffffffffu, fx, 8);
    fx += __shfl_xor_sync(0xffffffffu, fx, 4);
    fy += __shfl_xor_sync(0xffffffffu, fy, 16);
    fy += __shfl_xor_sync(0xffffffffu, fy, 8);
    fy += __shfl_xor_sync(0xffffffffu, fy, 4);
    if (lane == 0){
        atomicAdd(&s.Fxy[0], fx);
        atomicAdd(&s.Fxy[1], fy);
    }
    __syncthreads();

    if (tid < HH) g_magg[bi*HH + tid] = s.Magg[tid] - s.T2i[tid];
    if (tid < 2){
        float v = s.Fxy[tid];
        if (accumulate) g_fsum[bi*2 + tid] += v;
        else            g_fsum[bi*2 + tid] = v;
    }
}

// ---------------- fused: node update + next-layer prep ---------------------------
__global__ void k_nodeprep(const float* __restrict__ nw1l, const float* __restrict__ nb1l,
                           const float* __restrict__ nw2l, const float* __restrict__ nb2l,
                           const float* __restrict__ ew1n, const float* __restrict__ eb1n){
    __shared__ float sIn[2*HH];
    __shared__ float sY[HH];
    __shared__ float hs[HH];
    int node = blockIdx.x; int t = threadIdx.x;
    sIn[t]      = g_h[node*HH + t];
    sIn[HH + t] = g_magg[node*HH + t];
    __syncthreads();
    float a = nb1l[t];
    #pragma unroll 8
    for (int k = 0; k < 2*HH; ++k) a = fmaf(sIn[k], nw1l[k*HH + t], a);
    sY[t] = silu_f(a);
    __syncthreads();
    float o = nb2l[t];
    #pragma unroll 8
    for (int k = 0; k < HH; ++k) o = fmaf(sY[k], nw2l[k*HH + t], o);
    g_h[node*HH + t] = o;
    hs[t] = o;
    __syncthreads();
    float av = eb1n[t], c = 0.f;
    #pragma unroll 8
    for (int k = 0; k < HH; ++k){
        float hv = hs[k];
        av = fmaf(hv, ew1n[k*HH + t],        av);
        c  = fmaf(hv, ew1n[(HH + k)*HH + t], c);
    }
    g_a[node*HH + t] = av;
    int b = node >> 9, j = node & (NN - 1);
    g_ct[(b*HH + t)*NN + j] = c;
}

// ---------------- fused: last node update + wall MLP + output --------------------
__global__ void k_final(const float* __restrict__ state,
                        const float* __restrict__ nw1l, const float* __restrict__ nb1l,
                        const float* __restrict__ nw2l, const float* __restrict__ nb2l,
                        const float* __restrict__ w1, const float* __restrict__ b1,
                        const float* __restrict__ w2, const float* __restrict__ b2,
                        const float* __restrict__ w3, const float* __restrict__ b3,
                        float* __restrict__ out){
    __shared__ float sIn[2*HH];
    __shared__ float sY[HH];
    __shared__ float sH[HH + 4];
    __shared__ float sM[4];
    int node = blockIdx.x; int t = threadIdx.x;
    sIn[t]      = g_h[node*HH + t];
    sIn[HH + t] = g_magg[node*HH + t];
    __syncthreads();
    float a = nb1l[t];
    #pragma unroll 8
    for (int k = 0; k < 2*HH; ++k) a = fmaf(sIn[k], nw1l[k*HH + t], a);
    sY[t] = silu_f(a);
    __syncthreads();
    float o = nb2l[t];
    #pragma unroll 8
    for (int k = 0; k < HH; ++k) o = fmaf(sY[k], nw2l[k*HH + t], o);
    sH[t] = o;
    if (t < 4){
        float4 st = ((const float4*)state)[node];
        float d = (t == 0) ? st.x : (t == 1) ? 1.0f - st.x
                : (t == 2) ? st.y : 1.0f - st.y;
        sH[HH + t] = d;
    }
    __syncthreads();
    float a1 = b1[t];
    #pragma unroll 4
    for (int k = 0; k < HH + 4; ++k) a1 = fmaf(sH[k], w1[k*HH + t], a1);
    sY[t] = silu_f(a1);
    __syncthreads();
    float a2 = b2[t];
    #pragma unroll 8
    for (int k = 0; k < HH; ++k) a2 = fmaf(sY[k], w2[k*HH + t], a2);
    __syncthreads();
    sY[t] = silu_f(a2);
    __syncthreads();
    if (t < 4){
        float m = b3[t];
        #pragma unroll 8
        for (int k = 0; k < HH; ++k) m = fmaf(sY[k], w3[k*4 + t], m);
        sM[t] = m;
    }
    __syncthreads();
    if (t < 2){
        float wf = (t == 0) ? (sM[0] - sM[1]) : (sM[2] - sM[3]);
        out[node*2 + t] = g_fsum[node*2 + t] + wf;
    }
}

// ---------------- launch ----------------------------------------------------------
extern "C" void kernel_launch(void* const* d_in, const int* in_sizes, int n_in,
                              void* d_out, int out_size){
    const float* state = (const float*)d_in[0];
    const float* hiw  = (const float*)d_in[1];
    const float* hib  = (const float*)d_in[2];
    const float* ew1  = (const float*)d_in[3];
    const float* eb1  = (const float*)d_in[4];
    const float* ew2  = (const float*)d_in[5];
    const float* eb2  = (const float*)d_in[6];
    const float* fw1  = (const float*)d_in[7];
    const float* fb1  = (const float*)d_in[8];
    const float* fw2  = (const float*)d_in[9];
    const float* fb2  = (const float*)d_in[10];
    const float* nw1  = (const float*)d_in[11];
    const float* nb1  = (const float*)d_in[12];
    const float* nw2  = (const float*)d_in[13];
    const float* nb2  = (const float*)d_in[14];
    const float* ww1  = (const float*)d_in[15];
    const float* wb1  = (const float*)d_in[16];
    const float* ww2  = (const float*)d_in[17];
    const float* wb2  = (const float*)d_in[18];
    const float* ww3  = (const float*)d_in[19];
    const float* wb3  = (const float*)d_in[20];
    float* out = (float*)d_out;

    int smem = (int)sizeof(EdgeSmem);
    cudaFuncSetAttribute(k_edge, cudaFuncAttributeMaxDynamicSharedMemorySize, smem);

    k_wprep<<<6, 256>>>(ew2, fw1);
    k_pre<<<NODES, HH>>>(state, hiw, hib, ew1, eb1);
    for (int l = 0; l < 3; ++l){
        k_edge<<<NODES, 256, smem>>>(state,
                               ew1 + l*132*HH,
                               eb2 + l*HH,
                               fb1 + l*HH,
                               fw2 + l*HH,
                               fb2 + l,
                               l, l);
        if (l < 2)
            k_nodeprep<<<NODES, HH>>>(nw1 + l*2*HH*HH, nb1 + l*HH,
                                      nw2 + l*HH*HH,   nb2 + l*HH,
                                      ew1 + (l+1)*132*HH, eb1 + (l+1)*HH);
    }
    k_final<<<NODES, HH>>>(state,
                           nw1 + 2*2*HH*HH, nb1 + 2*HH,
                           nw2 + 2*HH*HH,   nb2 + 2*HH,
                           ww1, wb1, ww2, wb2, ww3, wb3, out);
}

// round 9
// speedup vs baseline: 4.3228x; 1.2000x over previous
#include <cuda_runtime.h>
#include <cuda_fp16.h>
#include <cstdint>

#define BB 2
#define NN 512
#define HH 64
#define NODES (BB*NN)
#define JT 128
#define NTILES (NN/JT)

// ---------------- scratch (device globals) -------------------------------------
__device__ float g_h[NODES*HH];
__device__ float g_a[NODES*HH];
__device__ float g_ct[BB*HH*NN];          // c_j, n-major: [b][n][j]
__device__ float g_fsum[NODES*2];
__device__ __half g_wh[3][4][HH*HH];      // per layer: W2hi,W2lo,F1hi,F1lo (swizzled [k][n] fp16)

// ---------------- helpers -------------------------------------------------------
__device__ __forceinline__ float silu_f(float x){
    float e = __expf(-x);
    return x * __fdividef(1.0f, 1.0f + e);
}
__device__ __forceinline__ uint32_t smem_u32(const void* p){
    uint32_t a;
    asm("{ .reg .u64 t; cvta.to.shared.u64 t, %1; cvt.u32.u64 %0, t; }" : "=r"(a) : "l"(p));
    return a;
}
__device__ __forceinline__ uint32_t sw128(uint32_t b){ return b ^ ((b >> 3) & 0x70); }

__device__ __forceinline__ void ldsm4(uint32_t& r0, uint32_t& r1, uint32_t& r2, uint32_t& r3, uint32_t a){
    asm volatile("ldmatrix.sync.aligned.m8n8.x4.shared.b16 {%0,%1,%2,%3}, [%4];"
                 : "=r"(r0), "=r"(r1), "=r"(r2), "=r"(r3) : "r"(a));
}
__device__ __forceinline__ void ldsm4t(uint32_t& r0, uint32_t& r1, uint32_t& r2, uint32_t& r3, uint32_t a){
    asm volatile("ldmatrix.sync.aligned.m8n8.x4.trans.shared.b16 {%0,%1,%2,%3}, [%4];"
                 : "=r"(r0), "=r"(r1), "=r"(r2), "=r"(r3) : "r"(a));
}
__device__ __forceinline__ void mma16816(float* d, uint32_t a0, uint32_t a1, uint32_t a2, uint32_t a3,
                                         uint32_t b0, uint32_t b1){
    asm volatile("mma.sync.aligned.m16n8k16.row.col.f32.f16.f16.f32 "
                 "{%0,%1,%2,%3},{%4,%5,%6,%7},{%8,%9},{%0,%1,%2,%3};"
                 : "+f"(d[0]), "+f"(d[1]), "+f"(d[2]), "+f"(d[3])
                 : "r"(a0), "r"(a1), "r"(a2), "r"(a3), "r"(b0), "r"(b1));
}

// fp16 split-GEMM: D[128x64] += T[128x64] @ W[64x64] with 3-product compensation.
__device__ __forceinline__ void gemm_mma(uint32_t Th, uint32_t Tl, uint32_t Wh, uint32_t Wl,
                                         int m0, int lane, float acc[8][4]){
    int rA    = m0 + (lane & 7) + ((lane >> 3) & 1) * 8;
    int colA8 = ((lane >> 4) & 1) * 8;
    int krB   = (lane & 7) + ((lane >> 3) & 1) * 8;
    int ncB8  = ((lane >> 4) & 1) * 8;
    #pragma unroll
    for (int kk = 0; kk < 4; ++kk){
        uint32_t aoff = sw128((uint32_t)(rA*128 + (kk*16 + colA8)*2));
        uint32_t ah0, ah1, ah2, ah3, al0, al1, al2, al3;
        ldsm4(ah0, ah1, ah2, ah3, Th + aoff);
        ldsm4(al0, al1, al2, al3, Tl + aoff);
        #pragma unroll
        for (int np = 0; np < 4; ++np){
            uint32_t boff = sw128((uint32_t)((kk*16 + krB)*128 + (np*16 + ncB8)*2));
            uint32_t bh0, bh1, bh2, bh3, bl0, bl1, bl2, bl3;
            ldsm4t(bh0, bh1, bh2, bh3, Wh + boff);
            ldsm4t(bl0, bl1, bl2, bl3, Wl + boff);
            mma16816(acc[np*2],   ah0, ah1, ah2, ah3, bh0, bh1);
            mma16816(acc[np*2+1], ah0, ah1, ah2, ah3, bh2, bh3);
            mma16816(acc[np*2],   ah0, ah1, ah2, ah3, bl0, bl1);
            mma16816(acc[np*2+1], ah0, ah1, ah2, ah3, bl2, bl3);
            mma16816(acc[np*2],   al0, al1, al2, al3, bh0, bh1);
            mma16816(acc[np*2+1], al0, al1, al2, al3, bh2, bh3);
        }
    }
}

// ---------------- weight prep: fp16 hi/lo split + SW128 swizzle -------------------
__global__ void k_wprep(const float* __restrict__ ew2, const float* __restrict__ fw1){
    int l = blockIdx.x >> 1, mat = blockIdx.x & 1;
    const float* src = (mat == 0) ? (ew2 + l*HH*HH) : (fw1 + l*HH*HH);
    __half* dh = g_wh[l][mat*2];
    __half* dl = g_wh[l][mat*2 + 1];
    for (int e = threadIdx.x; e < HH*HH; e += blockDim.x){
        float v = src[e];                      // [k][n], n fast
        __half hh = __float2half_rn(v);
        __half hl = __float2half_rn(v - __half2float(hh));
        uint32_t byte = (uint32_t)((e >> 6)*128 + (e & 63)*2);
        uint32_t sw = sw128(byte);
        dh[sw >> 1] = hh;
        dl[sw >> 1] = hl;
    }
}

// ---------------- fused: h init + layer-0 prep -----------------------------------
__global__ void k_pre(const float* __restrict__ state,
                      const float* __restrict__ hw, const float* __restrict__ hb,
                      const float* __restrict__ ew1l, const float* __restrict__ eb1l){
    __shared__ float hs[HH];
    int node = blockIdx.x; int t = threadIdx.x;
    float4 st = ((const float4*)state)[node];
    float spd = sqrtf(st.z*st.z + st.w*st.w);
    float h = silu_f(spd * hw[t] + hb[t]);
    g_h[node*HH + t] = h;
    hs[t] = h;
    __syncthreads();
    float a = eb1l[t], c = 0.f;
    #pragma unroll 8
    for (int k = 0; k < HH; ++k){
        float hv = hs[k];
        a = fmaf(hv, ew1l[k*HH + t],        a);
        c = fmaf(hv, ew1l[(HH + k)*HH + t], c);
    }
    g_a[node*HH + t] = a;
    int b = node >> 9, j = node & (NN - 1);
    g_ct[(b*HH + t)*NN + j] = c;
}

// ---------------- next-layer prep (a_i, c_j from updated h) ----------------------
__global__ void k_prep(const float* __restrict__ ew1n, const float* __restrict__ eb1n){
    __shared__ float hs[HH];
    int node = blockIdx.x; int t = threadIdx.x;
    hs[t] = g_h[node*HH + t];
    __syncthreads();
    float a = eb1n[t], c = 0.f;
    #pragma unroll 8
    for (int k = 0; k < HH; ++k){
        float hv = hs[k];
        a = fmaf(hv, ew1n[k*HH + t],        a);
        c = fmaf(hv, ew1n[(HH + k)*HH + t], c);
    }
    g_a[node*HH + t] = a;
    int b = node >> 9, j = node & (NN - 1);
    g_ct[(b*HH + t)*NN + j] = c;
}

// ---------------- edge smem -------------------------------------------------------
struct EdgeSmem {
    __half T1h[JT*HH], T1l[JT*HH];   // 16KB each (T1h aliased as MLP scratch in tail)
    __half T2h[JT*HH], T2l[JT*HH];
    __half WB[4][HH*HH];             // W2h, W2l, F1h, F1l : 8KB each
    float  A[HH];
    float4 WS[HH];
    float  B2[HH], FB1[HH], FW2[HH];
    float  Nx[JT], Ny[JT];
    float  Magg[HH], T2i[HH], Fxy[2];
};

// ---------------- edge kernel: CTA=(b,i), 256 thr, mma.sync fp16 ------------------
__global__ void __launch_bounds__(256, 2) k_edge(
    const float* __restrict__ state,
    const float* __restrict__ ew1l,
    const float* __restrict__ eb2l,
    const float* __restrict__ fb1l,
    const float* __restrict__ fw2l,
    const float* __restrict__ fb2l,
    const float* __restrict__ nw1l,
    const float* __restrict__ nb1l,
    const float* __restrict__ nw2l,
    const float* __restrict__ nb2l,
    int layer, int accumulate)
{
    extern __shared__ __align__(16) char smem_raw[];
    EdgeSmem& s = *reinterpret_cast<EdgeSmem*>(smem_raw);

    int tid  = threadIdx.x;
    int wid  = tid >> 5;
    int lane = tid & 31;
    int bi   = blockIdx.x;
    int b    = bi >> 9;
    int i    = bi & (NN - 1);
    int m0   = wid * 16;             // warp's m-tile (j rows)

    {   // stage weights (32KB flat, coalesced)
        const float4* src = (const float4*)g_wh[layer][0];
        float4* dst = (float4*)s.WB[0];
        #pragma unroll
        for (int q = 0; q < 8; ++q) dst[tid + 256*q] = src[tid + 256*q];
    }
    if (tid < HH){
        s.A[tid]   = g_a[bi*HH + tid];
        s.WS[tid]  = make_float4(ew1l[128*HH + tid], ew1l[129*HH + tid],
                                 ew1l[130*HH + tid], ew1l[131*HH + tid]);
        s.B2[tid]  = eb2l[tid];
        s.FB1[tid] = fb1l[tid];
        s.FW2[tid] = fw2l[tid];
        s.Magg[tid] = 0.0f;
        s.T2i[tid]  = 0.0f;
    }
    if (tid < 2) s.Fxy[tid] = 0.0f;

    uint32_t aT1h = smem_u32(s.T1h), aT1l = smem_u32(s.T1l);
    uint32_t aT2h = smem_u32(s.T2h), aT2l = smem_u32(s.T2l);
    uint32_t aW2h = smem_u32(s.WB[0]), aW2l = smem_u32(s.WB[1]);
    uint32_t aF1h = smem_u32(s.WB[2]), aF1l = smem_u32(s.WB[3]);

    float4 sti = ((const float4*)state)[b*NN + i];
    float spi  = sti.z*sti.z + sti.w*sti.w;
    float fb2v = fb2l[0];
    int jt_i = i >> 7, r_i = i & (JT - 1);

    float fx = 0.f, fy = 0.f;
    float cs[16];                    // deferred m_agg column partials
    #pragma unroll
    for (int q = 0; q < 16; ++q) cs[q] = 0.f;

    __syncthreads();   // (INIT) smem staging visible to all warps

    #pragma unroll 1
    for (int jt = 0; jt < NTILES; ++jt){
        // ================= stage 0: T1 row j -> fp16 hi/lo smem ==================
        {
            int jr = tid & (JT - 1);
            int half = tid >> 7;     // which 32 k's of the row
            int j = jt*JT + jr;
            float4 stj = ((const float4*)state)[b*NN + j];
            float dxp = stj.x - sti.x;
            float dyp = stj.y - sti.y;
            float dsq = dxp*dxp + dyp*dyp;
            float invd = rsqrtf(dsq + 1e-8f);
            float nx = dxp * invd;
            float ny = dyp * invd;
            float dvx = stj.z - sti.z;
            float dvy = stj.w - sti.w;
            float spj = stj.z*stj.z + stj.w*stj.w;
            float appr = dvx*nx + dvy*ny;
            if (half == 0){ s.Nx[jr] = nx; s.Ny[jr] = ny; }

            uint32_t hibuf[16], lobuf[16];
            #pragma unroll
            for (int q = 0; q < 16; ++q){
                float tv[2];
                #pragma unroll
                for (int e = 0; e < 2; ++e){
                    int n = half*32 + q*2 + e;
                    float c = g_ct[(b*HH + n)*NN + j];
                    float4 w = s.WS[n];
                    float p = s.A[n] + c;
                    p = fmaf(dsq,  w.x, p);
                    p = fmaf(spi,  w.y, p);
                    p = fmaf(spj,  w.z, p);
                    p = fmaf(appr, w.w, p);
                    tv[e] = silu_f(p);
                }
                __half2 hp = __floats2half2_rn(tv[0], tv[1]);
                float2 hf = __half22float2(hp);
                __half2 lp = __floats2half2_rn(tv[0] - hf.x, tv[1] - hf.y);
                hibuf[q] = *(uint32_t*)&hp;
                lobuf[q] = *(uint32_t*)&lp;
            }
            #pragma unroll
            for (int c = 0; c < 4; ++c){
                uint32_t cc = (uint32_t)(half*4 + c);
                uint32_t off = (uint32_t)(jr*128) + ((cc ^ (uint32_t)(jr & 7)) << 4);
                *(uint4*)((char*)s.T1h + off) =
                    make_uint4(hibuf[c*4], hibuf[c*4+1], hibuf[c*4+2], hibuf[c*4+3]);
                *(uint4*)((char*)s.T1l + off) =
                    make_uint4(lobuf[c*4], lobuf[c*4+1], lobuf[c*4+2], lobuf[c*4+3]);
            }
        }
        __syncthreads();   // (A) T1 / Nx / Ny ready

        // ================= GEMM1: D1 = T1 @ W2 (3-product fp16) ==================
        float acc[8][4];
        #pragma unroll
        for (int nt = 0; nt < 8; ++nt)
            #pragma unroll
            for (int p = 0; p < 4; ++p) acc[nt][p] = 0.f;
        gemm_mma(aT1h, aT1l, aW2h, aW2l, m0, lane, acc);

        // ---- epilogue1: silu(+b2), deferred magg partials, split->T2 smem ----
        #pragma unroll
        for (int nt = 0; nt < 8; ++nt){
            int c0 = nt*8 + (lane & 3)*2;
            float b2a = s.B2[c0], b2b = s.B2[c0+1];
            float v00 = silu_f(acc[nt][0] + b2a);
            float v01 = silu_f(acc[nt][1] + b2b);
            float v10 = silu_f(acc[nt][2] + b2a);
            float v11 = silu_f(acc[nt][3] + b2b);

            cs[nt*2]   += v00 + v10;
            cs[nt*2+1] += v01 + v11;

            int mg0 = m0 + (lane >> 2);
            int mg1 = mg0 + 8;
            uint32_t o0 = sw128((uint32_t)(mg0*128 + c0*2));
            uint32_t o1 = sw128((uint32_t)(mg1*128 + c0*2));
            __half2 h0p = __floats2half2_rn(v00, v01);
            float2  h0f = __half22float2(h0p);
            __half2 l0p = __floats2half2_rn(v00 - h0f.x, v01 - h0f.y);
            __half2 h1p = __floats2half2_rn(v10, v11);
            float2  h1f = __half22float2(h1p);
            __half2 l1p = __floats2half2_rn(v10 - h1f.x, v11 - h1f.y);
            *(__half2*)((char*)s.T2h + o0) = h0p;
            *(__half2*)((char*)s.T2l + o0) = l0p;
            *(__half2*)((char*)s.T2h + o1) = h1p;
            *(__half2*)((char*)s.T2l + o1) = l1p;
        }
        __syncthreads();   // (B) T2 ready

        // ---- capture T2 row i (for magg self-term subtraction) ----
        if (jt == jt_i && tid < 32){
            uint32_t o = sw128((uint32_t)(r_i*128 + tid*4));
            uint32_t hv = *(const uint32_t*)((const char*)s.T2h + o);
            uint32_t lv = *(const uint32_t*)((const char*)s.T2l + o);
            float v0 = __half2float(__ushort_as_half((unsigned short)(hv & 0xffff)))
                     + __half2float(__ushort_as_half((unsigned short)(lv & 0xffff)));
            float v1 = __half2float(__ushort_as_half((unsigned short)(hv >> 16)))
                     + __half2float(__ushort_as_half((unsigned short)(lv >> 16)));
            s.T2i[tid*2]     = v0;
            s.T2i[tid*2 + 1] = v1;
        }

        // ================= GEMM2: D2 = T2 @ F1 (3-product fp16) ==================
        #pragma unroll
        for (int nt = 0; nt < 8; ++nt)
            #pragma unroll
            for (int p = 0; p < 4; ++p) acc[nt][p] = 0.f;
        gemm_mma(aT2h, aT2l, aF1h, aF1l, m0, lane, acc);

        // ---- epilogue2: fw = silu(D2 + fb1) . fw2 + fb2; force ----
        float pm = 0.f, pm8 = 0.f;
        #pragma unroll
        for (int nt = 0; nt < 8; ++nt){
            int c0 = nt*8 + (lane & 3)*2;
            float fa = s.FB1[c0], fb = s.FB1[c0+1];
            float wa = s.FW2[c0], wb = s.FW2[c0+1];
            pm  = fmaf(silu_f(acc[nt][0] + fa), wa, pm);
            pm  = fmaf(silu_f(acc[nt][1] + fb), wb, pm);
            pm8 = fmaf(silu_f(acc[nt][2] + fa), wa, pm8);
            pm8 = fmaf(silu_f(acc[nt][3] + fb), wb, pm8);
        }
        pm  += __shfl_xor_sync(0xffffffffu, pm, 1);
        pm  += __shfl_xor_sync(0xffffffffu, pm, 2);
        pm8 += __shfl_xor_sync(0xffffffffu, pm8, 1);
        pm8 += __shfl_xor_sync(0xffffffffu, pm8, 2);
        if ((lane & 3) == 0){
            int r0_ = m0 + (lane >> 2);
            int r1_ = r0_ + 8;
            float f0 = pm + fb2v, f1 = pm8 + fb2v;
            // normal is exactly 0 at j==i -> self-term auto-masked
            fx = fmaf(f0, s.Nx[r0_], fx); fx = fmaf(f1, s.Nx[r1_], fx);
            fy = fmaf(f0, s.Ny[r0_], fy); fy = fmaf(f1, s.Ny[r1_], fy);
        }
        __syncthreads();   // (C) epilogue2's Nx/Ny reads done before next stage0
    }

    // ---- final m_agg reduction (once) ----
    #pragma unroll
    for (int nt = 0; nt < 8; ++nt){
        float s0 = cs[nt*2], s1 = cs[nt*2+1];
        s0 += __shfl_xor_sync(0xffffffffu, s0, 4);
        s0 += __shfl_xor_sync(0xffffffffu, s0, 8);
        s0 += __shfl_xor_sync(0xffffffffu, s0, 16);
        s1 += __shfl_xor_sync(0xffffffffu, s1, 4);
        s1 += __shfl_xor_sync(0xffffffffu, s1, 8);
        s1 += __shfl_xor_sync(0xffffffffu, s1, 16);
        if (lane < 4){
            int c0 = nt*8 + lane*2;
            atomicAdd(&s.Magg[c0],     s0);
            atomicAdd(&s.Magg[c0 + 1], s1);
        }
    }
    // ---- reduce forces ----
    fx += __shfl_xor_sync(0xffffffffu, fx, 16);
    fx += __shfl_xor_sync(0xffffffffu, fx, 8);
    fx += __shfl_xor_sync(0xffffffffu, fx, 4);
    fy += __shfl_xor_sync(0xffffffffu, fy, 16);
    fy += __shfl_xor_sync(0xffffffffu, fy, 8);
    fy += __shfl_xor_sync(0xffffffffu, fy, 4);
    if (lane == 0){
        atomicAdd(&s.Fxy[0], fx);
        atomicAdd(&s.Fxy[1], fy);
    }
    __syncthreads();   // Magg / Fxy final

    if (tid < 2){
        float v = s.Fxy[tid];
        if (accumulate) g_fsum[bi*2 + tid] += v;
        else            g_fsum[bi*2 + tid] = v;
    }

    // ================= fused node-update MLP (h_new for node bi) =================
    float* sIn = (float*)s.T1h;      // 128 floats (T1 region is dead now)
    float* sP  = sIn + 128;          // 256 partials
    float* sY  = sP + 256;           // 64
    if (tid < 64)       sIn[tid] = g_h[bi*HH + tid];
    else if (tid < 128) sIn[tid] = s.Magg[tid - 64] - s.T2i[tid - 64];
    __syncthreads();
    {
        int out = tid & 63, chk = tid >> 6;
        float p = 0.f;
        #pragma unroll 8
        for (int k = 0; k < 32; ++k)
            p = fmaf(sIn[chk*32 + k], nw1l[(chk*32 + k)*HH + out], p);
        sP[tid] = p;
    }
    __syncthreads();
    if (tid < 64)
        sY[tid] = silu_f(sP[tid] + sP[tid+64] + sP[tid+128] + sP[tid+192] + nb1l[tid]);
    __syncthreads();
    {
        int out = tid & 63, chk = tid >> 6;
        float p = 0.f;
        #pragma unroll 8
        for (int k = 0; k < 16; ++k)
            p = fmaf(sY[chk*16 + k], nw2l[(chk*16 + k)*HH + out], p);
        sP[tid] = p;
    }
    __syncthreads();
    if (tid < 64)
        g_h[bi*HH + tid] = sP[tid] + sP[tid+64] + sP[tid+128] + sP[tid+192] + nb2l[tid];
}

// ---------------- wall MLP + output (node update already fused) -------------------
__global__ void k_final(const float* __restrict__ state,
                        const float* __restrict__ w1, const float* __restrict__ b1,
                        const float* __restrict__ w2, const float* __restrict__ b2,
                        const float* __restrict__ w3, const float* __restrict__ b3,
                        float* __restrict__ out){
    __shared__ float sH[HH + 4];
    __shared__ float sY[HH];
    __shared__ float sM[4];
    int node = blockIdx.x; int t = threadIdx.x;
    sH[t] = g_h[node*HH + t];
    if (t < 4){
        float4 st = ((const float4*)state)[node];
        float d = (t == 0) ? st.x : (t == 1) ? 1.0f - st.x
                : (t == 2) ? st.y : 1.0f - st.y;
        sH[HH + t] = d;
    }
    __syncthreads();
    float a1 = b1[t];
    #pragma unroll 4
    for (int k = 0; k < HH + 4; ++k) a1 = fmaf(sH[k], w1[k*HH + t], a1);
    sY[t] = silu_f(a1);
    __syncthreads();
    float a2 = b2[t];
    #pragma unroll 8
    for (int k = 0; k < HH; ++k) a2 = fmaf(sY[k], w2[k*HH + t], a2);
    __syncthreads();
    sY[t] = silu_f(a2);
    __syncthreads();
    if (t < 4){
        float m = b3[t];
        #pragma unroll 8
        for (int k = 0; k < HH; ++k) m = fmaf(sY[k], w3[k*4 + t], m);
        sM[t] = m;
    }
    __syncthreads();
    if (t < 2){
        float wf = (t == 0) ? (sM[0] - sM[1]) : (sM[2] - sM[3]);
        out[node*2 + t] = g_fsum[node*2 + t] + wf;
    }
}

// ---------------- launch ----------------------------------------------------------
extern "C" void kernel_launch(void* const* d_in, const int* in_sizes, int n_in,
                              void* d_out, int out_size){
    const float* state = (const float*)d_in[0];
    const float* hiw  = (const float*)d_in[1];
    const float* hib  = (const float*)d_in[2];
    const float* ew1  = (const float*)d_in[3];
    const float* eb1  = (const float*)d_in[4];
    const float* ew2  = (const float*)d_in[5];
    const float* eb2  = (const float*)d_in[6];
    const float* fw1  = (const float*)d_in[7];
    const float* fb1  = (const float*)d_in[8];
    const float* fw2  = (const float*)d_in[9];
    const float* fb2  = (const float*)d_in[10];
    const float* nw1  = (const float*)d_in[11];
    const float* nb1  = (const float*)d_in[12];
    const float* nw2  = (const float*)d_in[13];
    const float* nb2  = (const float*)d_in[14];
    const float* ww1  = (const float*)d_in[15];
    const float* wb1  = (const float*)d_in[16];
    const float* ww2  = (const float*)d_in[17];
    const float* wb2  = (const float*)d_in[18];
    const float* ww3  = (const float*)d_in[19];
    const float* wb3  = (const float*)d_in[20];
    float* out = (float*)d_out;

    int smem = (int)sizeof(EdgeSmem);
    cudaFuncSetAttribute(k_edge, cudaFuncAttributeMaxDynamicSharedMemorySize, smem);

    k_wprep<<<6, 256>>>(ew2, fw1);
    k_pre<<<NODES, HH>>>(state, hiw, hib, ew1, eb1);
    for (int l = 0; l < 3; ++l){
        k_edge<<<NODES, 256, smem>>>(state,
                               ew1 + l*132*HH,
                               eb2 + l*HH,
                               fb1 + l*HH,
                               fw2 + l*HH,
                               fb2 + l,
                               nw1 + l*2*HH*HH, nb1 + l*HH,
                               nw2 + l*HH*HH,   nb2 + l*HH,
                               l, l);
        if (l < 2)
            k_prep<<<NODES, HH>>>(ew1 + (l+1)*132*HH, eb1 + (l+1)*HH);
    }
    k_final<<<NODES, HH>>>(state, ww1, wb1, ww2, wb2, ww3, wb3, out);
}

// round 11
// speedup vs baseline: 4.8130x; 1.1134x over previous
#include <cuda_runtime.h>
#include <cuda_fp16.h>
#include <cstdint>

#define BB 2
#define NN 512
#define HH 64
#define NODES (BB*NN)
#define JT 128
#define NTILES (NN/JT)

// ---------------- scratch (device globals) -------------------------------------
__device__ float g_h[NODES*HH];
__device__ float g_a[2][NODES*HH];        // ping-pong by layer parity (race-free fused prep)
__device__ float g_ct[2][BB*HH*NN];       // c_j, n-major: [b][n][j]
__device__ float g_fsum[NODES*2];
__device__ __half g_wh[3][4][HH*HH];      // per layer: W2hi,W2lo,F1hi,F1lo (swizzled [k][n] fp16)

// ---------------- helpers -------------------------------------------------------
// silu(x) = x * sigmoid(x) = 0.5*x*(1 + tanh(x/2)) ; tanh.approx = 1 MUFU op
__device__ __forceinline__ float silu_f(float x){
    float t;
    asm("tanh.approx.f32 %0, %1;" : "=f"(t) : "f"(x * 0.5f));
    return 0.5f * x * (1.0f + t);
}
// exact silu for the scalar pre/final paths (negligible cost there)
__device__ __forceinline__ float silu_x(float x){
    float e = __expf(-x);
    return x * __fdividef(1.0f, 1.0f + e);
}
__device__ __forceinline__ uint32_t smem_u32(const void* p){
    uint32_t a;
    asm("{ .reg .u64 t; cvta.to.shared.u64 t, %1; cvt.u32.u64 %0, t; }" : "=r"(a) : "l"(p));
    return a;
}
__device__ __forceinline__ uint32_t sw128(uint32_t b){ return b ^ ((b >> 3) & 0x70); }

__device__ __forceinline__ void ldsm4(uint32_t& r0, uint32_t& r1, uint32_t& r2, uint32_t& r3, uint32_t a){
    asm volatile("ldmatrix.sync.aligned.m8n8.x4.shared.b16 {%0,%1,%2,%3}, [%4];"
                 : "=r"(r0), "=r"(r1), "=r"(r2), "=r"(r3) : "r"(a));
}
__device__ __forceinline__ void ldsm4t(uint32_t& r0, uint32_t& r1, uint32_t& r2, uint32_t& r3, uint32_t a){
    asm volatile("ldmatrix.sync.aligned.m8n8.x4.trans.shared.b16 {%0,%1,%2,%3}, [%4];"
                 : "=r"(r0), "=r"(r1), "=r"(r2), "=r"(r3) : "r"(a));
}
__device__ __forceinline__ void mma16816(float* d, uint32_t a0, uint32_t a1, uint32_t a2, uint32_t a3,
                                         uint32_t b0, uint32_t b1){
    asm volatile("mma.sync.aligned.m16n8k16.row.col.f32.f16.f16.f32 "
                 "{%0,%1,%2,%3},{%4,%5,%6,%7},{%8,%9},{%0,%1,%2,%3};"
                 : "+f"(d[0]), "+f"(d[1]), "+f"(d[2]), "+f"(d[3])
                 : "r"(a0), "r"(a1), "r"(a2), "r"(a3), "r"(b0), "r"(b1));
}

// fp16 split-GEMM: D[128x64] += T[128x64] @ W[64x64] with 3-product compensation.
__device__ __forceinline__ void gemm_mma(uint32_t Th, uint32_t Tl, uint32_t Wh, uint32_t Wl,
                                         int m0, int lane, float acc[8][4]){
    int rA    = m0 + (lane & 7) + ((lane >> 3) & 1) * 8;
    int colA8 = ((lane >> 4) & 1) * 8;
    int krB   = (lane & 7) + ((lane >> 3) & 1) * 8;
    int ncB8  = ((lane >> 4) & 1) * 8;
    #pragma unroll
    for (int kk = 0; kk < 4; ++kk){
        uint32_t aoff = sw128((uint32_t)(rA*128 + (kk*16 + colA8)*2));
        uint32_t ah0, ah1, ah2, ah3, al0, al1, al2, al3;
        ldsm4(ah0, ah1, ah2, ah3, Th + aoff);
        ldsm4(al0, al1, al2, al3, Tl + aoff);
        #pragma unroll
        for (int np = 0; np < 4; ++np){
            uint32_t boff = sw128((uint32_t)((kk*16 + krB)*128 + (np*16 + ncB8)*2));
            uint32_t bh0, bh1, bh2, bh3, bl0, bl1, bl2, bl3;
            ldsm4t(bh0, bh1, bh2, bh3, Wh + boff);
            ldsm4t(bl0, bl1, bl2, bl3, Wl + boff);
            mma16816(acc[np*2],   ah0, ah1, ah2, ah3, bh0, bh1);
            mma16816(acc[np*2+1], ah0, ah1, ah2, ah3, bh2, bh3);
            mma16816(acc[np*2],   ah0, ah1, ah2, ah3, bl0, bl1);
            mma16816(acc[np*2+1], ah0, ah1, ah2, ah3, bl2, bl3);
            mma16816(acc[np*2],   al0, al1, al2, al3, bh0, bh1);
            mma16816(acc[np*2+1], al0, al1, al2, al3, bh2, bh3);
        }
    }
}

// ---------------- weight prep: fp16 hi/lo split + SW128 swizzle -------------------
__global__ void k_wprep(const float* __restrict__ ew2, const float* __restrict__ fw1){
    int l = blockIdx.x >> 1, mat = blockIdx.x & 1;
    const float* src = (mat == 0) ? (ew2 + l*HH*HH) : (fw1 + l*HH*HH);
    __half* dh = g_wh[l][mat*2];
    __half* dl = g_wh[l][mat*2 + 1];
    for (int e = threadIdx.x; e < HH*HH; e += blockDim.x){
        float v = src[e];                      // [k][n], n fast
        __half hh = __float2half_rn(v);
        __half hl = __float2half_rn(v - __half2float(hh));
        uint32_t byte = (uint32_t)((e >> 6)*128 + (e & 63)*2);
        uint32_t sw = sw128(byte);
        dh[sw >> 1] = hh;
        dl[sw >> 1] = hl;
    }
}

// ---------------- fused: h init + layer-0 prep (writes buffer 0) ------------------
__global__ void k_pre(const float* __restrict__ state,
                      const float* __restrict__ hw, const float* __restrict__ hb,
                      const float* __restrict__ ew1l, const float* __restrict__ eb1l){
    __shared__ float hs[HH];
    int node = blockIdx.x; int t = threadIdx.x;
    float4 st = ((const float4*)state)[node];
    float spd = sqrtf(st.z*st.z + st.w*st.w);
    float h = silu_x(spd * hw[t] + hb[t]);
    g_h[node*HH + t] = h;
    hs[t] = h;
    __syncthreads();
    float a = eb1l[t], c = 0.f;
    #pragma unroll 8
    for (int k = 0; k < HH; ++k){
        float hv = hs[k];
        a = fmaf(hv, ew1l[k*HH + t],        a);
        c = fmaf(hv, ew1l[(HH + k)*HH + t], c);
    }
    g_a[0][node*HH + t] = a;
    int b = node >> 9, j = node & (NN - 1);
    g_ct[0][(b*HH + t)*NN + j] = c;
}

// ---------------- edge smem -------------------------------------------------------
struct EdgeSmem {
    __half T1h[JT*HH], T1l[JT*HH];   // 16KB each (T1 region aliased as MLP scratch in tail)
    __half T2h[JT*HH], T2l[JT*HH];
    __half WB[4][HH*HH];             // W2h, W2l, F1h, F1l : 8KB each
    float  A[HH];
    float4 WS[HH];
    float  B2[HH], FB1[HH], FW2[HH];
    float  Nx[2][JT], Ny[2][JT];     // double-buffered by tile parity
    float  Magg[HH], T2i[HH], Fxy[2];
};

// ---------------- edge kernel: CTA=(b,i), 256 thr, mma.sync fp16 ------------------
__global__ void __launch_bounds__(256, 2) k_edge(
    const float* __restrict__ state,
    const float* __restrict__ ew1l,
    const float* __restrict__ eb2l,
    const float* __restrict__ fb1l,
    const float* __restrict__ fw2l,
    const float* __restrict__ fb2l,
    const float* __restrict__ nw1l,
    const float* __restrict__ nb1l,
    const float* __restrict__ nw2l,
    const float* __restrict__ nb2l,
    const float* __restrict__ ew1n,   // next-layer edge_w1 (prep fusion)
    const float* __restrict__ eb1n,
    int layer, int accumulate, int prep_next)
{
    extern __shared__ __align__(16) char smem_raw[];
    EdgeSmem& s = *reinterpret_cast<EdgeSmem*>(smem_raw);

    int tid  = threadIdx.x;
    int wid  = tid >> 5;
    int lane = tid & 31;
    int bi   = blockIdx.x;
    int b    = bi >> 9;
    int i    = bi & (NN - 1);
    int m0   = wid * 16;             // warp's m-tile (j rows)
    int rb   = layer & 1;            // read buffer; tail writes rb^1

    {   // stage weights (32KB flat, coalesced)
        const float4* src = (const float4*)g_wh[layer][0];
        float4* dst = (float4*)s.WB[0];
        #pragma unroll
        for (int q = 0; q < 8; ++q) dst[tid + 256*q] = src[tid + 256*q];
    }
    if (tid < HH){
        s.A[tid]   = g_a[rb][bi*HH + tid];
        s.WS[tid]  = make_float4(ew1l[128*HH + tid], ew1l[129*HH + tid],
                                 ew1l[130*HH + tid], ew1l[131*HH + tid]);
        s.B2[tid]  = eb2l[tid];
        s.FB1[tid] = fb1l[tid];
        s.FW2[tid] = fw2l[tid];
        s.Magg[tid] = 0.0f;
        s.T2i[tid]  = 0.0f;
    }
    if (tid < 2) s.Fxy[tid] = 0.0f;

    uint32_t aT1h = smem_u32(s.T1h), aT1l = smem_u32(s.T1l);
    uint32_t aT2h = smem_u32(s.T2h), aT2l = smem_u32(s.T2l);
    uint32_t aW2h = smem_u32(s.WB[0]), aW2l = smem_u32(s.WB[1]);
    uint32_t aF1h = smem_u32(s.WB[2]), aF1l = smem_u32(s.WB[3]);

    float4 sti = ((const float4*)state)[b*NN + i];
    float spi  = sti.z*sti.z + sti.w*sti.w;
    float fb2v = fb2l[0];
    int jt_i = i >> 7, r_i = i & (JT - 1);

    float fx = 0.f, fy = 0.f;
    float cs[16];                    // deferred m_agg column partials
    #pragma unroll
    for (int q = 0; q < 16; ++q) cs[q] = 0.f;

    __syncthreads();   // (INIT) smem staging visible to all warps

    #pragma unroll 1
    for (int jt = 0; jt < NTILES; ++jt){
        int pb = jt & 1;             // Nx/Ny parity buffer
        // ================= stage 0: T1 row j -> fp16 hi/lo smem ==================
        {
            int jr = tid & (JT - 1);
            int half = tid >> 7;     // which 32 k's of the row
            int j = jt*JT + jr;
            float4 stj = ((const float4*)state)[b*NN + j];
            float dxp = stj.x - sti.x;
            float dyp = stj.y - sti.y;
            float dsq = dxp*dxp + dyp*dyp;
            float invd = rsqrtf(dsq + 1e-8f);
            float nx = dxp * invd;
            float ny = dyp * invd;
            float dvx = stj.z - sti.z;
            float dvy = stj.w - sti.w;
            float spj = stj.z*stj.z + stj.w*stj.w;
            float appr = dvx*nx + dvy*ny;
            if (half == 0){ s.Nx[pb][jr] = nx; s.Ny[pb][jr] = ny; }

            uint32_t hibuf[16], lobuf[16];
            #pragma unroll
            for (int q = 0; q < 16; ++q){
                float tv[2];
                #pragma unroll
                for (int e = 0; e < 2; ++e){
                    int n = half*32 + q*2 + e;
                    float c = g_ct[rb][(b*HH + n)*NN + j];
                    float4 w = s.WS[n];
                    float p = s.A[n] + c;
                    p = fmaf(dsq,  w.x, p);
                    p = fmaf(spi,  w.y, p);
                    p = fmaf(spj,  w.z, p);
                    p = fmaf(appr, w.w, p);
                    tv[e] = silu_f(p);
                }
                __half2 hp = __floats2half2_rn(tv[0], tv[1]);
                float2 hf = __half22float2(hp);
                __half2 lp = __floats2half2_rn(tv[0] - hf.x, tv[1] - hf.y);
                hibuf[q] = *(uint32_t*)&hp;
                lobuf[q] = *(uint32_t*)&lp;
            }
            #pragma unroll
            for (int c = 0; c < 4; ++c){
                uint32_t cc = (uint32_t)(half*4 + c);
                uint32_t off = (uint32_t)(jr*128) + ((cc ^ (uint32_t)(jr & 7)) << 4);
                *(uint4*)((char*)s.T1h + off) =
                    make_uint4(hibuf[c*4], hibuf[c*4+1], hibuf[c*4+2], hibuf[c*4+3]);
                *(uint4*)((char*)s.T1l + off) =
                    make_uint4(lobuf[c*4], lobuf[c*4+1], lobuf[c*4+2], lobuf[c*4+3]);
            }
        }
        __syncthreads();   // (A) T1 / Nx / Ny ready; also fences prev GEMM2 T2 reads

        // ================= GEMM1: D1 = T1 @ W2 (3-product fp16) ==================
        float acc[8][4];
        #pragma unroll
        for (int nt = 0; nt < 8; ++nt)
            #pragma unroll
            for (int p = 0; p < 4; ++p) acc[nt][p] = 0.f;
        gemm_mma(aT1h, aT1l, aW2h, aW2l, m0, lane, acc);

        // ---- epilogue1: silu(+b2), deferred magg partials, split->T2 smem ----
        #pragma unroll
        for (int nt = 0; nt < 8; ++nt){
            int c0 = nt*8 + (lane & 3)*2;
            float b2a = s.B2[c0], b2b = s.B2[c0+1];
            float v00 = silu_f(acc[nt][0] + b2a);
            float v01 = silu_f(acc[nt][1] + b2b);
            float v10 = silu_f(acc[nt][2] + b2a);
            float v11 = silu_f(acc[nt][3] + b2b);

            cs[nt*2]   += v00 + v10;
            cs[nt*2+1] += v01 + v11;

            int mg0 = m0 + (lane >> 2);
            int mg1 = mg0 + 8;
            uint32_t o0 = sw128((uint32_t)(mg0*128 + c0*2));
            uint32_t o1 = sw128((uint32_t)(mg1*128 + c0*2));
            __half2 h0p = __floats2half2_rn(v00, v01);
            float2  h0f = __half22float2(h0p);
            __half2 l0p = __floats2half2_rn(v00 - h0f.x, v01 - h0f.y);
            __half2 h1p = __floats2half2_rn(v10, v11);
            float2  h1f = __half22float2(h1p);
            __half2 l1p = __floats2half2_rn(v10 - h1f.x, v11 - h1f.y);
            *(__half2*)((char*)s.T2h + o0) = h0p;
            *(__half2*)((char*)s.T2l + o0) = l0p;
            *(__half2*)((char*)s.T2h + o1) = h1p;
            *(__half2*)((char*)s.T2l + o1) = l1p;
        }
        __syncthreads();   // (B) T2 ready

        // ---- capture T2 row i (for magg self-term subtraction) ----
        if (jt == jt_i && tid < 32){
            uint32_t o = sw128((uint32_t)(r_i*128 + tid*4));
            uint32_t hv = *(const uint32_t*)((const char*)s.T2h + o);
            uint32_t lv = *(const uint32_t*)((const char*)s.T2l + o);
            float v0 = __half2float(__ushort_as_half((unsigned short)(hv & 0xffff)))
                     + __half2float(__ushort_as_half((unsigned short)(lv & 0xffff)));
            float v1 = __half2float(__ushort_as_half((unsigned short)(hv >> 16)))
                     + __half2float(__ushort_as_half((unsigned short)(lv >> 16)));
            s.T2i[tid*2]     = v0;
            s.T2i[tid*2 + 1] = v1;
        }

        // ================= GEMM2: D2 = T2 @ F1 (3-product fp16) ==================
        #pragma unroll
        for (int nt = 0; nt < 8; ++nt)
            #pragma unroll
            for (int p = 0; p < 4; ++p) acc[nt][p] = 0.f;
        gemm_mma(aT2h, aT2l, aF1h, aF1l, m0, lane, acc);

        // ---- epilogue2: fw = silu(D2 + fb1) . fw2 + fb2; force ----
        float pm = 0.f, pm8 = 0.f;
        #pragma unroll
        for (int nt = 0; nt < 8; ++nt){
            int c0 = nt*8 + (lane & 3)*2;
            float fa = s.FB1[c0], fb = s.FB1[c0+1];
            float wa = s.FW2[c0], wb = s.FW2[c0+1];
            pm  = fmaf(silu_f(acc[nt][0] + fa), wa, pm);
            pm  = fmaf(silu_f(acc[nt][1] + fb), wb, pm);
            pm8 = fmaf(silu_f(acc[nt][2] + fa), wa, pm8);
            pm8 = fmaf(silu_f(acc[nt][3] + fb), wb, pm8);
        }
        pm  += __shfl_xor_sync(0xffffffffu, pm, 1);
        pm  += __shfl_xor_sync(0xffffffffu, pm, 2);
        pm8 += __shfl_xor_sync(0xffffffffu, pm8, 1);
        pm8 += __shfl_xor_sync(0xffffffffu, pm8, 2);
        if ((lane & 3) == 0){
            int r0_ = m0 + (lane >> 2);
            int r1_ = r0_ + 8;
            float f0 = pm + fb2v, f1 = pm8 + fb2v;
            // normal is exactly 0 at j==i -> self-term auto-masked
            fx = fmaf(f0, s.Nx[pb][r0_], fx); fx = fmaf(f1, s.Nx[pb][r1_], fx);
            fy = fmaf(f0, s.Ny[pb][r0_], fy); fy = fmaf(f1, s.Ny[pb][r1_], fy);
        }
        // no barrier: Nx/Ny double-buffered; T1/T2 reuse fenced by sync (A)/(B)
    }

    // ---- final m_agg reduction (once) ----
    #pragma unroll
    for (int nt = 0; nt < 8; ++nt){
        float s0 = cs[nt*2], s1 = cs[nt*2+1];
        s0 += __shfl_xor_sync(0xffffffffu, s0, 4);
        s0 += __shfl_xor_sync(0xffffffffu, s0, 8);
        s0 += __shfl_xor_sync(0xffffffffu, s0, 16);
        s1 += __shfl_xor_sync(0xffffffffu, s1, 4);
        s1 += __shfl_xor_sync(0xffffffffu, s1, 8);
        s1 += __shfl_xor_sync(0xffffffffu, s1, 16);
        if (lane < 4){
            int c0 = nt*8 + lane*2;
            atomicAdd(&s.Magg[c0],     s0);
            atomicAdd(&s.Magg[c0 + 1], s1);
        }
    }
    // ---- reduce forces ----
    fx += __shfl_xor_sync(0xffffffffu, fx, 16);
    fx += __shfl_xor_sync(0xffffffffu, fx, 8);
    fx += __shfl_xor_sync(0xffffffffu, fx, 4);
    fy += __shfl_xor_sync(0xffffffffu, fy, 16);
    fy += __shfl_xor_sync(0xffffffffu, fy, 8);
    fy += __shfl_xor_sync(0xffffffffu, fy, 4);
    if (lane == 0){
        atomicAdd(&s.Fxy[0], fx);
        atomicAdd(&s.Fxy[1], fy);
    }
    __syncthreads();   // Magg / Fxy final

    if (tid < 2){
        float v = s.Fxy[tid];
        if (accumulate) g_fsum[bi*2 + tid] += v;
        else            g_fsum[bi*2 + tid] = v;
    }

    // ================= fused node-update MLP (h_new for node bi) =================
    float* sIn = (float*)s.T1h;      // 128 floats (T1 region is dead now)
    float* sP  = sIn + 128;          // 256 partials
    float* sY  = sP + 256;           // 64
    if (tid < 64)       sIn[tid] = g_h[bi*HH + tid];
    else if (tid < 128) sIn[tid] = s.Magg[tid - 64] - s.T2i[tid - 64];
    __syncthreads();
    {
        int out = tid & 63, chk = tid >> 6;
        float p = 0.f;
        #pragma unroll 8
        for (int k = 0; k < 32; ++k)
            p = fmaf(sIn[chk*32 + k], nw1l[(chk*32 + k)*HH + out], p);
        sP[tid] = p;
    }
    __syncthreads();
    if (tid < 64)
        sY[tid] = silu_x(sP[tid] + sP[tid+64] + sP[tid+128] + sP[tid+192] + nb1l[tid]);
    __syncthreads();
    {
        int out = tid & 63, chk = tid >> 6;
        float p = 0.f;
        #pragma unroll 8
        for (int k = 0; k < 16; ++k)
            p = fmaf(sY[chk*16 + k], nw2l[(chk*16 + k)*HH + out], p);
        sP[tid] = p;
    }
    __syncthreads();
    if (tid < 64){
        float hn = sP[tid] + sP[tid+64] + sP[tid+128] + sP[tid+192] + nb2l[tid];
        g_h[bi*HH + tid] = hn;
        sIn[tid] = hn;               // keep for fused next-layer prep
    }
    __syncthreads();

    // ====== fused next-layer prep: a_i, c_j for node bi (writes rb^1 buffer) ======
    if (prep_next && tid < 128){
        int out = tid & 63, which = tid >> 6;
        float a = which ? 0.f : eb1n[out];
        const float* w = ew1n + (which ? HH*HH : 0);
        #pragma unroll 8
        for (int k = 0; k < HH; ++k)
            a = fmaf(sIn[k], w[k*HH + out], a);
        if (which == 0) g_a[rb ^ 1][bi*HH + out] = a;
        else            g_ct[rb ^ 1][(b*HH + out)*NN + i] = a;
    }
}

// ---------------- wall MLP + output (node update already fused) -------------------
__global__ void k_final(const float* __restrict__ state,
                        const float* __restrict__ w1, const float* __restrict__ b1,
                        const float* __restrict__ w2, const float* __restrict__ b2,
                        const float* __restrict__ w3, const float* __restrict__ b3,
                        float* __restrict__ out){
    __shared__ float sH[HH + 4];
    __shared__ float sY[HH];
    __shared__ float sM[4];
    int node = blockIdx.x; int t = threadIdx.x;
    sH[t] = g_h[node*HH + t];
    if (t < 4){
        float4 st = ((const float4*)state)[node];
        float d = (t == 0) ? st.x : (t == 1) ? 1.0f - st.x
                : (t == 2) ? st.y : 1.0f - st.y;
        sH[HH + t] = d;
    }
    __syncthreads();
    float a1 = b1[t];
    #pragma unroll 4
    for (int k = 0; k < HH + 4; ++k) a1 = fmaf(sH[k], w1[k*HH + t], a1);
    sY[t] = silu_x(a1);
    __syncthreads();
    float a2 = b2[t];
    #pragma unroll 8
    for (int k = 0; k < HH; ++k) a2 = fmaf(sY[k], w2[k*HH + t], a2);
    __syncthreads();
    sY[t] = silu_x(a2);
    __syncthreads();
    if (t < 4){
        float m = b3[t];
        #pragma unroll 8
        for (int k = 0; k < HH; ++k) m = fmaf(sY[k], w3[k*4 + t], m);
        sM[t] = m;
    }
    __syncthreads();
    if (t < 2){
        float wf = (t == 0) ? (sM[0] - sM[1]) : (sM[2] - sM[3]);
        out[node*2 + t] = g_fsum[node*2 + t] + wf;
    }
}

// ---------------- launch ----------------------------------------------------------
extern "C" void kernel_launch(void* const* d_in, const int* in_sizes, int n_in,
                              void* d_out, int out_size){
    const float* state = (const float*)d_in[0];
    const float* hiw  = (const float*)d_in[1];
    const float* hib  = (const float*)d_in[2];
    const float* ew1  = (const float*)d_in[3];
    const float* eb1  = (const float*)d_in[4];
    const float* ew2  = (const float*)d_in[5];
    const float* eb2  = (const float*)d_in[6];
    const float* fw1  = (const float*)d_in[7];
    const float* fb1  = (const float*)d_in[8];
    const float* fw2  = (const float*)d_in[9];
    const float* fb2  = (const float*)d_in[10];
    const float* nw1  = (const float*)d_in[11];
    const float* nb1  = (const float*)d_in[12];
    const float* nw2  = (const float*)d_in[13];
    const float* nb2  = (const float*)d_in[14];
    const float* ww1  = (const float*)d_in[15];
    const float* wb1  = (const float*)d_in[16];
    const float* ww2  = (const float*)d_in[17];
    const float* wb2  = (const float*)d_in[18];
    const float* ww3  = (const float*)d_in[19];
    const float* wb3  = (const float*)d_in[20];
    float* out = (float*)d_out;

    int smem = (int)sizeof(EdgeSmem);
    cudaFuncSetAttribute(k_edge, cudaFuncAttributeMaxDynamicSharedMemorySize, smem);

    k_wprep<<<6, 256>>>(ew2, fw1);
    k_pre<<<NODES, HH>>>(state, hiw, hib, ew1, eb1);
    for (int l = 0; l < 3; ++l){
        int pn = (l < 2) ? 1 : 0;
        const float* ew1n = ew1 + (pn ? (l+1)*132*HH : 0);
        const float* eb1n = eb1 + (pn ? (l+1)*HH : 0);
        k_edge<<<NODES, 256, smem>>>(state,
                               ew1 + l*132*HH,
                               eb2 + l*HH,
                               fb1 + l*HH,
                               fw2 + l*HH,
                               fb2 + l,
                               nw1 + l*2*HH*HH, nb1 + l*HH,
                               nw2 + l*HH*HH,   nb2 + l*HH,
                               ew1n, eb1n,
                               l, l, pn);
    }
    k_final<<<NODES, HH>>>(state, ww1, wb1, ww2, wb2, ww3, wb3, out);
}

// round 12
// speedup vs baseline: 5.5029x; 1.1433x over previous
#include <cuda_runtime.h>
#include <cuda_fp16.h>
#include <cstdint>

#define BB 2
#define NN 512
#define HH 64
#define NODES (BB*NN)
#define JT 128
#define NTILES (NN/JT)

// ---------------- scratch (device globals) -------------------------------------
__device__ float g_h[NODES*HH];
__device__ float g_a[2][NODES*HH];        // ping-pong by layer parity (race-free fused prep)
__device__ float g_ct[2][BB*HH*NN];       // c_j, n-major: [b][n][j]
__device__ float g_fsum[NODES*2];
__device__ __half g_wh[3][4][HH*HH];      // per layer: W2hi,W2lo,F1hi,F1lo (swizzled [k][n] fp16)

// ---------------- helpers -------------------------------------------------------
// silu(x) = x * sigmoid(x) = 0.5*x*(1 + tanh(x/2)) ; tanh.approx = 1 MUFU op
__device__ __forceinline__ float silu_f(float x){
    float t;
    asm("tanh.approx.f32 %0, %1;" : "=f"(t) : "f"(x * 0.5f));
    return 0.5f * x * (1.0f + t);
}
// exact silu for the scalar pre/final paths (negligible cost there)
__device__ __forceinline__ float silu_x(float x){
    float e = __expf(-x);
    return x * __fdividef(1.0f, 1.0f + e);
}
__device__ __forceinline__ uint32_t smem_u32(const void* p){
    uint32_t a;
    asm("{ .reg .u64 t; cvta.to.shared.u64 t, %1; cvt.u32.u64 %0, t; }" : "=r"(a) : "l"(p));
    return a;
}
__device__ __forceinline__ uint32_t sw128(uint32_t b){ return b ^ ((b >> 3) & 0x70); }

__device__ __forceinline__ void ldsm4(uint32_t& r0, uint32_t& r1, uint32_t& r2, uint32_t& r3, uint32_t a){
    asm volatile("ldmatrix.sync.aligned.m8n8.x4.shared.b16 {%0,%1,%2,%3}, [%4];"
                 : "=r"(r0), "=r"(r1), "=r"(r2), "=r"(r3) : "r"(a));
}
__device__ __forceinline__ void ldsm4t(uint32_t& r0, uint32_t& r1, uint32_t& r2, uint32_t& r3, uint32_t a){
    asm volatile("ldmatrix.sync.aligned.m8n8.x4.trans.shared.b16 {%0,%1,%2,%3}, [%4];"
                 : "=r"(r0), "=r"(r1), "=r"(r2), "=r"(r3) : "r"(a));
}
__device__ __forceinline__ void mma16816(float* d, uint32_t a0, uint32_t a1, uint32_t a2, uint32_t a3,
                                         uint32_t b0, uint32_t b1){
    asm volatile("mma.sync.aligned.m16n8k16.row.col.f32.f16.f16.f32 "
                 "{%0,%1,%2,%3},{%4,%5,%6,%7},{%8,%9},{%0,%1,%2,%3};"
                 : "+f"(d[0]), "+f"(d[1]), "+f"(d[2]), "+f"(d[3])
                 : "r"(a0), "r"(a1), "r"(a2), "r"(a3), "r"(b0), "r"(b1));
}

// fp16 split-GEMM: D[128x64] += T[128x64] @ W[64x64], 2-product compensation:
// T in fp16 (hi only), W = Wh + Wl split. D += Th·Wh + Th·Wl.
__device__ __forceinline__ void gemm_mma(uint32_t Th, uint32_t Wh, uint32_t Wl,
                                         int m0, int lane, float acc[8][4]){
    int rA    = m0 + (lane & 7) + ((lane >> 3) & 1) * 8;
    int colA8 = ((lane >> 4) & 1) * 8;
    int krB   = (lane & 7) + ((lane >> 3) & 1) * 8;
    int ncB8  = ((lane >> 4) & 1) * 8;
    #pragma unroll
    for (int kk = 0; kk < 4; ++kk){
        uint32_t aoff = sw128((uint32_t)(rA*128 + (kk*16 + colA8)*2));
        uint32_t ah0, ah1, ah2, ah3;
        ldsm4(ah0, ah1, ah2, ah3, Th + aoff);
        #pragma unroll
        for (int np = 0; np < 4; ++np){
            uint32_t boff = sw128((uint32_t)((kk*16 + krB)*128 + (np*16 + ncB8)*2));
            uint32_t bh0, bh1, bh2, bh3, bl0, bl1, bl2, bl3;
            ldsm4t(bh0, bh1, bh2, bh3, Wh + boff);
            ldsm4t(bl0, bl1, bl2, bl3, Wl + boff);
            mma16816(acc[np*2],   ah0, ah1, ah2, ah3, bh0, bh1);
            mma16816(acc[np*2+1], ah0, ah1, ah2, ah3, bh2, bh3);
            mma16816(acc[np*2],   ah0, ah1, ah2, ah3, bl0, bl1);
            mma16816(acc[np*2+1], ah0, ah1, ah2, ah3, bl2, bl3);
        }
    }
}

// ---------------- weight prep: fp16 hi/lo split + SW128 swizzle -------------------
__global__ void k_wprep(const float* __restrict__ ew2, const float* __restrict__ fw1){
    int l = blockIdx.x >> 1, mat = blockIdx.x & 1;
    const float* src = (mat == 0) ? (ew2 + l*HH*HH) : (fw1 + l*HH*HH);
    __half* dh = g_wh[l][mat*2];
    __half* dl = g_wh[l][mat*2 + 1];
    for (int e = threadIdx.x; e < HH*HH; e += blockDim.x){
        float v = src[e];                      // [k][n], n fast
        __half hh = __float2half_rn(v);
        __half hl = __float2half_rn(v - __half2float(hh));
        uint32_t byte = (uint32_t)((e >> 6)*128 + (e & 63)*2);
        uint32_t sw = sw128(byte);
        dh[sw >> 1] = hh;
        dl[sw >> 1] = hl;
    }
}

// ---------------- fused: h init + layer-0 prep (writes buffer 0) ------------------
__global__ void k_pre(const float* __restrict__ state,
                      const float* __restrict__ hw, const float* __restrict__ hb,
                      const float* __restrict__ ew1l, const float* __restrict__ eb1l){
    __shared__ float hs[HH];
    int node = blockIdx.x; int t = threadIdx.x;
    float4 st = ((const float4*)state)[node];
    float spd = sqrtf(st.z*st.z + st.w*st.w);
    float h = silu_x(spd * hw[t] + hb[t]);
    g_h[node*HH + t] = h;
    hs[t] = h;
    __syncthreads();
    float a = eb1l[t], c = 0.f;
    #pragma unroll 8
    for (int k = 0; k < HH; ++k){
        float hv = hs[k];
        a = fmaf(hv, ew1l[k*HH + t],        a);
        c = fmaf(hv, ew1l[(HH + k)*HH + t], c);
    }
    g_a[0][node*HH + t] = a;
    int b = node >> 9, j = node & (NN - 1);
    g_ct[0][(b*HH + t)*NN + j] = c;
}

// ---------------- edge smem -------------------------------------------------------
struct EdgeSmem {
    __half T1h[JT*HH];               // 16KB (aliased as MLP scratch in tail)
    __half T2h[JT*HH];               // 16KB
    __half WB[4][HH*HH];             // W2h, W2l, F1h, F1l : 8KB each
    float  A[HH];
    float4 WS[HH];
    float  B2[HH], FB1[HH], FW2[HH];
    float  Nx[2][JT], Ny[2][JT];     // double-buffered by tile parity
    float  Magg[HH], T2i[HH], Fxy[2];
};

// ---------------- edge kernel: CTA=(b,i), 256 thr, mma.sync fp16 ------------------
__global__ void __launch_bounds__(256, 2) k_edge(
    const float* __restrict__ state,
    const float* __restrict__ ew1l,
    const float* __restrict__ eb2l,
    const float* __restrict__ fb1l,
    const float* __restrict__ fw2l,
    const float* __restrict__ fb2l,
    const float* __restrict__ nw1l,
    const float* __restrict__ nb1l,
    const float* __restrict__ nw2l,
    const float* __restrict__ nb2l,
    const float* __restrict__ ew1n,   // next-layer edge_w1 (prep fusion)
    const float* __restrict__ eb1n,
    int layer, int accumulate, int prep_next)
{
    extern __shared__ __align__(16) char smem_raw[];
    EdgeSmem& s = *reinterpret_cast<EdgeSmem*>(smem_raw);

    int tid  = threadIdx.x;
    int wid  = tid >> 5;
    int lane = tid & 31;
    int bi   = blockIdx.x;
    int b    = bi >> 9;
    int i    = bi & (NN - 1);
    int m0   = wid * 16;             // warp's m-tile (j rows)
    int rb   = layer & 1;            // read buffer; tail writes rb^1

    {   // stage weights (32KB flat, coalesced)
        const float4* src = (const float4*)g_wh[layer][0];
        float4* dst = (float4*)s.WB[0];
        #pragma unroll
        for (int q = 0; q < 8; ++q) dst[tid + 256*q] = src[tid + 256*q];
    }
    if (tid < HH){
        s.A[tid]   = g_a[rb][bi*HH + tid];
        s.WS[tid]  = make_float4(ew1l[128*HH + tid], ew1l[129*HH + tid],
                                 ew1l[130*HH + tid], ew1l[131*HH + tid]);
        s.B2[tid]  = eb2l[tid];
        s.FB1[tid] = fb1l[tid];
        s.FW2[tid] = fw2l[tid];
        s.Magg[tid] = 0.0f;
        s.T2i[tid]  = 0.0f;
    }
    if (tid < 2) s.Fxy[tid] = 0.0f;

    uint32_t aT1h = smem_u32(s.T1h);
    uint32_t aT2h = smem_u32(s.T2h);
    uint32_t aW2h = smem_u32(s.WB[0]), aW2l = smem_u32(s.WB[1]);
    uint32_t aF1h = smem_u32(s.WB[2]), aF1l = smem_u32(s.WB[3]);

    float4 sti = ((const float4*)state)[b*NN + i];
    float spi  = sti.z*sti.z + sti.w*sti.w;
    float fb2v = fb2l[0];
    int jt_i = i >> 7, r_i = i & (JT - 1);

    float fx = 0.f, fy = 0.f;
    float cs[16];                    // deferred m_agg column partials
    #pragma unroll
    for (int q = 0; q < 16; ++q) cs[q] = 0.f;

    __syncthreads();   // (INIT) smem staging visible to all warps

    #pragma unroll 1
    for (int jt = 0; jt < NTILES; ++jt){
        int pb = jt & 1;             // Nx/Ny parity buffer
        // ================= stage 0: T1 row j -> fp16 smem ========================
        {
            int jr = tid & (JT - 1);
            int half = tid >> 7;     // which 32 k's of the row
            int j = jt*JT + jr;
            float4 stj = ((const float4*)state)[b*NN + j];
            float dxp = stj.x - sti.x;
            float dyp = stj.y - sti.y;
            float dsq = dxp*dxp + dyp*dyp;
            float invd = rsqrtf(dsq + 1e-8f);
            float nx = dxp * invd;
            float ny = dyp * invd;
            float dvx = stj.z - sti.z;
            float dvy = stj.w - sti.w;
            float spj = stj.z*stj.z + stj.w*stj.w;
            float appr = dvx*nx + dvy*ny;
            if (half == 0){ s.Nx[pb][jr] = nx; s.Ny[pb][jr] = ny; }

            uint32_t hibuf[16];
            #pragma unroll
            for (int q = 0; q < 16; ++q){
                float tv[2];
                #pragma unroll
                for (int e = 0; e < 2; ++e){
                    int n = half*32 + q*2 + e;
                    float c = g_ct[rb][(b*HH + n)*NN + j];
                    float4 w = s.WS[n];
                    float p = s.A[n] + c;
                    p = fmaf(dsq,  w.x, p);
                    p = fmaf(spi,  w.y, p);
                    p = fmaf(spj,  w.z, p);
                    p = fmaf(appr, w.w, p);
                    tv[e] = silu_f(p);
                }
                __half2 hp = __floats2half2_rn(tv[0], tv[1]);
                hibuf[q] = *(uint32_t*)&hp;
            }
            #pragma unroll
            for (int c = 0; c < 4; ++c){
                uint32_t cc = (uint32_t)(half*4 + c);
                uint32_t off = (uint32_t)(jr*128) + ((cc ^ (uint32_t)(jr & 7)) << 4);
                *(uint4*)((char*)s.T1h + off) =
                    make_uint4(hibuf[c*4], hibuf[c*4+1], hibuf[c*4+2], hibuf[c*4+3]);
            }
        }
        __syncthreads();   // (A) T1 / Nx / Ny ready; also fences prev GEMM2 T2 reads

        // ================= GEMM1: D1 = T1 @ (W2h + W2l) ==========================
        float acc[8][4];
        #pragma unroll
        for (int nt = 0; nt < 8; ++nt)
            #pragma unroll
            for (int p = 0; p < 4; ++p) acc[nt][p] = 0.f;
        gemm_mma(aT1h, aW2h, aW2l, m0, lane, acc);

        // ---- epilogue1: silu(+b2), deferred magg partials, ->T2 smem ----
        #pragma unroll
        for (int nt = 0; nt < 8; ++nt){
            int c0 = nt*8 + (lane & 3)*2;
            float b2a = s.B2[c0], b2b = s.B2[c0+1];
            float v00 = silu_f(acc[nt][0] + b2a);
            float v01 = silu_f(acc[nt][1] + b2b);
            float v10 = silu_f(acc[nt][2] + b2a);
            float v11 = silu_f(acc[nt][3] + b2b);

            cs[nt*2]   += v00 + v10;
            cs[nt*2+1] += v01 + v11;

            int mg0 = m0 + (lane >> 2);
            int mg1 = mg0 + 8;
            uint32_t o0 = sw128((uint32_t)(mg0*128 + c0*2));
            uint32_t o1 = sw128((uint32_t)(mg1*128 + c0*2));
            *(__half2*)((char*)s.T2h + o0) = __floats2half2_rn(v00, v01);
            *(__half2*)((char*)s.T2h + o1) = __floats2half2_rn(v10, v11);
        }
        __syncthreads();   // (B) T2 ready

        // ---- capture T2 row i (for magg self-term subtraction) ----
        if (jt == jt_i && tid < 32){
            uint32_t o = sw128((uint32_t)(r_i*128 + tid*4));
            uint32_t hv = *(const uint32_t*)((const char*)s.T2h + o);
            s.T2i[tid*2]     = __half2float(__ushort_as_half((unsigned short)(hv & 0xffff)));
            s.T2i[tid*2 + 1] = __half2float(__ushort_as_half((unsigned short)(hv >> 16)));
        }

        // ================= GEMM2: D2 = T2 @ (F1h + F1l) ==========================
        #pragma unroll
        for (int nt = 0; nt < 8; ++nt)
            #pragma unroll
            for (int p = 0; p < 4; ++p) acc[nt][p] = 0.f;
        gemm_mma(aT2h, aF1h, aF1l, m0, lane, acc);

        // ---- epilogue2: fw = silu(D2 + fb1) . fw2 + fb2; force ----
        float pm = 0.f, pm8 = 0.f;
        #pragma unroll
        for (int nt = 0; nt < 8; ++nt){
            int c0 = nt*8 + (lane & 3)*2;
            float fa = s.FB1[c0], fb = s.FB1[c0+1];
            float wa = s.FW2[c0], wb = s.FW2[c0+1];
            pm  = fmaf(silu_f(acc[nt][0] + fa), wa, pm);
            pm  = fmaf(silu_f(acc[nt][1] + fb), wb, pm);
            pm8 = fmaf(silu_f(acc[nt][2] + fa), wa, pm8);
            pm8 = fmaf(silu_f(acc[nt][3] + fb), wb, pm8);
        }
        pm  += __shfl_xor_sync(0xffffffffu, pm, 1);
        pm  += __shfl_xor_sync(0xffffffffu, pm, 2);
        pm8 += __shfl_xor_sync(0xffffffffu, pm8, 1);
        pm8 += __shfl_xor_sync(0xffffffffu, pm8, 2);
        if ((lane & 3) == 0){
            int r0_ = m0 + (lane >> 2);
            int r1_ = r0_ + 8;
            float f0 = pm + fb2v, f1 = pm8 + fb2v;
            // normal is exactly 0 at j==i -> self-term auto-masked
            fx = fmaf(f0, s.Nx[pb][r0_], fx); fx = fmaf(f1, s.Nx[pb][r1_], fx);
            fy = fmaf(f0, s.Ny[pb][r0_], fy); fy = fmaf(f1, s.Ny[pb][r1_], fy);
        }
        // no barrier: Nx/Ny double-buffered; T1/T2 reuse fenced by sync (A)/(B)
    }

    // ---- final m_agg reduction (once) ----
    #pragma unroll
    for (int nt = 0; nt < 8; ++nt){
        float s0 = cs[nt*2], s1 = cs[nt*2+1];
        s0 += __shfl_xor_sync(0xffffffffu, s0, 4);
        s0 += __shfl_xor_sync(0xffffffffu, s0, 8);
        s0 += __shfl_xor_sync(0xffffffffu, s0, 16);
        s1 += __shfl_xor_sync(0xffffffffu, s1, 4);
        s1 += __shfl_xor_sync(0xffffffffu, s1, 8);
        s1 += __shfl_xor_sync(0xffffffffu, s1, 16);
        if (lane < 4){
            int c0 = nt*8 + lane*2;
            atomicAdd(&s.Magg[c0],     s0);
            atomicAdd(&s.Magg[c0 + 1], s1);
        }
    }
    // ---- reduce forces ----
    fx += __shfl_xor_sync(0xffffffffu, fx, 16);
    fx += __shfl_xor_sync(0xffffffffu, fx, 8);
    fx += __shfl_xor_sync(0xffffffffu, fx, 4);
    fy += __shfl_xor_sync(0xffffffffu, fy, 16);
    fy += __shfl_xor_sync(0xffffffffu, fy, 8);
    fy += __shfl_xor_sync(0xffffffffu, fy, 4);
    if (lane == 0){
        atomicAdd(&s.Fxy[0], fx);
        atomicAdd(&s.Fxy[1], fy);
    }
    __syncthreads();   // Magg / Fxy final

    if (tid < 2){
        float v = s.Fxy[tid];
        if (accumulate) g_fsum[bi*2 + tid] += v;
        else            g_fsum[bi*2 + tid] = v;
    }

    // ================= fused node-update MLP (h_new for node bi) =================
    float* sIn = (float*)s.T1h;      // 128 floats (T1 region is dead now)
    float* sP  = sIn + 128;          // 256 partials
    float* sY  = sP + 256;           // 64
    if (tid < 64)       sIn[tid] = g_h[bi*HH + tid];
    else if (tid < 128) sIn[tid] = s.Magg[tid - 64] - s.T2i[tid - 64];
    __syncthreads();
    {
        int out = tid & 63, chk = tid >> 6;
        float p = 0.f;
        #pragma unroll 8
        for (int k = 0; k < 32; ++k)
            p = fmaf(sIn[chk*32 + k], nw1l[(chk*32 + k)*HH + out], p);
        sP[tid] = p;
    }
    __syncthreads();
    if (tid < 64)
        sY[tid] = silu_x(sP[tid] + sP[tid+64] + sP[tid+128] + sP[tid+192] + nb1l[tid]);
    __syncthreads();
    {
        int out = tid & 63, chk = tid >> 6;
        float p = 0.f;
        #pragma unroll 8
        for (int k = 0; k < 16; ++k)
            p = fmaf(sY[chk*16 + k], nw2l[(chk*16 + k)*HH + out], p);
        sP[tid] = p;
    }
    __syncthreads();
    if (tid < 64){
        float hn = sP[tid] + sP[tid+64] + sP[tid+128] + sP[tid+192] + nb2l[tid];
        g_h[bi*HH + tid] = hn;
        sIn[tid] = hn;               // keep for fused next-layer prep
    }
    __syncthreads();

    // ====== fused next-layer prep: a_i, c_j for node bi (writes rb^1 buffer) ======
    if (prep_next && tid < 128){
        int out = tid & 63, which = tid >> 6;
        float a = which ? 0.f : eb1n[out];
        const float* w = ew1n + (which ? HH*HH : 0);
        #pragma unroll 8
        for (int k = 0; k < HH; ++k)
            a = fmaf(sIn[k], w[k*HH + out], a);
        if (which == 0) g_a[rb ^ 1][bi*HH + out] = a;
        else            g_ct[rb ^ 1][(b*HH + out)*NN + i] = a;
    }
}

// ---------------- wall MLP + output (node update already fused) -------------------
__global__ void k_final(const float* __restrict__ state,
                        const float* __restrict__ w1, const float* __restrict__ b1,
                        const float* __restrict__ w2, const float* __restrict__ b2,
                        const float* __restrict__ w3, const float* __restrict__ b3,
                        float* __restrict__ out){
    __shared__ float sH[HH + 4];
    __shared__ float sY[HH];
    __shared__ float sM[4];
    int node = blockIdx.x; int t = threadIdx.x;
    sH[t] = g_h[node*HH + t];
    if (t < 4){
        float4 st = ((const float4*)state)[node];
        float d = (t == 0) ? st.x : (t == 1) ? 1.0f - st.x
                : (t == 2) ? st.y : 1.0f - st.y;
        sH[HH + t] = d;
    }
    __syncthreads();
    float a1 = b1[t];
    #pragma unroll 4
    for (int k = 0; k < HH + 4; ++k) a1 = fmaf(sH[k], w1[k*HH + t], a1);
    sY[t] = silu_x(a1);
    __syncthreads();
    float a2 = b2[t];
    #pragma unroll 8
    for (int k = 0; k < HH; ++k) a2 = fmaf(sY[k], w2[k*HH + t], a2);
    __syncthreads();
    sY[t] = silu_x(a2);
    __syncthreads();
    if (t < 4){
        float m = b3[t];
        #pragma unroll 8
        for (int k = 0; k < HH; ++k) m = fmaf(sY[k], w3[k*4 + t], m);
        sM[t] = m;
    }
    __syncthreads();
    if (t < 2){
        float wf = (t == 0) ? (sM[0] - sM[1]) : (sM[2] - sM[3]);
        out[node*2 + t] = g_fsum[node*2 + t] + wf;
    }
}

// ---------------- launch ----------------------------------------------------------
extern "C" void kernel_launch(void* const* d_in, const int* in_sizes, int n_in,
                              void* d_out, int out_size){
    const float* state = (const float*)d_in[0];
    const float* hiw  = (const float*)d_in[1];
    const float* hib  = (const float*)d_in[2];
    const float* ew1  = (const float*)d_in[3];
    const float* eb1  = (const float*)d_in[4];
    const float* ew2  = (const float*)d_in[5];
    const float* eb2  = (const float*)d_in[6];
    const float* fw1  = (const float*)d_in[7];
    const float* fb1  = (const float*)d_in[8];
    const float* fw2  = (const float*)d_in[9];
    const float* fb2  = (const float*)d_in[10];
    const float* nw1  = (const float*)d_in[11];
    const float* nb1  = (const float*)d_in[12];
    const float* nw2  = (const float*)d_in[13];
    const float* nb2  = (const float*)d_in[14];
    const float* ww1  = (const float*)d_in[15];
    const float* wb1  = (const float*)d_in[16];
    const float* ww2  = (const float*)d_in[17];
    const float* wb2  = (const float*)d_in[18];
    const float* ww3  = (const float*)d_in[19];
    const float* wb3  = (const float*)d_in[20];
    float* out = (float*)d_out;

    int smem = (int)sizeof(EdgeSmem);
    cudaFuncSetAttribute(k_edge, cudaFuncAttributeMaxDynamicSharedMemorySize, smem);

    k_wprep<<<6, 256>>>(ew2, fw1);
    k_pre<<<NODES, HH>>>(state, hiw, hib, ew1, eb1);
    for (int l = 0; l < 3; ++l){
        int pn = (l < 2) ? 1 : 0;
        const float* ew1n = ew1 + (pn ? (l+1)*132*HH : 0);
        const float* eb1n = eb1 + (pn ? (l+1)*HH : 0);
        k_edge<<<NODES, 256, smem>>>(state,
                               ew1 + l*132*HH,
                               eb2 + l*HH,
                               fb1 + l*HH,
                               fw2 + l*HH,
                               fb2 + l,
                               nw1 + l*2*HH*HH, nb1 + l*HH,
                               nw2 + l*HH*HH,   nb2 + l*HH,
                               ew1n, eb1n,
                               l, l, pn);
    }
    k_final<<<NODES, HH>>>(state, ww1, wb1, ww2, wb2, ww3, wb3, out);
}

// round 13
// speedup vs baseline: 6.4737x; 1.1764x over previous
#include <cuda_runtime.h>
#include <cuda_fp16.h>
#include <cstdint>

#define BB 2
#define NN 512
#define HH 64
#define NODES (BB*NN)
#define JT 128
#define NTILES (NN/JT)

// ---------------- scratch (device globals) -------------------------------------
__device__ float g_h[NODES*HH];
__device__ float g_a[2][NODES*HH];        // ping-pong by layer parity (race-free fused prep)
__device__ float g_ct[2][BB*HH*NN];       // c_j, n-major: [b][n][j]
__device__ float g_fsum[NODES*2];
__device__ __half g_wh[3][2][HH*HH];      // per layer: W2, F1 (fp16, swizzled [k][n])

// ---------------- helpers -------------------------------------------------------
// silu(x) = x * sigmoid(x) = 0.5*x*(1 + tanh(x/2)) ; tanh.approx = 1 MUFU op
__device__ __forceinline__ float silu_f(float x){
    float t;
    asm("tanh.approx.f32 %0, %1;" : "=f"(t) : "f"(x * 0.5f));
    return 0.5f * x * (1.0f + t);
}
// exact silu for the scalar pre/final paths (negligible cost there)
__device__ __forceinline__ float silu_x(float x){
    float e = __expf(-x);
    return x * __fdividef(1.0f, 1.0f + e);
}
__device__ __forceinline__ uint32_t smem_u32(const void* p){
    uint32_t a;
    asm("{ .reg .u64 t; cvta.to.shared.u64 t, %1; cvt.u32.u64 %0, t; }" : "=r"(a) : "l"(p));
    return a;
}
__device__ __forceinline__ uint32_t sw128(uint32_t b){ return b ^ ((b >> 3) & 0x70); }

__device__ __forceinline__ void ldsm4(uint32_t& r0, uint32_t& r1, uint32_t& r2, uint32_t& r3, uint32_t a){
    asm volatile("ldmatrix.sync.aligned.m8n8.x4.shared.b16 {%0,%1,%2,%3}, [%4];"
                 : "=r"(r0), "=r"(r1), "=r"(r2), "=r"(r3) : "r"(a));
}
__device__ __forceinline__ void ldsm4t(uint32_t& r0, uint32_t& r1, uint32_t& r2, uint32_t& r3, uint32_t a){
    asm volatile("ldmatrix.sync.aligned.m8n8.x4.trans.shared.b16 {%0,%1,%2,%3}, [%4];"
                 : "=r"(r0), "=r"(r1), "=r"(r2), "=r"(r3) : "r"(a));
}
__device__ __forceinline__ void mma16816(float* d, uint32_t a0, uint32_t a1, uint32_t a2, uint32_t a3,
                                         uint32_t b0, uint32_t b1){
    asm volatile("mma.sync.aligned.m16n8k16.row.col.f32.f16.f16.f32 "
                 "{%0,%1,%2,%3},{%4,%5,%6,%7},{%8,%9},{%0,%1,%2,%3};"
                 : "+f"(d[0]), "+f"(d[1]), "+f"(d[2]), "+f"(d[3])
                 : "r"(a0), "r"(a1), "r"(a2), "r"(a3), "r"(b0), "r"(b1));
}

// fp16 GEMM: D[128x64] += T[128x64] @ W[64x64] (plain fp16 operands, fp32 accum)
__device__ __forceinline__ void gemm_mma(uint32_t Th, uint32_t Wh,
                                         int m0, int lane, float acc[8][4]){
    int rA    = m0 + (lane & 7) + ((lane >> 3) & 1) * 8;
    int colA8 = ((lane >> 4) & 1) * 8;
    int krB   = (lane & 7) + ((lane >> 3) & 1) * 8;
    int ncB8  = ((lane >> 4) & 1) * 8;
    #pragma unroll
    for (int kk = 0; kk < 4; ++kk){
        uint32_t aoff = sw128((uint32_t)(rA*128 + (kk*16 + colA8)*2));
        uint32_t ah0, ah1, ah2, ah3;
        ldsm4(ah0, ah1, ah2, ah3, Th + aoff);
        #pragma unroll
        for (int np = 0; np < 4; ++np){
            uint32_t boff = sw128((uint32_t)((kk*16 + krB)*128 + (np*16 + ncB8)*2));
            uint32_t bh0, bh1, bh2, bh3;
            ldsm4t(bh0, bh1, bh2, bh3, Wh + boff);
            mma16816(acc[np*2],   ah0, ah1, ah2, ah3, bh0, bh1);
            mma16816(acc[np*2+1], ah0, ah1, ah2, ah3, bh2, bh3);
        }
    }
}

// ---------------- weight prep: fp16 + SW128 swizzle --------------------------------
__global__ void k_wprep(const float* __restrict__ ew2, const float* __restrict__ fw1){
    int l = blockIdx.x >> 1, mat = blockIdx.x & 1;
    const float* src = (mat == 0) ? (ew2 + l*HH*HH) : (fw1 + l*HH*HH);
    __half* dh = g_wh[l][mat];
    for (int e = threadIdx.x; e < HH*HH; e += blockDim.x){
        float v = src[e];                      // [k][n], n fast
        uint32_t byte = (uint32_t)((e >> 6)*128 + (e & 63)*2);
        uint32_t sw = sw128(byte);
        dh[sw >> 1] = __float2half_rn(v);
    }
}

// ---------------- fused: h init + layer-0 prep (writes buffer 0) ------------------
__global__ void k_pre(const float* __restrict__ state,
                      const float* __restrict__ hw, const float* __restrict__ hb,
                      const float* __restrict__ ew1l, const float* __restrict__ eb1l){
    __shared__ float hs[HH];
    int node = blockIdx.x; int t = threadIdx.x;
    float4 st = ((const float4*)state)[node];
    float spd = sqrtf(st.z*st.z + st.w*st.w);
    float h = silu_x(spd * hw[t] + hb[t]);
    g_h[node*HH + t] = h;
    hs[t] = h;
    __syncthreads();
    float a = eb1l[t], c = 0.f;
    #pragma unroll 8
    for (int k = 0; k < HH; ++k){
        float hv = hs[k];
        a = fmaf(hv, ew1l[k*HH + t],        a);
        c = fmaf(hv, ew1l[(HH + k)*HH + t], c);
    }
    g_a[0][node*HH + t] = a;
    int b = node >> 9, j = node & (NN - 1);
    g_ct[0][(b*HH + t)*NN + j] = c;
}

// ---------------- edge smem -------------------------------------------------------
struct EdgeSmem {
    __half T1h[JT*HH];               // 16KB (aliased as MLP scratch in tail)
    __half T2h[JT*HH];               // 16KB
    __half WB[2][HH*HH];             // W2, F1 : 8KB each
    float  A[HH];
    float4 WS[HH];
    float  B2[HH], FB1[HH], FW2[HH];
    float  Nx[2][JT], Ny[2][JT];     // double-buffered by tile parity
    float  Magg[HH], T2i[HH], Fxy[2];
};

// ---------------- edge kernel: CTA=(b,i), 256 thr, mma.sync fp16 ------------------
__global__ void __launch_bounds__(256, 2) k_edge(
    const float* __restrict__ state,
    const float* __restrict__ ew1l,
    const float* __restrict__ eb2l,
    const float* __restrict__ fb1l,
    const float* __restrict__ fw2l,
    const float* __restrict__ fb2l,
    const float* __restrict__ nw1l,
    const float* __restrict__ nb1l,
    const float* __restrict__ nw2l,
    const float* __restrict__ nb2l,
    const float* __restrict__ ew1n,   // next-layer edge_w1 (prep fusion)
    const float* __restrict__ eb1n,
    int layer, int accumulate, int prep_next)
{
    extern __shared__ __align__(16) char smem_raw[];
    EdgeSmem& s = *reinterpret_cast<EdgeSmem*>(smem_raw);

    int tid  = threadIdx.x;
    int wid  = tid >> 5;
    int lane = tid & 31;
    int bi   = blockIdx.x;
    int b    = bi >> 9;
    int i    = bi & (NN - 1);
    int m0   = wid * 16;             // warp's m-tile (j rows)
    int rb   = layer & 1;            // read buffer; tail writes rb^1

    {   // stage weights (16KB flat, coalesced)
        const float4* src = (const float4*)g_wh[layer][0];
        float4* dst = (float4*)s.WB[0];
        #pragma unroll
        for (int q = 0; q < 4; ++q) dst[tid + 256*q] = src[tid + 256*q];
    }
    if (tid < HH){
        s.A[tid]   = g_a[rb][bi*HH + tid];
        s.WS[tid]  = make_float4(ew1l[128*HH + tid], ew1l[129*HH + tid],
                                 ew1l[130*HH + tid], ew1l[131*HH + tid]);
        s.B2[tid]  = eb2l[tid];
        s.FB1[tid] = fb1l[tid];
        s.FW2[tid] = fw2l[tid];
        s.Magg[tid] = 0.0f;
        s.T2i[tid]  = 0.0f;
    }
    if (tid < 2) s.Fxy[tid] = 0.0f;

    uint32_t aT1h = smem_u32(s.T1h);
    uint32_t aT2h = smem_u32(s.T2h);
    uint32_t aW2h = smem_u32(s.WB[0]);
    uint32_t aF1h = smem_u32(s.WB[1]);

    float4 sti = ((const float4*)state)[b*NN + i];
    float spi  = sti.z*sti.z + sti.w*sti.w;
    float fb2v = fb2l[0];
    int jt_i = i >> 7, r_i = i & (JT - 1);

    float fx = 0.f, fy = 0.f;
    float cs[16];                    // deferred m_agg column partials
    #pragma unroll
    for (int q = 0; q < 16; ++q) cs[q] = 0.f;

    __syncthreads();   // (INIT) smem staging visible to all warps

    #pragma unroll 1
    for (int jt = 0; jt < NTILES; ++jt){
        int pb = jt & 1;             // Nx/Ny parity buffer
        // ================= stage 0: T1 row j -> fp16 smem ========================
        {
            int jr = tid & (JT - 1);
            int half = tid >> 7;     // which 32 k's of the row
            int j = jt*JT + jr;
            float4 stj = ((const float4*)state)[b*NN + j];
            float dxp = stj.x - sti.x;
            float dyp = stj.y - sti.y;
            float dsq = dxp*dxp + dyp*dyp;
            float invd = rsqrtf(dsq + 1e-8f);
            float nx = dxp * invd;
            float ny = dyp * invd;
            float dvx = stj.z - sti.z;
            float dvy = stj.w - sti.w;
            float spj = stj.z*stj.z + stj.w*stj.w;
            float appr = dvx*nx + dvy*ny;
            if (half == 0){ s.Nx[pb][jr] = nx; s.Ny[pb][jr] = ny; }

            uint32_t hibuf[16];
            #pragma unroll
            for (int q = 0; q < 16; ++q){
                float tv[2];
                #pragma unroll
                for (int e = 0; e < 2; ++e){
                    int n = half*32 + q*2 + e;
                    float c = g_ct[rb][(b*HH + n)*NN + j];
                    float4 w = s.WS[n];
                    float p = s.A[n] + c;
                    p = fmaf(dsq,  w.x, p);
                    p = fmaf(spi,  w.y, p);
                    p = fmaf(spj,  w.z, p);
                    p = fmaf(appr, w.w, p);
                    tv[e] = silu_f(p);
                }
                __half2 hp = __floats2half2_rn(tv[0], tv[1]);
                hibuf[q] = *(uint32_t*)&hp;
            }
            #pragma unroll
            for (int c = 0; c < 4; ++c){
                uint32_t cc = (uint32_t)(half*4 + c);
                uint32_t off = (uint32_t)(jr*128) + ((cc ^ (uint32_t)(jr & 7)) << 4);
                *(uint4*)((char*)s.T1h + off) =
                    make_uint4(hibuf[c*4], hibuf[c*4+1], hibuf[c*4+2], hibuf[c*4+3]);
            }
        }
        __syncthreads();   // (A) T1 / Nx / Ny ready; also fences prev GEMM2 T2 reads

        // ================= GEMM1: D1 = T1 @ W2 ====================================
        float acc[8][4];
        #pragma unroll
        for (int nt = 0; nt < 8; ++nt)
            #pragma unroll
            for (int p = 0; p < 4; ++p) acc[nt][p] = 0.f;
        gemm_mma(aT1h, aW2h, m0, lane, acc);

        // ---- epilogue1: silu(+b2), deferred magg partials, ->T2 smem ----
        #pragma unroll
        for (int nt = 0; nt < 8; ++nt){
            int c0 = nt*8 + (lane & 3)*2;
            float b2a = s.B2[c0], b2b = s.B2[c0+1];
            float v00 = silu_f(acc[nt][0] + b2a);
            float v01 = silu_f(acc[nt][1] + b2b);
            float v10 = silu_f(acc[nt][2] + b2a);
            float v11 = silu_f(acc[nt][3] + b2b);

            cs[nt*2]   += v00 + v10;
            cs[nt*2+1] += v01 + v11;

            int mg0 = m0 + (lane >> 2);
            int mg1 = mg0 + 8;
            uint32_t o0 = sw128((uint32_t)(mg0*128 + c0*2));
            uint32_t o1 = sw128((uint32_t)(mg1*128 + c0*2));
            *(__half2*)((char*)s.T2h + o0) = __floats2half2_rn(v00, v01);
            *(__half2*)((char*)s.T2h + o1) = __floats2half2_rn(v10, v11);
        }
        __syncthreads();   // (B) T2 ready

        // ---- capture T2 row i (for magg self-term subtraction) ----
        if (jt == jt_i && tid < 32){
            uint32_t o = sw128((uint32_t)(r_i*128 + tid*4));
            uint32_t hv = *(const uint32_t*)((const char*)s.T2h + o);
            s.T2i[tid*2]     = __half2float(__ushort_as_half((unsigned short)(hv & 0xffff)));
            s.T2i[tid*2 + 1] = __half2float(__ushort_as_half((unsigned short)(hv >> 16)));
        }

        // ================= GEMM2: D2 = T2 @ F1 ====================================
        #pragma unroll
        for (int nt = 0; nt < 8; ++nt)
            #pragma unroll
            for (int p = 0; p < 4; ++p) acc[nt][p] = 0.f;
        gemm_mma(aT2h, aF1h, m0, lane, acc);

        // ---- epilogue2: fw = silu(D2 + fb1) . fw2 + fb2; force ----
        float pm = 0.f, pm8 = 0.f;
        #pragma unroll
        for (int nt = 0; nt < 8; ++nt){
            int c0 = nt*8 + (lane & 3)*2;
            float fa = s.FB1[c0], fb = s.FB1[c0+1];
            float wa = s.FW2[c0], wb = s.FW2[c0+1];
            pm  = fmaf(silu_f(acc[nt][0] + fa), wa, pm);
            pm  = fmaf(silu_f(acc[nt][1] + fb), wb, pm);
            pm8 = fmaf(silu_f(acc[nt][2] + fa), wa, pm8);
            pm8 = fmaf(silu_f(acc[nt][3] + fb), wb, pm8);
        }
        pm  += __shfl_xor_sync(0xffffffffu, pm, 1);
        pm  += __shfl_xor_sync(0xffffffffu, pm, 2);
        pm8 += __shfl_xor_sync(0xffffffffu, pm8, 1);
        pm8 += __shfl_xor_sync(0xffffffffu, pm8, 2);
        if ((lane & 3) == 0){
            int r0_ = m0 + (lane >> 2);
            int r1_ = r0_ + 8;
            float f0 = pm + fb2v, f1 = pm8 + fb2v;
            // normal is exactly 0 at j==i -> self-term auto-masked
            fx = fmaf(f0, s.Nx[pb][r0_], fx); fx = fmaf(f1, s.Nx[pb][r1_], fx);
            fy = fmaf(f0, s.Ny[pb][r0_], fy); fy = fmaf(f1, s.Ny[pb][r1_], fy);
        }
        // no barrier: Nx/Ny double-buffered; T1/T2 reuse fenced by sync (A)/(B)
    }

    // ---- final m_agg reduction (once) ----
    #pragma unroll
    for (int nt = 0; nt < 8; ++nt){
        float s0 = cs[nt*2], s1 = cs[nt*2+1];
        s0 += __shfl_xor_sync(0xffffffffu, s0, 4);
        s0 += __shfl_xor_sync(0xffffffffu, s0, 8);
        s0 += __shfl_xor_sync(0xffffffffu, s0, 16);
        s1 += __shfl_xor_sync(0xffffffffu, s1, 4);
        s1 += __shfl_xor_sync(0xffffffffu, s1, 8);
        s1 += __shfl_xor_sync(0xffffffffu, s1, 16);
        if (lane < 4){
            int c0 = nt*8 + lane*2;
            atomicAdd(&s.Magg[c0],     s0);
            atomicAdd(&s.Magg[c0 + 1], s1);
        }
    }
    // ---- reduce forces ----
    fx += __shfl_xor_sync(0xffffffffu, fx, 16);
    fx += __shfl_xor_sync(0xffffffffu, fx, 8);
    fx += __shfl_xor_sync(0xffffffffu, fx, 4);
    fy += __shfl_xor_sync(0xffffffffu, fy, 16);
    fy += __shfl_xor_sync(0xffffffffu, fy, 8);
    fy += __shfl_xor_sync(0xffffffffu, fy, 4);
    if (lane == 0){
        atomicAdd(&s.Fxy[0], fx);
        atomicAdd(&s.Fxy[1], fy);
    }
    __syncthreads();   // Magg / Fxy final

    if (tid < 2){
        float v = s.Fxy[tid];
        if (accumulate) g_fsum[bi*2 + tid] += v;
        else            g_fsum[bi*2 + tid] = v;
    }

    // ================= fused node-update MLP (h_new for node bi) =================
    float* sIn = (float*)s.T1h;      // 128 floats (T1 region is dead now)
    float* sP  = sIn + 128;          // 256 partials
    float* sY  = sP + 256;           // 64
    if (tid < 64)       sIn[tid] = g_h[bi*HH + tid];
    else if (tid < 128) sIn[tid] = s.Magg[tid - 64] - s.T2i[tid - 64];
    __syncthreads();
    {
        int out = tid & 63, chk = tid >> 6;
        float p = 0.f;
        #pragma unroll 8
        for (int k = 0; k < 32; ++k)
            p = fmaf(sIn[chk*32 + k], nw1l[(chk*32 + k)*HH + out], p);
        sP[tid] = p;
    }
    __syncthreads();
    if (tid < 64)
        sY[tid] = silu_x(sP[tid] + sP[tid+64] + sP[tid+128] + sP[tid+192] + nb1l[tid]);
    __syncthreads();
    {
        int out = tid & 63, chk = tid >> 6;
        float p = 0.f;
        #pragma unroll 8
        for (int k = 0; k < 16; ++k)
            p = fmaf(sY[chk*16 + k], nw2l[(chk*16 + k)*HH + out], p);
        sP[tid] = p;
    }
    __syncthreads();
    if (tid < 64){
        float hn = sP[tid] + sP[tid+64] + sP[tid+128] + sP[tid+192] + nb2l[tid];
        g_h[bi*HH + tid] = hn;
        sIn[tid] = hn;               // keep for fused next-layer prep
    }
    __syncthreads();

    // ====== fused next-layer prep: a_i, c_j for node bi (writes rb^1 buffer) ======
    if (prep_next && tid < 128){
        int out = tid & 63, which = tid >> 6;
        float a = which ? 0.f : eb1n[out];
        const float* w = ew1n + (which ? HH*HH : 0);
        #pragma unroll 8
        for (int k = 0; k < HH; ++k)
            a = fmaf(sIn[k], w[k*HH + out], a);
        if (which == 0) g_a[rb ^ 1][bi*HH + out] = a;
        else            g_ct[rb ^ 1][(b*HH + out)*NN + i] = a;
    }
}

// ---------------- wall MLP + output (node update already fused) -------------------
__global__ void k_final(const float* __restrict__ state,
                        const float* __restrict__ w1, const float* __restrict__ b1,
                        const float* __restrict__ w2, const float* __restrict__ b2,
                        const float* __restrict__ w3, const float* __restrict__ b3,
                        float* __restrict__ out){
    __shared__ float sH[HH + 4];
    __shared__ float sY[HH];
    __shared__ float sM[4];
    int node = blockIdx.x; int t = threadIdx.x;
    sH[t] = g_h[node*HH + t];
    if (t < 4){
        float4 st = ((const float4*)state)[node];
        float d = (t == 0) ? st.x : (t == 1) ? 1.0f - st.x
                : (t == 2) ? st.y : 1.0f - st.y;
        sH[HH + t] = d;
    }
    __syncthreads();
    float a1 = b1[t];
    #pragma unroll 4
    for (int k = 0; k < HH + 4; ++k) a1 = fmaf(sH[k], w1[k*HH + t], a1);
    sY[t] = silu_x(a1);
    __syncthreads();
    float a2 = b2[t];
    #pragma unroll 8
    for (int k = 0; k < HH; ++k) a2 = fmaf(sY[k], w2[k*HH + t], a2);
    __syncthreads();
    sY[t] = silu_x(a2);
    __syncthreads();
    if (t < 4){
        float m = b3[t];
        #pragma unroll 8
        for (int k = 0; k < HH; ++k) m = fmaf(sY[k], w3[k*4 + t], m);
        sM[t] = m;
    }
    __syncthreads();
    if (t < 2){
        float wf = (t == 0) ? (sM[0] - sM[1]) : (sM[2] - sM[3]);
        out[node*2 + t] = g_fsum[node*2 + t] + wf;
    }
}

// ---------------- launch ----------------------------------------------------------
extern "C" void kernel_launch(void* const* d_in, const int* in_sizes, int n_in,
                              void* d_out, int out_size){
    const float* state = (const float*)d_in[0];
    const float* hiw  = (const float*)d_in[1];
    const float* hib  = (const float*)d_in[2];
    const float* ew1  = (const float*)d_in[3];
    const float* eb1  = (const float*)d_in[4];
    const float* ew2  = (const float*)d_in[5];
    const float* eb2  = (const float*)d_in[6];
    const float* fw1  = (const float*)d_in[7];
    const float* fb1  = (const float*)d_in[8];
    const float* fw2  = (const float*)d_in[9];
    const float* fb2  = (const float*)d_in[10];
    const float* nw1  = (const float*)d_in[11];
    const float* nb1  = (const float*)d_in[12];
    const float* nw2  = (const float*)d_in[13];
    const float* nb2  = (const float*)d_in[14];
    const float* ww1  = (const float*)d_in[15];
    const float* wb1  = (const float*)d_in[16];
    const float* ww2  = (const float*)d_in[17];
    const float* wb2  = (const float*)d_in[18];
    const float* ww3  = (const float*)d_in[19];
    const float* wb3  = (const float*)d_in[20];
    float* out = (float*)d_out;

    int smem = (int)sizeof(EdgeSmem);
    cudaFuncSetAttribute(k_edge, cudaFuncAttributeMaxDynamicSharedMemorySize, smem);

    k_wprep<<<6, 256>>>(ew2, fw1);
    k_pre<<<NODES, HH>>>(state, hiw, hib, ew1, eb1);
    for (int l = 0; l < 3; ++l){
        int pn = (l < 2) ? 1 : 0;
        const float* ew1n = ew1 + (pn ? (l+1)*132*HH : 0);
        const float* eb1n = eb1 + (pn ? (l+1)*HH : 0);
        k_edge<<<NODES, 256, smem>>>(state,
                               ew1 + l*132*HH,
                               eb2 + l*HH,
                               fb1 + l*HH,
                               fw2 + l*HH,
                               fb2 + l,
                               nw1 + l*2*HH*HH, nb1 + l*HH,
                               nw2 + l*HH*HH,   nb2 + l*HH,
                               ew1n, eb1n,
                               l, l, pn);
    }
    k_final<<<NODES, HH>>>(state, ww1, wb1, ww2, wb2, ww3, wb3, out);
}